// round 1
// baseline (speedup 1.0000x reference)
#include <cuda_runtime.h>
#include <math.h>

#define N_ 1024
#define H_ 1024
#define B_ 64
#define T_ 256
#define BT_ (B_*T_)
#define HID_ 512

// ---------------- scratch (static device globals; no allocation) ----------------
__device__ float g_hgate[B_*H_];
__device__ float g_hmean[H_];
__device__ float g_Ecur[N_*H_];
__device__ float g_S[N_*N_];
__device__ float g_rowsum[N_];
__device__ float g_Abase[N_*N_];
__device__ float g_AmixT[N_*N_];
__device__ float g_hid[B_*HID_];
__device__ float g_gamma[B_*N_];
__device__ float g_gmean[N_];
__device__ float g_znodes[16777216];   // [BT, N]
__device__ float g_zgcn[16777216];     // [BT, N]
__device__ float g_msg[16777216];      // [BT, H]

// ---------------- small kernels ----------------

// h_gate[b][h] = mean_t h_time[b][t][h]
__global__ void k_meanT(const float* __restrict__ h) {
    int idx = blockIdx.x * blockDim.x + threadIdx.x;   // B*H
    if (idx >= B_*H_) return;
    int b = idx >> 10;
    int hh = idx & 1023;
    const float* p = h + (size_t)b * T_ * H_ + hh;
    float s = 0.f;
    #pragma unroll 8
    for (int t = 0; t < T_; t++) s += p[(size_t)t * H_];
    g_hgate[idx] = s * (1.0f / T_);
}

// h_mean[h] = mean_b h_gate[b][h]
__global__ void k_meanB() {
    int hh = blockIdx.x * blockDim.x + threadIdx.x;
    if (hh >= H_) return;
    float s = 0.f;
    #pragma unroll
    for (int b = 0; b < B_; b++) s += g_hgate[b * H_ + hh];
    g_hmean[hh] = s * (1.0f / B_);
}

// E_cur[i][:] = normalize(E_dyn[i][:] + h_mean)
__global__ __launch_bounds__(256) void k_enorm(const float* __restrict__ E_dyn) {
    int i = blockIdx.x;
    __shared__ float red[256];
    float vals[4];
    float ss = 0.f;
    #pragma unroll
    for (int j = 0; j < 4; j++) {
        int hh = threadIdx.x + j * 256;
        float v = E_dyn[i * H_ + hh] + g_hmean[hh];
        vals[j] = v;
        ss += v * v;
    }
    red[threadIdx.x] = ss; __syncthreads();
    for (int off = 128; off > 0; off >>= 1) {
        if (threadIdx.x < off) red[threadIdx.x] += red[threadIdx.x + off];
        __syncthreads();
    }
    float inv = 1.0f / fmaxf(sqrtf(red[0]), 1e-12f);
    #pragma unroll
    for (int j = 0; j < 4; j++) {
        int hh = threadIdx.x + j * 256;
        g_Ecur[i * H_ + hh] = vals[j] * inv;
    }
}

// rowsum[i] = sum_j S[i][j]
__global__ __launch_bounds__(256) void k_rowsum() {
    int i = blockIdx.x;
    __shared__ float red[256];
    float s = 0.f;
    for (int j = threadIdx.x; j < N_; j += 256) s += g_S[i * N_ + j];
    red[threadIdx.x] = s; __syncthreads();
    for (int off = 128; off > 0; off >>= 1) {
        if (threadIdx.x < off) red[threadIdx.x] += red[threadIdx.x + off];
        __syncthreads();
    }
    if (threadIdx.x == 0) g_rowsum[i] = red[0];
}

// A_base = alpha*A_pearson + (1-alpha)*0.5*(S[i][j]/rs[i] + S[j][i]/rs[j])
__global__ void k_abase(const float* __restrict__ Ap, const float* __restrict__ alpha_raw) {
    int idx = blockIdx.x * blockDim.x + threadIdx.x;
    if (idx >= N_*N_) return;
    int i = idx >> 10, j = idx & 1023;
    float alpha = 1.0f / (1.0f + expf(-alpha_raw[0]));
    float ad = 0.5f * (g_S[idx] / (g_rowsum[i] + 1e-6f) + g_S[j * N_ + i] / (g_rowsum[j] + 1e-6f));
    g_Abase[idx] = alpha * Ap[idx] + (1.0f - alpha) * ad;
}

// hid = gelu(h_gate @ W1 + b1)   [B,512]
__global__ void k_gate1(const float* __restrict__ W1, const float* __restrict__ b1) {
    int idx = blockIdx.x * blockDim.x + threadIdx.x;  // B*512
    if (idx >= B_*HID_) return;
    int b = idx >> 9, m = idx & 511;
    const float* x = g_hgate + b * H_;
    float s = b1[m];
    for (int k = 0; k < H_; k++) s += x[k] * W1[k * HID_ + m];
    g_hid[idx] = 0.5f * s * (1.0f + erff(s * 0.70710678118654752f));
}

// gamma = sigmoid(hid @ W2 + b2)   [B,N]
__global__ void k_gate2(const float* __restrict__ W2, const float* __restrict__ b2) {
    int idx = blockIdx.x * blockDim.x + threadIdx.x;  // B*N
    if (idx >= B_*N_) return;
    int b = idx >> 10, n = idx & 1023;
    const float* x = g_hid + b * HID_;
    float s = b2[n];
    for (int k = 0; k < HID_; k++) s += x[k] * W2[k * N_ + n];
    g_gamma[idx] = 1.0f / (1.0f + expf(-s));
}

// gmean[n] = mean_b gamma[b][n]
__global__ void k_gmean() {
    int n = blockIdx.x * blockDim.x + threadIdx.x;
    if (n >= N_) return;
    float s = 0.f;
    #pragma unroll
    for (int b = 0; b < B_; b++) s += g_gamma[b * N_ + n];
    g_gmean[n] = s * (1.0f / B_);
}

// AmixT[n][m] = A_base[m][n] * gmean[m]   (so z_gcn = z_nodes @ AmixT is a plain NN GEMM)
__global__ void k_amixT() {
    int idx = blockIdx.x * blockDim.x + threadIdx.x;
    if (idx >= N_*N_) return;
    int n = idx >> 10, m = idx & 1023;
    g_AmixT[idx] = g_Abase[m * N_ + n] * g_gmean[m];
}

// final: y = h_time*(1+tanh(1/N)) + msg  -> LayerNorm
__global__ __launch_bounds__(256) void k_final(const float* __restrict__ h,
                                               const float* __restrict__ lw,
                                               const float* __restrict__ lb,
                                               float* __restrict__ out) {
    int row = blockIdx.x;                      // BT rows
    size_t base = (size_t)row * H_ + threadIdx.x * 4;
    const float gw = 1.0f + tanhf(1.0f / 1024.0f);
    float4 a = *(const float4*)(h + base);
    float4 m = *(const float4*)(g_msg + base);
    float v0 = a.x * gw + m.x;
    float v1 = a.y * gw + m.y;
    float v2 = a.z * gw + m.z;
    float v3 = a.w * gw + m.w;

    __shared__ float red[256];
    red[threadIdx.x] = v0 + v1 + v2 + v3;
    __syncthreads();
    for (int off = 128; off > 0; off >>= 1) {
        if (threadIdx.x < off) red[threadIdx.x] += red[threadIdx.x + off];
        __syncthreads();
    }
    float mu = red[0] * (1.0f / H_);
    __syncthreads();
    float d0 = v0 - mu, d1 = v1 - mu, d2 = v2 - mu, d3 = v3 - mu;
    red[threadIdx.x] = d0 * d0 + d1 * d1 + d2 * d2 + d3 * d3;
    __syncthreads();
    for (int off = 128; off > 0; off >>= 1) {
        if (threadIdx.x < off) red[threadIdx.x] += red[threadIdx.x + off];
        __syncthreads();
    }
    float rstd = rsqrtf(red[0] * (1.0f / H_) + 1e-5f);
    float4 w = *(const float4*)(lw + threadIdx.x * 4);
    float4 bb = *(const float4*)(lb + threadIdx.x * 4);
    float4 o;
    o.x = d0 * rstd * w.x + bb.x;
    o.y = d1 * rstd * w.y + bb.y;
    o.z = d2 * rstd * w.z + bb.z;
    o.w = d3 * rstd * w.w + bb.w;
    *(float4*)(out + base) = o;
}

// ---------------- 128x128x8 SGEMM, double-buffered ----------------
// C[M,Nn] = A[M,K] @ op(B) (+bias) (+relu)
// TRANSB=0: B is [K,Nn] row-major. TRANSB=1: B is [Nn,K] row-major (C = A @ B^T).
template<int TRANSB, int RELU, int BIAS>
__global__ __launch_bounds__(256) void sgemm128(const float* __restrict__ A,
                                                const float* __restrict__ B,
                                                const float* __restrict__ bias,
                                                float* __restrict__ C,
                                                int M, int Nn, int K) {
    __shared__ float As[2][8][128];
    __shared__ float Bs[2][8][128];
    const int tid = threadIdx.x;
    const int bx = blockIdx.x;   // N tile
    const int by = blockIdx.y;   // M tile
    const int tx = tid & 15;
    const int ty = tid >> 4;

    const int arow = tid >> 1;          // 0..127
    const int acol = (tid & 1) << 2;    // 0 or 4
    const int brow = tid >> 5;          // 0..7
    const int bcol = (tid & 31) << 2;   // 0..124

    const float* Ag = A + (size_t)(by * 128 + arow) * K + acol;
    const float* Bg = TRANSB ? (B + (size_t)(bx * 128 + arow) * K + acol)
                             : (B + (size_t)brow * Nn + bx * 128 + bcol);

    float acc[8][8];
    #pragma unroll
    for (int i = 0; i < 8; i++)
        #pragma unroll
        for (int j = 0; j < 8; j++) acc[i][j] = 0.f;

    const int NK = K >> 3;

    // prologue: tile 0
    {
        float4 av = *(const float4*)(Ag);
        As[0][acol + 0][arow] = av.x; As[0][acol + 1][arow] = av.y;
        As[0][acol + 2][arow] = av.z; As[0][acol + 3][arow] = av.w;
        if (TRANSB) {
            float4 bv = *(const float4*)(Bg);
            Bs[0][acol + 0][arow] = bv.x; Bs[0][acol + 1][arow] = bv.y;
            Bs[0][acol + 2][arow] = bv.z; Bs[0][acol + 3][arow] = bv.w;
        } else {
            *(float4*)&Bs[0][brow][bcol] = *(const float4*)(Bg);
        }
    }
    __syncthreads();

    for (int kt = 0; kt < NK; kt++) {
        const int cur = kt & 1;
        float4 avn, bvn;
        const bool more = (kt + 1 < NK);
        if (more) {
            avn = *(const float4*)(Ag + (kt + 1) * 8);
            bvn = TRANSB ? *(const float4*)(Bg + (kt + 1) * 8)
                         : *(const float4*)(Bg + (size_t)(kt + 1) * 8 * Nn);
        }
        #pragma unroll
        for (int k = 0; k < 8; k++) {
            float4 a0 = *(const float4*)&As[cur][k][ty * 4];
            float4 a1 = *(const float4*)&As[cur][k][ty * 4 + 64];
            float4 b0 = *(const float4*)&Bs[cur][k][tx * 4];
            float4 b1 = *(const float4*)&Bs[cur][k][tx * 4 + 64];
            float a[8] = {a0.x, a0.y, a0.z, a0.w, a1.x, a1.y, a1.z, a1.w};
            float b[8] = {b0.x, b0.y, b0.z, b0.w, b1.x, b1.y, b1.z, b1.w};
            #pragma unroll
            for (int i = 0; i < 8; i++)
                #pragma unroll
                for (int j = 0; j < 8; j++)
                    acc[i][j] += a[i] * b[j];
        }
        if (more) {
            const int nxt = cur ^ 1;
            As[nxt][acol + 0][arow] = avn.x; As[nxt][acol + 1][arow] = avn.y;
            As[nxt][acol + 2][arow] = avn.z; As[nxt][acol + 3][arow] = avn.w;
            if (TRANSB) {
                Bs[nxt][acol + 0][arow] = bvn.x; Bs[nxt][acol + 1][arow] = bvn.y;
                Bs[nxt][acol + 2][arow] = bvn.z; Bs[nxt][acol + 3][arow] = bvn.w;
            } else {
                *(float4*)&Bs[nxt][brow][bcol] = bvn;
            }
        }
        __syncthreads();
    }

    // epilogue
    #pragma unroll
    for (int i = 0; i < 8; i++) {
        int rl = (i < 4) ? (ty * 4 + i) : (64 + ty * 4 + (i - 4));
        size_t r = (size_t)(by * 128 + rl);
        #pragma unroll
        for (int jb = 0; jb < 2; jb++) {
            int c = bx * 128 + jb * 64 + tx * 4;
            float4 v;
            v.x = acc[i][jb * 4 + 0];
            v.y = acc[i][jb * 4 + 1];
            v.z = acc[i][jb * 4 + 2];
            v.w = acc[i][jb * 4 + 3];
            if (BIAS) {
                v.x += bias[c]; v.y += bias[c + 1]; v.z += bias[c + 2]; v.w += bias[c + 3];
            }
            if (RELU) {
                v.x = fmaxf(v.x, 0.f); v.y = fmaxf(v.y, 0.f);
                v.z = fmaxf(v.z, 0.f); v.w = fmaxf(v.w, 0.f);
            }
            *(float4*)&C[r * Nn + c] = v;
        }
    }
}

// ---------------- launcher ----------------
extern "C" void kernel_launch(void* const* d_in, const int* in_sizes, int n_in,
                              void* d_out, int out_size) {
    const float* h_time    = (const float*)d_in[0];
    const float* A_pearson = (const float*)d_in[1];
    const float* E_dyn     = (const float*)d_in[2];
    const float* alpha_raw = (const float*)d_in[3];
    // d_in[4] = tau_raw : unused (softmax-mean is analytically 1/N)
    const float* gate_W1   = (const float*)d_in[5];
    const float* gate_b1   = (const float*)d_in[6];
    const float* gate_W2   = (const float*)d_in[7];
    const float* gate_b2   = (const float*)d_in[8];
    const float* h2n_W     = (const float*)d_in[9];
    const float* h2n_b     = (const float*)d_in[10];
    const float* n2h_W     = (const float*)d_in[11];
    const float* n2h_b     = (const float*)d_in[12];
    const float* ln_w      = (const float*)d_in[13];
    const float* ln_b      = (const float*)d_in[14];
    float* out = (float*)d_out;

    float *p_Ecur, *p_S, *p_AmixT, *p_znodes, *p_zgcn, *p_msg;
    cudaGetSymbolAddress((void**)&p_Ecur,   g_Ecur);
    cudaGetSymbolAddress((void**)&p_S,      g_S);
    cudaGetSymbolAddress((void**)&p_AmixT,  g_AmixT);
    cudaGetSymbolAddress((void**)&p_znodes, g_znodes);
    cudaGetSymbolAddress((void**)&p_zgcn,   g_zgcn);
    cudaGetSymbolAddress((void**)&p_msg,    g_msg);

    // 1) reductions
    k_meanT<<<(B_*H_ + 255) / 256, 256>>>(h_time);
    k_meanB<<<(H_ + 255) / 256, 256>>>();

    // 2) E_cur
    k_enorm<<<N_, 256>>>(E_dyn);

    // 3) S = relu(E_cur @ E_cur^T)
    {
        dim3 g(N_ / 128, N_ / 128);
        sgemm128<1, 1, 0><<<g, 256>>>(p_Ecur, p_Ecur, nullptr, p_S, N_, N_, H_);
    }
    k_rowsum<<<N_, 256>>>();
    k_abase<<<(N_*N_ + 255) / 256, 256>>>(A_pearson, alpha_raw);

    // 4) gate MLP
    k_gate1<<<(B_*HID_ + 255) / 256, 256>>>(gate_W1, gate_b1);
    k_gate2<<<(B_*N_ + 255) / 256, 256>>>(gate_W2, gate_b2);
    k_gmean<<<(N_ + 255) / 256, 256>>>();
    k_amixT<<<(N_*N_ + 255) / 256, 256>>>();

    // 5) big GEMM chain
    {
        dim3 g(N_ / 128, BT_ / 128);
        sgemm128<0, 0, 1><<<g, 256>>>(h_time,   h2n_W,   h2n_b, p_znodes, BT_, N_, H_);
        sgemm128<0, 0, 0><<<g, 256>>>(p_znodes, p_AmixT, nullptr, p_zgcn, BT_, N_, N_);
        sgemm128<0, 0, 1><<<g, 256>>>(p_zgcn,   n2h_W,   n2h_b, p_msg,   BT_, H_, N_);
    }

    // 6) fused residual + LayerNorm
    k_final<<<BT_, 256>>>(h_time, ln_w, ln_b, out);
}

// round 3
// speedup vs baseline: 2.9330x; 2.9330x over previous
#include <cuda_runtime.h>
#include <cuda_bf16.h>
#include <math.h>
#include <stdint.h>

#define N_ 1024
#define H_ 1024
#define B_ 64
#define T_ 256
#define BT_ (B_*T_)
#define HID_ 512

typedef __nv_bfloat16 bf16;

// ---------------- scratch (static device globals; no allocation) ----------------
__device__ float g_hgate[B_*H_];
__device__ float g_hmean[H_];
__device__ bf16  g_Ehi[N_*H_], g_Elo[N_*H_];
__device__ float g_S[N_*N_];
__device__ float g_rowsum[N_];
__device__ float g_hid[B_*HID_];
__device__ float g_gamma[B_*N_];
__device__ float g_gmean[N_];
__device__ bf16  g_Amh[N_*N_], g_Aml[N_*N_];       // A_mix [m][n] split
__device__ float g_Amf[N_*N_];                      // A_mix fp32 (for exact bias fold)
__device__ bf16  g_W1h[H_*N_], g_W1l[H_*N_];       // h2n_W [H,N] split (direct)
__device__ bf16  g_W2th[H_*N_], g_W2tl[H_*N_];     // n2h_W transposed -> [H,N] split
__device__ bf16  g_Ph[H_*N_], g_Pl[H_*N_];         // P = W1 @ AmixT  [H,N] split
__device__ bf16  g_Mh[H_*H_], g_Ml[H_*H_];         // McombT [H,H] split
__device__ bf16  g_hAh[BT_*H_], g_hAl[BT_*H_];     // h_time split
__device__ float g_u[N_];
__device__ float g_cvec[H_];
__device__ float g_msg[BT_*H_];

// ---------------- helpers ----------------
__device__ __forceinline__ unsigned short bfbits(bf16 x) {
    return *reinterpret_cast<unsigned short*>(&x);
}
__device__ __forceinline__ uint32_t smem_u32(const void* p) {
    uint32_t a;
    asm("{ .reg .u64 t; cvta.to.shared.u64 t, %1; cvt.u32.u64 %0, t; }" : "=r"(a) : "l"(p));
    return a;
}
__device__ __forceinline__ uint32_t swz(uint32_t off) {
    return off ^ ((off >> 3) & 0x70);
}
#define CP_COMMIT() asm volatile("cp.async.commit_group;" ::: "memory")

__device__ __forceinline__ void ldsm4(uint32_t (&r)[4], uint32_t addr) {
    asm volatile("ldmatrix.sync.aligned.m8n8.x4.shared.b16 {%0,%1,%2,%3}, [%4];"
        : "=r"(r[0]), "=r"(r[1]), "=r"(r[2]), "=r"(r[3]) : "r"(addr));
}
__device__ __forceinline__ void mma16816(float* c, const uint32_t* a, uint32_t b0, uint32_t b1) {
    asm volatile("mma.sync.aligned.m16n8k16.row.col.f32.bf16.bf16.f32 "
        "{%0,%1,%2,%3}, {%4,%5,%6,%7}, {%8,%9}, {%0,%1,%2,%3};"
        : "+f"(c[0]), "+f"(c[1]), "+f"(c[2]), "+f"(c[3])
        : "r"(a[0]), "r"(a[1]), "r"(a[2]), "r"(a[3]), "r"(b0), "r"(b1));
}

// load one 128row x 64col bf16 tile (SW128 swizzled, 128B/row) for K-chunk kc; 256 threads
__device__ __forceinline__ void ld_tile(uint32_t sdst, const bf16* __restrict__ g,
                                        int row0, int K, int kc, int tid) {
    const int row = tid >> 1, half = tid & 1;
    const char* src = (const char*)(g + (size_t)(row0 + row) * K + (kc << 6) + half * 32);
    uint32_t rb = (uint32_t)row * 128 + (uint32_t)half * 64;
    #pragma unroll
    for (int j = 0; j < 4; j++) {
        uint32_t sw = swz(rb + (j << 4));
        asm volatile("cp.async.cg.shared.global [%0], [%1], 16;"
            :: "r"(sdst + sw), "l"(src + (j << 4)));
    }
}

// ---------------- split-bf16 HMMA GEMM (TN): C[M,Nn] = (Ahi+Alo)[M,K] @ (Bhi+Blo)[Nn,K]^T
// OUT_MODE: 0 = fp32 (+bias), 1 = fp32 relu, 2 = split bf16 hi/lo
#define TILE_B 16384
#define BUF_B  65536
#define GEMM_SMEM (1024 + 2 * BUF_B)

template<int OUT_MODE, int BIAS>
__global__ __launch_bounds__(256, 1) void hgemm(
    const bf16* __restrict__ Ahi, const bf16* __restrict__ Alo,
    const bf16* __restrict__ Bhi, const bf16* __restrict__ Blo,
    const float* __restrict__ bias,
    float* __restrict__ Cf, bf16* __restrict__ Chi, bf16* __restrict__ Clo,
    int M, int Nn, int K)
{
    extern __shared__ __align__(1024) char smem[];
    uint32_t sb = smem_u32(smem);
    const int tid = threadIdx.x;
    const int wid = tid >> 5, lane = tid & 31;
    const int wm = wid >> 1, wn = wid & 1;          // 4x2 warps, each 32x64
    const int bx = blockIdx.x, by = blockIdx.y;

    float* sBias = (float*)(smem + 512);
    if (BIAS && tid < 128) sBias[tid] = bias[bx * 128 + tid];

    const uint32_t T0 = sb + 1024;
    const int NK = K >> 6;
    const int arow0 = by * 128, brow0 = bx * 128;

    float acc[2][8][4];
    #pragma unroll
    for (int i = 0; i < 2; i++)
        #pragma unroll
        for (int j = 0; j < 8; j++)
            #pragma unroll
            for (int l = 0; l < 4; l++) acc[i][j][l] = 0.f;

    // ldmatrix per-lane addressing (canonical x4 layout)
    const int mi = lane >> 3, li = lane & 7;
    const int rowoff = (mi & 1) * 8 + li;
    const int coloff = (mi >> 1) * 16;   // bytes

    // prologue: chunk 0 -> buf 0
    ld_tile(T0,              Ahi, arow0, K, 0, tid);
    ld_tile(T0 + TILE_B,     Alo, arow0, K, 0, tid);
    ld_tile(T0 + 2 * TILE_B, Bhi, brow0, K, 0, tid);
    ld_tile(T0 + 3 * TILE_B, Blo, brow0, K, 0, tid);
    CP_COMMIT();

    for (int kc = 0; kc < NK; kc++) {
        const int cur = kc & 1;
        if (kc + 1 < NK) {
            uint32_t nb = T0 + (cur ^ 1) * BUF_B;
            ld_tile(nb,              Ahi, arow0, K, kc + 1, tid);
            ld_tile(nb + TILE_B,     Alo, arow0, K, kc + 1, tid);
            ld_tile(nb + 2 * TILE_B, Bhi, brow0, K, kc + 1, tid);
            ld_tile(nb + 3 * TILE_B, Blo, brow0, K, kc + 1, tid);
            CP_COMMIT();
            asm volatile("cp.async.wait_group 1;" ::: "memory");
        } else {
            asm volatile("cp.async.wait_group 0;" ::: "memory");
        }
        __syncthreads();

        const uint32_t Ah = T0 + cur * BUF_B;
        const uint32_t Al = Ah + TILE_B;
        const uint32_t Bh = Ah + 2 * TILE_B;
        const uint32_t Bl = Ah + 3 * TILE_B;

        #pragma unroll
        for (int ks = 0; ks < 4; ks++) {
            const int kb = ks * 32;
            uint32_t ahi[2][4], alo[2][4];
            #pragma unroll
            for (int mt = 0; mt < 2; mt++) {
                uint32_t ra = swz((uint32_t)(wm * 32 + mt * 16 + rowoff) * 128 + kb + coloff);
                ldsm4(ahi[mt], Ah + ra);
                ldsm4(alo[mt], Al + ra);
            }
            #pragma unroll
            for (int g = 0; g < 4; g++) {
                uint32_t rb = swz((uint32_t)(wn * 64 + g * 16 + rowoff) * 128 + kb + coloff);
                uint32_t bh[4], bl[4];
                ldsm4(bh, Bh + rb);
                ldsm4(bl, Bl + rb);
                #pragma unroll
                for (int mt = 0; mt < 2; mt++) {
                    #pragma unroll
                    for (int sub = 0; sub < 2; sub++) {
                        float* c = acc[mt][g * 2 + sub];
                        mma16816(c, ahi[mt], bh[sub], bh[2 + sub]);
                        mma16816(c, ahi[mt], bl[sub], bl[2 + sub]);
                        mma16816(c, alo[mt], bh[sub], bh[2 + sub]);
                    }
                }
            }
        }
        __syncthreads();
    }

    // epilogue: C frag layout — c0,c1: row lane/4, cols (lane%4)*2+{0,1}; c2,c3: row+8
    #pragma unroll
    for (int mt = 0; mt < 2; mt++) {
        #pragma unroll
        for (int nt = 0; nt < 8; nt++) {
            const int r0 = by * 128 + wm * 32 + mt * 16 + (lane >> 2);
            const int cb = wn * 64 + nt * 8 + (lane & 3) * 2;
            const int cg = bx * 128 + cb;
            float v0 = acc[mt][nt][0], v1 = acc[mt][nt][1];
            float v2 = acc[mt][nt][2], v3 = acc[mt][nt][3];
            if (BIAS) {
                float bb0 = sBias[cb], bb1 = sBias[cb + 1];
                v0 += bb0; v1 += bb1; v2 += bb0; v3 += bb1;
            }
            if (OUT_MODE == 1) {
                v0 = fmaxf(v0, 0.f); v1 = fmaxf(v1, 0.f);
                v2 = fmaxf(v2, 0.f); v3 = fmaxf(v3, 0.f);
            }
            if (OUT_MODE == 2) {
                bf16 h0 = __float2bfloat16(v0), h1 = __float2bfloat16(v1);
                bf16 h2 = __float2bfloat16(v2), h3 = __float2bfloat16(v3);
                bf16 l0 = __float2bfloat16(v0 - __bfloat162float(h0));
                bf16 l1 = __float2bfloat16(v1 - __bfloat162float(h1));
                bf16 l2 = __float2bfloat16(v2 - __bfloat162float(h2));
                bf16 l3 = __float2bfloat16(v3 - __bfloat162float(h3));
                *(uint32_t*)(Chi + (size_t)r0 * Nn + cg)       = ((uint32_t)bfbits(h1) << 16) | bfbits(h0);
                *(uint32_t*)(Chi + (size_t)(r0 + 8) * Nn + cg) = ((uint32_t)bfbits(h3) << 16) | bfbits(h2);
                *(uint32_t*)(Clo + (size_t)r0 * Nn + cg)       = ((uint32_t)bfbits(l1) << 16) | bfbits(l0);
                *(uint32_t*)(Clo + (size_t)(r0 + 8) * Nn + cg) = ((uint32_t)bfbits(l3) << 16) | bfbits(l2);
            } else {
                *(float2*)(Cf + (size_t)r0 * Nn + cg)       = make_float2(v0, v1);
                *(float2*)(Cf + (size_t)(r0 + 8) * Nn + cg) = make_float2(v2, v3);
            }
        }
    }
}

// ---------------- small kernels ----------------
__global__ void k_meanT(const float* __restrict__ h) {
    int idx = blockIdx.x * blockDim.x + threadIdx.x;
    if (idx >= B_*H_) return;
    int b = idx >> 10, hh = idx & 1023;
    const float* p = h + (size_t)b * T_ * H_ + hh;
    float s = 0.f;
    #pragma unroll 8
    for (int t = 0; t < T_; t++) s += p[(size_t)t * H_];
    g_hgate[idx] = s * (1.0f / T_);
}

__global__ void k_meanB() {
    int hh = blockIdx.x * blockDim.x + threadIdx.x;
    if (hh >= H_) return;
    float s = 0.f;
    #pragma unroll
    for (int b = 0; b < B_; b++) s += g_hgate[b * H_ + hh];
    g_hmean[hh] = s * (1.0f / B_);
}

// E_cur = normalize(E_dyn + h_mean) -> split bf16
__global__ __launch_bounds__(256) void k_enorm(const float* __restrict__ E_dyn) {
    int i = blockIdx.x;
    __shared__ float red[256];
    float vals[4];
    float ss = 0.f;
    #pragma unroll
    for (int j = 0; j < 4; j++) {
        int hh = threadIdx.x + j * 256;
        float v = E_dyn[i * H_ + hh] + g_hmean[hh];
        vals[j] = v; ss += v * v;
    }
    red[threadIdx.x] = ss; __syncthreads();
    for (int off = 128; off > 0; off >>= 1) {
        if (threadIdx.x < off) red[threadIdx.x] += red[threadIdx.x + off];
        __syncthreads();
    }
    float inv = 1.0f / fmaxf(sqrtf(red[0]), 1e-12f);
    #pragma unroll
    for (int j = 0; j < 4; j++) {
        int hh = threadIdx.x + j * 256;
        float v = vals[j] * inv;
        bf16 h = __float2bfloat16(v);
        g_Ehi[i * H_ + hh] = h;
        g_Elo[i * H_ + hh] = __float2bfloat16(v - __bfloat162float(h));
    }
}

__global__ __launch_bounds__(256) void k_rowsum() {
    int i = blockIdx.x;
    __shared__ float red[256];
    float s = 0.f;
    for (int j = threadIdx.x; j < N_; j += 256) s += g_S[i * N_ + j];
    red[threadIdx.x] = s; __syncthreads();
    for (int off = 128; off > 0; off >>= 1) {
        if (threadIdx.x < off) red[threadIdx.x] += red[threadIdx.x + off];
        __syncthreads();
    }
    if (threadIdx.x == 0) g_rowsum[i] = red[0];
}

__global__ void k_gate1(const float* __restrict__ W1, const float* __restrict__ b1) {
    int idx = blockIdx.x * blockDim.x + threadIdx.x;
    if (idx >= B_*HID_) return;
    int b = idx >> 9, m = idx & 511;
    const float* x = g_hgate + b * H_;
    float s = b1[m];
    for (int k = 0; k < H_; k++) s += x[k] * W1[k * HID_ + m];
    g_hid[idx] = 0.5f * s * (1.0f + erff(s * 0.70710678118654752f));
}

__global__ void k_gate2(const float* __restrict__ W2, const float* __restrict__ b2) {
    int idx = blockIdx.x * blockDim.x + threadIdx.x;
    if (idx >= B_*N_) return;
    int b = idx >> 10, n = idx & 1023;
    const float* x = g_hid + b * HID_;
    float s = b2[n];
    for (int k = 0; k < HID_; k++) s += x[k] * W2[k * N_ + n];
    g_gamma[idx] = 1.0f / (1.0f + expf(-s));
}

__global__ void k_gmean() {
    int n = blockIdx.x * blockDim.x + threadIdx.x;
    if (n >= N_) return;
    float s = 0.f;
    #pragma unroll
    for (int b = 0; b < B_; b++) s += g_gamma[b * N_ + n];
    g_gmean[n] = s * (1.0f / B_);
}

// A_mix[m][n] = (alpha*Ap[m][n] + (1-alpha)*A_dyn_sym[m][n]) * gmean[m] -> split + fp32
__global__ void k_amix(const float* __restrict__ Ap, const float* __restrict__ alpha_raw) {
    int idx = blockIdx.x * blockDim.x + threadIdx.x;
    if (idx >= N_*N_) return;
    int m = idx >> 10, n = idx & 1023;
    float alpha = 1.0f / (1.0f + expf(-alpha_raw[0]));
    float ad = 0.5f * (g_S[idx] / (g_rowsum[m] + 1e-6f) + g_S[n * N_ + m] / (g_rowsum[n] + 1e-6f));
    float v = (alpha * Ap[idx] + (1.0f - alpha) * ad) * g_gmean[m];
    bf16 h = __float2bfloat16(v);
    g_Amh[idx] = h;
    g_Aml[idx] = __float2bfloat16(v - __bfloat162float(h));
    g_Amf[idx] = v;
}

// fp32 -> bf16 hi/lo split
__global__ void k_split(const float* __restrict__ x, bf16* __restrict__ hi, bf16* __restrict__ lo, int n4) {
    for (int i = blockIdx.x * blockDim.x + threadIdx.x; i < n4; i += gridDim.x * blockDim.x) {
        float4 v = ((const float4*)x)[i];
        bf16 h0 = __float2bfloat16(v.x), h1 = __float2bfloat16(v.y);
        bf16 h2 = __float2bfloat16(v.z), h3 = __float2bfloat16(v.w);
        bf16 l0 = __float2bfloat16(v.x - __bfloat162float(h0));
        bf16 l1 = __float2bfloat16(v.y - __bfloat162float(h1));
        bf16 l2 = __float2bfloat16(v.z - __bfloat162float(h2));
        bf16 l3 = __float2bfloat16(v.w - __bfloat162float(h3));
        uint2 hv, lv;
        hv.x = ((uint32_t)bfbits(h1) << 16) | bfbits(h0);
        hv.y = ((uint32_t)bfbits(h3) << 16) | bfbits(h2);
        lv.x = ((uint32_t)bfbits(l1) << 16) | bfbits(l0);
        lv.y = ((uint32_t)bfbits(l3) << 16) | bfbits(l2);
        ((uint2*)hi)[i] = hv;
        ((uint2*)lo)[i] = lv;
    }
}

// transpose [Rin,Cin] -> [Cin,Rin] + split bf16
__global__ void k_tsplit(const float* __restrict__ W, bf16* __restrict__ Oh, bf16* __restrict__ Ol,
                         int Rin, int Cin) {
    __shared__ float t[32][33];
    int c0 = blockIdx.x * 32, r0 = blockIdx.y * 32;
    #pragma unroll
    for (int i = 0; i < 4; i++)
        t[threadIdx.y + i * 8][threadIdx.x] = W[(size_t)(r0 + threadIdx.y + i * 8) * Cin + c0 + threadIdx.x];
    __syncthreads();
    #pragma unroll
    for (int i = 0; i < 4; i++) {
        int oc = threadIdx.y + i * 8;
        float v = t[threadIdx.x][oc];
        size_t o = (size_t)(c0 + oc) * Rin + r0 + threadIdx.x;
        bf16 h = __float2bfloat16(v);
        Oh[o] = h;
        Ol[o] = __float2bfloat16(v - __bfloat162float(h));
    }
}

// u[m] = sum_n A_mix[m][n] * b1[n]
__global__ __launch_bounds__(256) void k_bias_u(const float* __restrict__ b1) {
    int m = blockIdx.x;
    __shared__ float red[256];
    float s = 0.f;
    for (int n = threadIdx.x; n < N_; n += 256) s += g_Amf[m * N_ + n] * b1[n];
    red[threadIdx.x] = s; __syncthreads();
    for (int off = 128; off > 0; off >>= 1) {
        if (threadIdx.x < off) red[threadIdx.x] += red[threadIdx.x + off];
        __syncthreads();
    }
    if (threadIdx.x == 0) g_u[m] = red[0];
}

// cvec[h'] = sum_m u[m] * n2h_W[m][h'] + b2[h']
__global__ void k_bias_c(const float* __restrict__ W2, const float* __restrict__ b2) {
    int h = blockIdx.x * blockDim.x + threadIdx.x;
    if (h >= H_) return;
    float s = b2[h];
    for (int m = 0; m < N_; m++) s += g_u[m] * W2[(size_t)m * H_ + h];
    g_cvec[h] = s;
}

// y = h_time*(1+tanh(1/N)) + msg -> LayerNorm
__global__ __launch_bounds__(256) void k_final(const float* __restrict__ h,
                                               const float* __restrict__ lw,
                                               const float* __restrict__ lb,
                                               float* __restrict__ out) {
    int row = blockIdx.x;
    size_t base = (size_t)row * H_ + threadIdx.x * 4;
    const float gw = 1.0f + tanhf(1.0f / 1024.0f);
    float4 a = *(const float4*)(h + base);
    float4 m = *(const float4*)(g_msg + base);
    float v0 = a.x * gw + m.x, v1 = a.y * gw + m.y;
    float v2 = a.z * gw + m.z, v3 = a.w * gw + m.w;

    __shared__ float red[256];
    red[threadIdx.x] = v0 + v1 + v2 + v3;
    __syncthreads();
    for (int off = 128; off > 0; off >>= 1) {
        if (threadIdx.x < off) red[threadIdx.x] += red[threadIdx.x + off];
        __syncthreads();
    }
    float mu = red[0] * (1.0f / H_);
    __syncthreads();
    float d0 = v0 - mu, d1 = v1 - mu, d2 = v2 - mu, d3 = v3 - mu;
    red[threadIdx.x] = d0 * d0 + d1 * d1 + d2 * d2 + d3 * d3;
    __syncthreads();
    for (int off = 128; off > 0; off >>= 1) {
        if (threadIdx.x < off) red[threadIdx.x] += red[threadIdx.x + off];
        __syncthreads();
    }
    float rstd = rsqrtf(red[0] * (1.0f / H_) + 1e-5f);
    float4 w = *(const float4*)(lw + threadIdx.x * 4);
    float4 bb = *(const float4*)(lb + threadIdx.x * 4);
    float4 o;
    o.x = d0 * rstd * w.x + bb.x;
    o.y = d1 * rstd * w.y + bb.y;
    o.z = d2 * rstd * w.z + bb.z;
    o.w = d3 * rstd * w.w + bb.w;
    *(float4*)(out + base) = o;
}

// ---------------- launcher ----------------
extern "C" void kernel_launch(void* const* d_in, const int* in_sizes, int n_in,
                              void* d_out, int out_size) {
    const float* h_time    = (const float*)d_in[0];
    const float* A_pearson = (const float*)d_in[1];
    const float* E_dyn     = (const float*)d_in[2];
    const float* alpha_raw = (const float*)d_in[3];
    // d_in[4] = tau_raw : analytically eliminated (mean over softmax axis == 1/N)
    const float* gate_W1   = (const float*)d_in[5];
    const float* gate_b1   = (const float*)d_in[6];
    const float* gate_W2   = (const float*)d_in[7];
    const float* gate_b2   = (const float*)d_in[8];
    const float* h2n_W     = (const float*)d_in[9];
    const float* h2n_b     = (const float*)d_in[10];
    const float* n2h_W     = (const float*)d_in[11];
    const float* n2h_b     = (const float*)d_in[12];
    const float* ln_w      = (const float*)d_in[13];
    const float* ln_b      = (const float*)d_in[14];
    float* out = (float*)d_out;

    bf16 *p_Ehi, *p_Elo, *p_Amh, *p_Aml, *p_W1h, *p_W1l, *p_W2th, *p_W2tl;
    bf16 *p_Ph, *p_Pl, *p_Mh, *p_Ml, *p_hAh, *p_hAl;
    float *p_S, *p_msg, *p_cvec;
    cudaGetSymbolAddress((void**)&p_Ehi, g_Ehi);   cudaGetSymbolAddress((void**)&p_Elo, g_Elo);
    cudaGetSymbolAddress((void**)&p_Amh, g_Amh);   cudaGetSymbolAddress((void**)&p_Aml, g_Aml);
    cudaGetSymbolAddress((void**)&p_W1h, g_W1h);   cudaGetSymbolAddress((void**)&p_W1l, g_W1l);
    cudaGetSymbolAddress((void**)&p_W2th, g_W2th); cudaGetSymbolAddress((void**)&p_W2tl, g_W2tl);
    cudaGetSymbolAddress((void**)&p_Ph, g_Ph);     cudaGetSymbolAddress((void**)&p_Pl, g_Pl);
    cudaGetSymbolAddress((void**)&p_Mh, g_Mh);     cudaGetSymbolAddress((void**)&p_Ml, g_Ml);
    cudaGetSymbolAddress((void**)&p_hAh, g_hAh);   cudaGetSymbolAddress((void**)&p_hAl, g_hAl);
    cudaGetSymbolAddress((void**)&p_S, g_S);       cudaGetSymbolAddress((void**)&p_msg, g_msg);
    cudaGetSymbolAddress((void**)&p_cvec, g_cvec);

    cudaFuncSetAttribute(hgemm<0, 1>, cudaFuncAttributeMaxDynamicSharedMemorySize, GEMM_SMEM);
    cudaFuncSetAttribute(hgemm<1, 0>, cudaFuncAttributeMaxDynamicSharedMemorySize, GEMM_SMEM);
    cudaFuncSetAttribute(hgemm<2, 0>, cudaFuncAttributeMaxDynamicSharedMemorySize, GEMM_SMEM);

    // reductions + E_cur
    k_meanT<<<(B_*H_ + 255) / 256, 256>>>(h_time);
    k_meanB<<<(H_ + 255) / 256, 256>>>();
    k_enorm<<<N_, 256>>>(E_dyn);

    // independent input conversions
    k_split<<<2048, 256>>>(h_time, p_hAh, p_hAl, BT_*H_ / 4);
    k_split<<<512, 256>>>(h2n_W, p_W1h, p_W1l, H_*N_ / 4);
    {
        dim3 b(32, 8);
        k_tsplit<<<dim3(H_ / 32, N_ / 32), b>>>(n2h_W, p_W2th, p_W2tl, N_, H_);  // [N,H]->[H,N]
    }

    // S = relu(E_cur @ E_cur^T)
    hgemm<1, 0><<<dim3(N_ / 128, N_ / 128), 256, GEMM_SMEM>>>(
        p_Ehi, p_Elo, p_Ehi, p_Elo, nullptr, p_S, nullptr, nullptr, N_, N_, H_);
    k_rowsum<<<N_, 256>>>();

    // gate MLP
    k_gate1<<<(B_*HID_ + 255) / 256, 256>>>(gate_W1, gate_b1);
    k_gate2<<<(B_*N_ + 255) / 256, 256>>>(gate_W2, gate_b2);
    k_gmean<<<(N_ + 255) / 256, 256>>>();
    k_amix<<<(N_*N_ + 255) / 256, 256>>>(A_pearson, alpha_raw);

    // Mcomb^T = (W1 @ AmixT @ W2)^T via two small GEMMs
    dim3 gSq(N_ / 128, H_ / 128);
    // P[h][m] = sum_n W1[h][n] * Amix[m][n]
    hgemm<2, 0><<<gSq, 256, GEMM_SMEM>>>(p_W1h, p_W1l, p_Amh, p_Aml, nullptr,
                                         nullptr, p_Ph, p_Pl, H_, N_, N_);
    // McombT[h'][h] = sum_m W2t[h'][m] * P[h][m]
    hgemm<2, 0><<<dim3(H_ / 128, H_ / 128), 256, GEMM_SMEM>>>(
        p_W2th, p_W2tl, p_Ph, p_Pl, nullptr, nullptr, p_Mh, p_Ml, H_, H_, N_);

    // bias fold: cvec = b1 @ AmixT @ W2 + b2  (exact fp32)
    k_bias_u<<<N_, 256>>>(h2n_b);
    k_bias_c<<<(H_ + 255) / 256, 256>>>(n2h_W, n2h_b);

    // msg = h_time @ Mcomb + cvec  (THE big GEMM, 1 instead of 3)
    hgemm<0, 1><<<dim3(H_ / 128, BT_ / 128), 256, GEMM_SMEM>>>(
        p_hAh, p_hAl, p_Mh, p_Ml, p_cvec, p_msg, nullptr, nullptr, BT_, H_, H_);

    // fused residual + LayerNorm
    k_final<<<BT_, 256>>>(h_time, ln_w, ln_b, out);
}

// round 4
// speedup vs baseline: 3.6469x; 1.2434x over previous
#include <cuda_runtime.h>
#include <cuda_bf16.h>
#include <cuda_fp16.h>
#include <math.h>
#include <stdint.h>

#define N_ 1024
#define H_ 1024
#define B_ 64
#define T_ 256
#define BT_ (B_*T_)
#define HID_ 512

typedef __nv_bfloat16 bf16;

// ---------------- scratch (static device globals; no allocation) ----------------
__device__ __half g_hA16[BT_*H_];                  // h_time fp16
__device__ float g_hgate[B_*H_];
__device__ bf16  g_hgHi[128*H_], g_hgLo[128*H_];   // h_gate split, padded to 128 rows
__device__ float g_hmean[H_];
__device__ bf16  g_Ehi[N_*H_], g_Elo[N_*H_];
__device__ float g_S[N_*N_];
__device__ float g_rowsum[N_];
__device__ bf16  g_G1h[HID_*H_], g_G1l[HID_*H_];   // gate_W1^T [512,1024] split
__device__ bf16  g_G2h[N_*HID_], g_G2l[N_*HID_];   // gate_W2^T [1024,512] split
__device__ bf16  g_hidh[128*HID_], g_hidl[128*HID_];
__device__ float g_gamma[128*N_];
__device__ float g_gmean[N_];
__device__ bf16  g_Amh[N_*N_], g_Aml[N_*N_];       // A_mix [m][n] split
__device__ float g_Amf[N_*N_];                      // A_mix fp32 (bias fold)
__device__ bf16  g_W1h[H_*N_], g_W1l[H_*N_];       // h2n_W [H,N] split
__device__ bf16  g_W2th[H_*N_], g_W2tl[H_*N_];     // n2h_W^T [H,N] split
__device__ bf16  g_Ph[H_*N_], g_Pl[H_*N_];         // P = W1 @ AmixT
__device__ __half g_M16h[H_*H_], g_M16l[H_*H_];    // McombT fp16 split
__device__ float g_u[N_];
__device__ float g_cvec[H_];
__device__ float g_msg[BT_*H_];

// ---------------- helpers ----------------
__device__ __forceinline__ unsigned short bfbits(bf16 x) {
    return *reinterpret_cast<unsigned short*>(&x);
}
__device__ __forceinline__ unsigned short hfbits(__half x) {
    return *reinterpret_cast<unsigned short*>(&x);
}
__device__ __forceinline__ uint32_t smem_u32(const void* p) {
    uint32_t a;
    asm("{ .reg .u64 t; cvta.to.shared.u64 t, %1; cvt.u32.u64 %0, t; }" : "=r"(a) : "l"(p));
    return a;
}
__device__ __forceinline__ uint32_t swz(uint32_t off) {
    return off ^ ((off >> 3) & 0x70);
}
#define CP_COMMIT() asm volatile("cp.async.commit_group;" ::: "memory")

__device__ __forceinline__ void ldsm4(uint32_t (&r)[4], uint32_t addr) {
    asm volatile("ldmatrix.sync.aligned.m8n8.x4.shared.b16 {%0,%1,%2,%3}, [%4];"
        : "=r"(r[0]), "=r"(r[1]), "=r"(r[2]), "=r"(r[3]) : "r"(addr));
}
__device__ __forceinline__ void mma_bf(float* c, const uint32_t* a, uint32_t b0, uint32_t b1) {
    asm volatile("mma.sync.aligned.m16n8k16.row.col.f32.bf16.bf16.f32 "
        "{%0,%1,%2,%3}, {%4,%5,%6,%7}, {%8,%9}, {%0,%1,%2,%3};"
        : "+f"(c[0]), "+f"(c[1]), "+f"(c[2]), "+f"(c[3])
        : "r"(a[0]), "r"(a[1]), "r"(a[2]), "r"(a[3]), "r"(b0), "r"(b1));
}
__device__ __forceinline__ void mma_fp(float* c, const uint32_t* a, uint32_t b0, uint32_t b1) {
    asm volatile("mma.sync.aligned.m16n8k16.row.col.f32.f16.f16.f32 "
        "{%0,%1,%2,%3}, {%4,%5,%6,%7}, {%8,%9}, {%0,%1,%2,%3};"
        : "+f"(c[0]), "+f"(c[1]), "+f"(c[2]), "+f"(c[3])
        : "r"(a[0]), "r"(a[1]), "r"(a[2]), "r"(a[3]), "r"(b0), "r"(b1));
}

// load one 128row x 64col 16-bit tile (SW128 swizzled, 128B/row); 256 threads
__device__ __forceinline__ void ld_tile(uint32_t sdst, const void* __restrict__ g,
                                        int row0, int K, int kc, int tid) {
    const int row = tid >> 1, half = tid & 1;
    const char* src = (const char*)g + (((size_t)(row0 + row) * K + (kc << 6)) << 1) + half * 64;
    uint32_t rb = (uint32_t)row * 128 + (uint32_t)half * 64;
    #pragma unroll
    for (int j = 0; j < 4; j++) {
        uint32_t sw = swz(rb + (j << 4));
        asm volatile("cp.async.cg.shared.global [%0], [%1], 16;"
            :: "r"(sdst + sw), "l"(src + (j << 4)));
    }
}

// ---------------- split-bf16 HMMA GEMM (TN), 3 passes: C = (Ah+Al)(Bh+Bl)^T - Al*Bl
// OUT_MODE: 0 f32(+bias), 1 f32 relu, 2 split bf16, 3 gelu->split bf16, 4 sigmoid->f32, 5 split fp16
#define TILE_B 16384
#define BUF_B  65536
#define GEMM_SMEM (1024 + 2 * BUF_B)

template<int OUT_MODE, int BIAS>
__global__ __launch_bounds__(256, 1) void hgemm(
    const bf16* __restrict__ Ahi, const bf16* __restrict__ Alo,
    const bf16* __restrict__ Bhi, const bf16* __restrict__ Blo,
    const float* __restrict__ bias,
    float* __restrict__ Cf, bf16* __restrict__ Chi, bf16* __restrict__ Clo,
    int M, int Nn, int K)
{
    extern __shared__ __align__(1024) char smem[];
    uint32_t sb = smem_u32(smem);
    const int tid = threadIdx.x;
    const int wid = tid >> 5, lane = tid & 31;
    const int wm = wid >> 1, wn = wid & 1;
    const int bx = blockIdx.x, by = blockIdx.y;

    float* sBias = (float*)(smem + 512);
    if (BIAS && tid < 128) sBias[tid] = bias[bx * 128 + tid];

    const uint32_t T0 = sb + 1024;
    const int NK = K >> 6;
    const int arow0 = by * 128, brow0 = bx * 128;

    float acc[2][8][4];
    #pragma unroll
    for (int i = 0; i < 2; i++)
        #pragma unroll
        for (int j = 0; j < 8; j++)
            #pragma unroll
            for (int l = 0; l < 4; l++) acc[i][j][l] = 0.f;

    const int mi = lane >> 3, li = lane & 7;
    const int rowoff = (mi & 1) * 8 + li;
    const int coloff = (mi >> 1) * 16;

    ld_tile(T0,              Ahi, arow0, K, 0, tid);
    ld_tile(T0 + TILE_B,     Alo, arow0, K, 0, tid);
    ld_tile(T0 + 2 * TILE_B, Bhi, brow0, K, 0, tid);
    ld_tile(T0 + 3 * TILE_B, Blo, brow0, K, 0, tid);
    CP_COMMIT();

    for (int kc = 0; kc < NK; kc++) {
        const int cur = kc & 1;
        if (kc + 1 < NK) {
            uint32_t nb = T0 + (cur ^ 1) * BUF_B;
            ld_tile(nb,              Ahi, arow0, K, kc + 1, tid);
            ld_tile(nb + TILE_B,     Alo, arow0, K, kc + 1, tid);
            ld_tile(nb + 2 * TILE_B, Bhi, brow0, K, kc + 1, tid);
            ld_tile(nb + 3 * TILE_B, Blo, brow0, K, kc + 1, tid);
            CP_COMMIT();
            asm volatile("cp.async.wait_group 1;" ::: "memory");
        } else {
            asm volatile("cp.async.wait_group 0;" ::: "memory");
        }
        __syncthreads();

        const uint32_t Ah = T0 + cur * BUF_B;
        const uint32_t Al = Ah + TILE_B;
        const uint32_t Bh = Ah + 2 * TILE_B;
        const uint32_t Bl = Ah + 3 * TILE_B;

        #pragma unroll
        for (int ks = 0; ks < 4; ks++) {
            const int kb = ks * 32;
            uint32_t ahi[2][4], alo[2][4];
            #pragma unroll
            for (int mt = 0; mt < 2; mt++) {
                uint32_t ra = swz((uint32_t)(wm * 32 + mt * 16 + rowoff) * 128 + kb + coloff);
                ldsm4(ahi[mt], Ah + ra);
                ldsm4(alo[mt], Al + ra);
            }
            #pragma unroll
            for (int g = 0; g < 4; g++) {
                uint32_t rb = swz((uint32_t)(wn * 64 + g * 16 + rowoff) * 128 + kb + coloff);
                uint32_t bh[4], bl[4];
                ldsm4(bh, Bh + rb);
                ldsm4(bl, Bl + rb);
                #pragma unroll
                for (int mt = 0; mt < 2; mt++) {
                    #pragma unroll
                    for (int sub = 0; sub < 2; sub++) {
                        float* c = acc[mt][g * 2 + sub];
                        mma_bf(c, ahi[mt], bh[sub], bh[2 + sub]);
                        mma_bf(c, ahi[mt], bl[sub], bl[2 + sub]);
                        mma_bf(c, alo[mt], bh[sub], bh[2 + sub]);
                    }
                }
            }
        }
        __syncthreads();
    }

    #pragma unroll
    for (int mt = 0; mt < 2; mt++) {
        #pragma unroll
        for (int nt = 0; nt < 8; nt++) {
            const int r0 = by * 128 + wm * 32 + mt * 16 + (lane >> 2);
            const int cb = wn * 64 + nt * 8 + (lane & 3) * 2;
            const int cg = bx * 128 + cb;
            float v0 = acc[mt][nt][0], v1 = acc[mt][nt][1];
            float v2 = acc[mt][nt][2], v3 = acc[mt][nt][3];
            if (BIAS) {
                float bb0 = sBias[cb], bb1 = sBias[cb + 1];
                v0 += bb0; v1 += bb1; v2 += bb0; v3 += bb1;
            }
            if (OUT_MODE == 1) {
                v0 = fmaxf(v0, 0.f); v1 = fmaxf(v1, 0.f);
                v2 = fmaxf(v2, 0.f); v3 = fmaxf(v3, 0.f);
            }
            if (OUT_MODE == 3) {
                const float is2 = 0.70710678118654752f;
                v0 = 0.5f * v0 * (1.0f + erff(v0 * is2));
                v1 = 0.5f * v1 * (1.0f + erff(v1 * is2));
                v2 = 0.5f * v2 * (1.0f + erff(v2 * is2));
                v3 = 0.5f * v3 * (1.0f + erff(v3 * is2));
            }
            if (OUT_MODE == 4) {
                v0 = 1.0f / (1.0f + expf(-v0)); v1 = 1.0f / (1.0f + expf(-v1));
                v2 = 1.0f / (1.0f + expf(-v2)); v3 = 1.0f / (1.0f + expf(-v3));
            }
            if (OUT_MODE == 2 || OUT_MODE == 3) {
                bf16 h0 = __float2bfloat16(v0), h1 = __float2bfloat16(v1);
                bf16 h2 = __float2bfloat16(v2), h3 = __float2bfloat16(v3);
                bf16 l0 = __float2bfloat16(v0 - __bfloat162float(h0));
                bf16 l1 = __float2bfloat16(v1 - __bfloat162float(h1));
                bf16 l2 = __float2bfloat16(v2 - __bfloat162float(h2));
                bf16 l3 = __float2bfloat16(v3 - __bfloat162float(h3));
                *(uint32_t*)(Chi + (size_t)r0 * Nn + cg)       = ((uint32_t)bfbits(h1) << 16) | bfbits(h0);
                *(uint32_t*)(Chi + (size_t)(r0 + 8) * Nn + cg) = ((uint32_t)bfbits(h3) << 16) | bfbits(h2);
                *(uint32_t*)(Clo + (size_t)r0 * Nn + cg)       = ((uint32_t)bfbits(l1) << 16) | bfbits(l0);
                *(uint32_t*)(Clo + (size_t)(r0 + 8) * Nn + cg) = ((uint32_t)bfbits(l3) << 16) | bfbits(l2);
            } else if (OUT_MODE == 5) {
                __half* Hh = (__half*)Chi;
                __half* Hl = (__half*)Clo;
                __half h0 = __float2half(v0), h1 = __float2half(v1);
                __half h2 = __float2half(v2), h3 = __float2half(v3);
                __half l0 = __float2half(v0 - __half2float(h0));
                __half l1 = __float2half(v1 - __half2float(h1));
                __half l2 = __float2half(v2 - __half2float(h2));
                __half l3 = __float2half(v3 - __half2float(h3));
                *(uint32_t*)(Hh + (size_t)r0 * Nn + cg)       = ((uint32_t)hfbits(h1) << 16) | hfbits(h0);
                *(uint32_t*)(Hh + (size_t)(r0 + 8) * Nn + cg) = ((uint32_t)hfbits(h3) << 16) | hfbits(h2);
                *(uint32_t*)(Hl + (size_t)r0 * Nn + cg)       = ((uint32_t)hfbits(l1) << 16) | hfbits(l0);
                *(uint32_t*)(Hl + (size_t)(r0 + 8) * Nn + cg) = ((uint32_t)hfbits(l3) << 16) | hfbits(l2);
            } else {
                *(float2*)(Cf + (size_t)r0 * Nn + cg)       = make_float2(v0, v1);
                *(float2*)(Cf + (size_t)(r0 + 8) * Nn + cg) = make_float2(v2, v3);
            }
        }
    }
}

// ---------------- fp16 2-pass GEMM: C = A @ (Bh+Bl)^T + bias, 3-stage pipeline ----------------
#define FTILE_B 16384
#define FSTAGE_B (3 * FTILE_B)
#define FGEMM_SMEM (1024 + 3 * FSTAGE_B)

__global__ __launch_bounds__(256, 1) void fgemm(
    const __half* __restrict__ A,
    const __half* __restrict__ Bh, const __half* __restrict__ Bl,
    const float* __restrict__ bias,
    float* __restrict__ Cf, int M, int Nn, int K)
{
    extern __shared__ __align__(1024) char smem[];
    uint32_t sb = smem_u32(smem);
    const int tid = threadIdx.x;
    const int wid = tid >> 5, lane = tid & 31;
    const int wm = wid >> 1, wn = wid & 1;
    const int bx = blockIdx.x, by = blockIdx.y;

    float* sBias = (float*)(smem + 512);
    if (tid < 128) sBias[tid] = bias[bx * 128 + tid];

    const uint32_t T0 = sb + 1024;
    const int NK = K >> 6;
    const int arow0 = by * 128, brow0 = bx * 128;

    float acc[2][8][4];
    #pragma unroll
    for (int i = 0; i < 2; i++)
        #pragma unroll
        for (int j = 0; j < 8; j++)
            #pragma unroll
            for (int l = 0; l < 4; l++) acc[i][j][l] = 0.f;

    const int mi = lane >> 3, li = lane & 7;
    const int rowoff = (mi & 1) * 8 + li;
    const int coloff = (mi >> 1) * 16;

    // prologue: stage 0, 1
    #pragma unroll
    for (int s = 0; s < 2; s++) {
        uint32_t st = T0 + s * FSTAGE_B;
        ld_tile(st,                A,  arow0, K, s, tid);
        ld_tile(st + FTILE_B,      Bh, brow0, K, s, tid);
        ld_tile(st + 2 * FTILE_B,  Bl, brow0, K, s, tid);
        CP_COMMIT();
    }

    for (int kc = 0; kc < NK; kc++) {
        if (kc == NK - 1) asm volatile("cp.async.wait_group 0;" ::: "memory");
        else              asm volatile("cp.async.wait_group 1;" ::: "memory");
        __syncthreads();

        if (kc + 2 < NK) {
            uint32_t st = T0 + ((kc + 2) % 3) * FSTAGE_B;
            ld_tile(st,               A,  arow0, K, kc + 2, tid);
            ld_tile(st + FTILE_B,     Bh, brow0, K, kc + 2, tid);
            ld_tile(st + 2 * FTILE_B, Bl, brow0, K, kc + 2, tid);
            CP_COMMIT();
        }

        const uint32_t Sa = T0 + (kc % 3) * FSTAGE_B;
        const uint32_t Sh = Sa + FTILE_B;
        const uint32_t Sl = Sa + 2 * FTILE_B;

        #pragma unroll
        for (int ks = 0; ks < 4; ks++) {
            const int kb = ks * 32;
            uint32_t a[2][4];
            #pragma unroll
            for (int mt = 0; mt < 2; mt++) {
                uint32_t ra = swz((uint32_t)(wm * 32 + mt * 16 + rowoff) * 128 + kb + coloff);
                ldsm4(a[mt], Sa + ra);
            }
            #pragma unroll
            for (int g = 0; g < 4; g++) {
                uint32_t rb = swz((uint32_t)(wn * 64 + g * 16 + rowoff) * 128 + kb + coloff);
                uint32_t bh[4], bl[4];
                ldsm4(bh, Sh + rb);
                ldsm4(bl, Sl + rb);
                #pragma unroll
                for (int mt = 0; mt < 2; mt++) {
                    #pragma unroll
                    for (int sub = 0; sub < 2; sub++) {
                        float* c = acc[mt][g * 2 + sub];
                        mma_fp(c, a[mt], bh[sub], bh[2 + sub]);
                        mma_fp(c, a[mt], bl[sub], bl[2 + sub]);
                    }
                }
            }
        }
    }

    #pragma unroll
    for (int mt = 0; mt < 2; mt++) {
        #pragma unroll
        for (int nt = 0; nt < 8; nt++) {
            const int r0 = by * 128 + wm * 32 + mt * 16 + (lane >> 2);
            const int cb = wn * 64 + nt * 8 + (lane & 3) * 2;
            const int cg = bx * 128 + cb;
            float bb0 = sBias[cb], bb1 = sBias[cb + 1];
            *(float2*)(Cf + (size_t)r0 * Nn + cg) =
                make_float2(acc[mt][nt][0] + bb0, acc[mt][nt][1] + bb1);
            *(float2*)(Cf + (size_t)(r0 + 8) * Nn + cg) =
                make_float2(acc[mt][nt][2] + bb0, acc[mt][nt][3] + bb1);
        }
    }
}

// ---------------- small kernels ----------------
// fused: h_time -> fp16 copy + h_gate (mean over T) fp32 + bf16 split
__global__ __launch_bounds__(256) void k_pre(const float* __restrict__ h) {
    int b = blockIdx.y;
    int hh = blockIdx.x * 256 + threadIdx.x;
    const float* p = h + (size_t)b * T_ * H_ + hh;
    __half* q = g_hA16 + (size_t)b * T_ * H_ + hh;
    float s = 0.f;
    #pragma unroll 4
    for (int t = 0; t < T_; t++) {
        float v = p[(size_t)t * H_];
        q[(size_t)t * H_] = __float2half(v);
        s += v;
    }
    float mean = s * (1.0f / T_);
    g_hgate[b * H_ + hh] = mean;
    bf16 hi = __float2bfloat16(mean);
    g_hgHi[b * H_ + hh] = hi;
    g_hgLo[b * H_ + hh] = __float2bfloat16(mean - __bfloat162float(hi));
}

__global__ void k_padzero() {
    int i = blockIdx.x * blockDim.x + threadIdx.x;
    if (i >= 64 * H_) return;
    g_hgHi[64 * H_ + i] = __float2bfloat16(0.f);
    g_hgLo[64 * H_ + i] = __float2bfloat16(0.f);
}

__global__ void k_meanB() {
    int hh = blockIdx.x * blockDim.x + threadIdx.x;
    if (hh >= H_) return;
    float s = 0.f;
    #pragma unroll
    for (int b = 0; b < B_; b++) s += g_hgate[b * H_ + hh];
    g_hmean[hh] = s * (1.0f / B_);
}

__global__ __launch_bounds__(256) void k_enorm(const float* __restrict__ E_dyn) {
    int i = blockIdx.x;
    __shared__ float red[256];
    float vals[4];
    float ss = 0.f;
    #pragma unroll
    for (int j = 0; j < 4; j++) {
        int hh = threadIdx.x + j * 256;
        float v = E_dyn[i * H_ + hh] + g_hmean[hh];
        vals[j] = v; ss += v * v;
    }
    red[threadIdx.x] = ss; __syncthreads();
    for (int off = 128; off > 0; off >>= 1) {
        if (threadIdx.x < off) red[threadIdx.x] += red[threadIdx.x + off];
        __syncthreads();
    }
    float inv = 1.0f / fmaxf(sqrtf(red[0]), 1e-12f);
    #pragma unroll
    for (int j = 0; j < 4; j++) {
        int hh = threadIdx.x + j * 256;
        float v = vals[j] * inv;
        bf16 h = __float2bfloat16(v);
        g_Ehi[i * H_ + hh] = h;
        g_Elo[i * H_ + hh] = __float2bfloat16(v - __bfloat162float(h));
    }
}

__global__ __launch_bounds__(256) void k_rowsum() {
    int i = blockIdx.x;
    __shared__ float red[256];
    float s = 0.f;
    for (int j = threadIdx.x; j < N_; j += 256) s += g_S[i * N_ + j];
    red[threadIdx.x] = s; __syncthreads();
    for (int off = 128; off > 0; off >>= 1) {
        if (threadIdx.x < off) red[threadIdx.x] += red[threadIdx.x + off];
        __syncthreads();
    }
    if (threadIdx.x == 0) g_rowsum[i] = red[0];
}

__global__ void k_gmean() {
    int n = blockIdx.x * blockDim.x + threadIdx.x;
    if (n >= N_) return;
    float s = 0.f;
    #pragma unroll
    for (int b = 0; b < B_; b++) s += g_gamma[b * N_ + n];
    g_gmean[n] = s * (1.0f / B_);
}

__global__ void k_amix(const float* __restrict__ Ap, const float* __restrict__ alpha_raw) {
    int idx = blockIdx.x * blockDim.x + threadIdx.x;
    if (idx >= N_*N_) return;
    int m = idx >> 10, n = idx & 1023;
    float alpha = 1.0f / (1.0f + expf(-alpha_raw[0]));
    float ad = 0.5f * (g_S[idx] / (g_rowsum[m] + 1e-6f) + g_S[n * N_ + m] / (g_rowsum[n] + 1e-6f));
    float v = (alpha * Ap[idx] + (1.0f - alpha) * ad) * g_gmean[m];
    bf16 h = __float2bfloat16(v);
    g_Amh[idx] = h;
    g_Aml[idx] = __float2bfloat16(v - __bfloat162float(h));
    g_Amf[idx] = v;
}

__global__ void k_split(const float* __restrict__ x, bf16* __restrict__ hi, bf16* __restrict__ lo, int n4) {
    for (int i = blockIdx.x * blockDim.x + threadIdx.x; i < n4; i += gridDim.x * blockDim.x) {
        float4 v = ((const float4*)x)[i];
        bf16 h0 = __float2bfloat16(v.x), h1 = __float2bfloat16(v.y);
        bf16 h2 = __float2bfloat16(v.z), h3 = __float2bfloat16(v.w);
        bf16 l0 = __float2bfloat16(v.x - __bfloat162float(h0));
        bf16 l1 = __float2bfloat16(v.y - __bfloat162float(h1));
        bf16 l2 = __float2bfloat16(v.z - __bfloat162float(h2));
        bf16 l3 = __float2bfloat16(v.w - __bfloat162float(h3));
        uint2 hv, lv;
        hv.x = ((uint32_t)bfbits(h1) << 16) | bfbits(h0);
        hv.y = ((uint32_t)bfbits(h3) << 16) | bfbits(h2);
        lv.x = ((uint32_t)bfbits(l1) << 16) | bfbits(l0);
        lv.y = ((uint32_t)bfbits(l3) << 16) | bfbits(l2);
        ((uint2*)hi)[i] = hv;
        ((uint2*)lo)[i] = lv;
    }
}

__global__ void k_tsplit(const float* __restrict__ W, bf16* __restrict__ Oh, bf16* __restrict__ Ol,
                         int Rin, int Cin) {
    __shared__ float t[32][33];
    int c0 = blockIdx.x * 32, r0 = blockIdx.y * 32;
    #pragma unroll
    for (int i = 0; i < 4; i++)
        t[threadIdx.y + i * 8][threadIdx.x] = W[(size_t)(r0 + threadIdx.y + i * 8) * Cin + c0 + threadIdx.x];
    __syncthreads();
    #pragma unroll
    for (int i = 0; i < 4; i++) {
        int oc = threadIdx.y + i * 8;
        float v = t[threadIdx.x][oc];
        size_t o = (size_t)(c0 + oc) * Rin + r0 + threadIdx.x;
        bf16 h = __float2bfloat16(v);
        Oh[o] = h;
        Ol[o] = __float2bfloat16(v - __bfloat162float(h));
    }
}

// u[m] = sum_n A_mix[m][n] * b1[n]
__global__ __launch_bounds__(256) void k_bias_u(const float* __restrict__ b1) {
    int m = blockIdx.x;
    __shared__ float red[256];
    float s = 0.f;
    for (int n = threadIdx.x; n < N_; n += 256) s += g_Amf[m * N_ + n] * b1[n];
    red[threadIdx.x] = s; __syncthreads();
    for (int off = 128; off > 0; off >>= 1) {
        if (threadIdx.x < off) red[threadIdx.x] += red[threadIdx.x + off];
        __syncthreads();
    }
    if (threadIdx.x == 0) g_u[m] = red[0];
}

// cvec[h] = sum_m u[m] * W2t[h][m] + b2[h]   (W2t = hi+lo bf16 reconstruct)
__global__ __launch_bounds__(256) void k_bias_c(const float* __restrict__ b2) {
    int h = blockIdx.x;
    __shared__ float red[256];
    float s = 0.f;
    for (int m = threadIdx.x; m < N_; m += 256)
        s += g_u[m] * (__bfloat162float(g_W2th[(size_t)h * N_ + m]) +
                       __bfloat162float(g_W2tl[(size_t)h * N_ + m]));
    red[threadIdx.x] = s; __syncthreads();
    for (int off = 128; off > 0; off >>= 1) {
        if (threadIdx.x < off) red[threadIdx.x] += red[threadIdx.x + off];
        __syncthreads();
    }
    if (threadIdx.x == 0) g_cvec[h] = red[0] + b2[h];
}

__global__ __launch_bounds__(256) void k_final(const float* __restrict__ h,
                                               const float* __restrict__ lw,
                                               const float* __restrict__ lb,
                                               float* __restrict__ out) {
    int row = blockIdx.x;
    size_t base = (size_t)row * H_ + threadIdx.x * 4;
    const float gw = 1.0f + tanhf(1.0f / 1024.0f);
    float4 a = *(const float4*)(h + base);
    float4 m = *(const float4*)(g_msg + base);
    float v0 = a.x * gw + m.x, v1 = a.y * gw + m.y;
    float v2 = a.z * gw + m.z, v3 = a.w * gw + m.w;

    __shared__ float red[256];
    red[threadIdx.x] = v0 + v1 + v2 + v3;
    __syncthreads();
    for (int off = 128; off > 0; off >>= 1) {
        if (threadIdx.x < off) red[threadIdx.x] += red[threadIdx.x + off];
        __syncthreads();
    }
    float mu = red[0] * (1.0f / H_);
    __syncthreads();
    float d0 = v0 - mu, d1 = v1 - mu, d2 = v2 - mu, d3 = v3 - mu;
    red[threadIdx.x] = d0 * d0 + d1 * d1 + d2 * d2 + d3 * d3;
    __syncthreads();
    for (int off = 128; off > 0; off >>= 1) {
        if (threadIdx.x < off) red[threadIdx.x] += red[threadIdx.x + off];
        __syncthreads();
    }
    float rstd = rsqrtf(red[0] * (1.0f / H_) + 1e-5f);
    float4 w = *(const float4*)(lw + threadIdx.x * 4);
    float4 bb = *(const float4*)(lb + threadIdx.x * 4);
    float4 o;
    o.x = d0 * rstd * w.x + bb.x;
    o.y = d1 * rstd * w.y + bb.y;
    o.z = d2 * rstd * w.z + bb.z;
    o.w = d3 * rstd * w.w + bb.w;
    *(float4*)(out + base) = o;
}

// ---------------- launcher ----------------
extern "C" void kernel_launch(void* const* d_in, const int* in_sizes, int n_in,
                              void* d_out, int out_size) {
    const float* h_time    = (const float*)d_in[0];
    const float* A_pearson = (const float*)d_in[1];
    const float* E_dyn     = (const float*)d_in[2];
    const float* alpha_raw = (const float*)d_in[3];
    // d_in[4] = tau_raw : analytically eliminated (mean over softmax axis == 1/N)
    const float* gate_W1   = (const float*)d_in[5];
    const float* gate_b1   = (const float*)d_in[6];
    const float* gate_W2   = (const float*)d_in[7];
    const float* gate_b2   = (const float*)d_in[8];
    const float* h2n_W     = (const float*)d_in[9];
    const float* h2n_b     = (const float*)d_in[10];
    const float* n2h_W     = (const float*)d_in[11];
    const float* n2h_b     = (const float*)d_in[12];
    const float* ln_w      = (const float*)d_in[13];
    const float* ln_b      = (const float*)d_in[14];
    float* out = (float*)d_out;

    bf16 *p_Ehi, *p_Elo, *p_Amh, *p_Aml, *p_W1h, *p_W1l, *p_W2th, *p_W2tl;
    bf16 *p_Ph, *p_Pl, *p_hgHi, *p_hgLo, *p_G1h, *p_G1l, *p_G2h, *p_G2l, *p_hidh, *p_hidl;
    __half *p_hA16, *p_M16h, *p_M16l;
    float *p_S, *p_msg, *p_cvec, *p_gamma;
    cudaGetSymbolAddress((void**)&p_Ehi, g_Ehi);   cudaGetSymbolAddress((void**)&p_Elo, g_Elo);
    cudaGetSymbolAddress((void**)&p_Amh, g_Amh);   cudaGetSymbolAddress((void**)&p_Aml, g_Aml);
    cudaGetSymbolAddress((void**)&p_W1h, g_W1h);   cudaGetSymbolAddress((void**)&p_W1l, g_W1l);
    cudaGetSymbolAddress((void**)&p_W2th, g_W2th); cudaGetSymbolAddress((void**)&p_W2tl, g_W2tl);
    cudaGetSymbolAddress((void**)&p_Ph, g_Ph);     cudaGetSymbolAddress((void**)&p_Pl, g_Pl);
    cudaGetSymbolAddress((void**)&p_hgHi, g_hgHi); cudaGetSymbolAddress((void**)&p_hgLo, g_hgLo);
    cudaGetSymbolAddress((void**)&p_G1h, g_G1h);   cudaGetSymbolAddress((void**)&p_G1l, g_G1l);
    cudaGetSymbolAddress((void**)&p_G2h, g_G2h);   cudaGetSymbolAddress((void**)&p_G2l, g_G2l);
    cudaGetSymbolAddress((void**)&p_hidh, g_hidh); cudaGetSymbolAddress((void**)&p_hidl, g_hidl);
    cudaGetSymbolAddress((void**)&p_hA16, g_hA16);
    cudaGetSymbolAddress((void**)&p_M16h, g_M16h); cudaGetSymbolAddress((void**)&p_M16l, g_M16l);
    cudaGetSymbolAddress((void**)&p_S, g_S);       cudaGetSymbolAddress((void**)&p_msg, g_msg);
    cudaGetSymbolAddress((void**)&p_cvec, g_cvec); cudaGetSymbolAddress((void**)&p_gamma, g_gamma);

    cudaFuncSetAttribute(hgemm<1, 0>, cudaFuncAttributeMaxDynamicSharedMemorySize, GEMM_SMEM);
    cudaFuncSetAttribute(hgemm<2, 0>, cudaFuncAttributeMaxDynamicSharedMemorySize, GEMM_SMEM);
    cudaFuncSetAttribute(hgemm<3, 1>, cudaFuncAttributeMaxDynamicSharedMemorySize, GEMM_SMEM);
    cudaFuncSetAttribute(hgemm<4, 1>, cudaFuncAttributeMaxDynamicSharedMemorySize, GEMM_SMEM);
    cudaFuncSetAttribute(hgemm<5, 0>, cudaFuncAttributeMaxDynamicSharedMemorySize, GEMM_SMEM);
    cudaFuncSetAttribute(fgemm, cudaFuncAttributeMaxDynamicSharedMemorySize, FGEMM_SMEM);

    // fused reductions + fp16 convert; weight prep
    k_pre<<<dim3(4, 64), 256>>>(h_time);
    k_padzero<<<(64 * H_ + 255) / 256, 256>>>();
    k_meanB<<<(H_ + 255) / 256, 256>>>();
    k_enorm<<<N_, 256>>>(E_dyn);
    k_split<<<512, 256>>>(h2n_W, p_W1h, p_W1l, H_*N_ / 4);
    {
        dim3 b(32, 8);
        k_tsplit<<<dim3(H_ / 32, N_ / 32), b>>>(n2h_W, p_W2th, p_W2tl, N_, H_);     // [N,H]->[H,N]
        k_tsplit<<<dim3(HID_ / 32, H_ / 32), b>>>(gate_W1, p_G1h, p_G1l, H_, HID_); // [H,HID]->[HID,H]
        k_tsplit<<<dim3(N_ / 32, HID_ / 32), b>>>(gate_W2, p_G2h, p_G2l, HID_, N_); // [HID,N]->[N,HID]
    }

    // S = relu(E_cur @ E_cur^T)
    hgemm<1, 0><<<dim3(N_ / 128, N_ / 128), 256, GEMM_SMEM>>>(
        p_Ehi, p_Elo, p_Ehi, p_Elo, nullptr, p_S, nullptr, nullptr, N_, N_, H_);
    k_rowsum<<<N_, 256>>>();

    // gate MLP on tensor cores (M padded 64->128; rows >=64 are junk, never consumed)
    hgemm<3, 1><<<dim3(HID_ / 128, 1), 256, GEMM_SMEM>>>(
        p_hgHi, p_hgLo, p_G1h, p_G1l, gate_b1, nullptr, p_hidh, p_hidl, 128, HID_, H_);
    hgemm<4, 1><<<dim3(N_ / 128, 1), 256, GEMM_SMEM>>>(
        p_hidh, p_hidl, p_G2h, p_G2l, gate_b2, p_gamma, nullptr, nullptr, 128, N_, HID_);
    k_gmean<<<(N_ + 255) / 256, 256>>>();
    k_amix<<<(N_*N_ + 255) / 256, 256>>>(A_pearson, alpha_raw);

    // Mcomb^T = (W1 @ AmixT @ W2)^T via two 1024^3 GEMMs (3-pass bf16, accurate)
    hgemm<2, 0><<<dim3(N_ / 128, H_ / 128), 256, GEMM_SMEM>>>(
        p_W1h, p_W1l, p_Amh, p_Aml, nullptr, nullptr, p_Ph, p_Pl, H_, N_, N_);
    hgemm<5, 0><<<dim3(H_ / 128, H_ / 128), 256, GEMM_SMEM>>>(
        p_W2th, p_W2tl, p_Ph, p_Pl, nullptr, nullptr, (bf16*)p_M16h, (bf16*)p_M16l, H_, H_, N_);

    // bias fold: cvec = b1 @ AmixT @ W2 + b2
    k_bias_u<<<N_, 256>>>(h2n_b);
    k_bias_c<<<H_, 256>>>(n2h_b);

    // THE big GEMM: msg = h_time @ Mcomb + cvec  (fp16 A-single, B-split, 2 passes)
    fgemm<<<dim3(H_ / 128, BT_ / 128), 256, FGEMM_SMEM>>>(
        p_hA16, p_M16h, p_M16l, p_cvec, p_msg, BT_, H_, H_);

    // fused residual + LayerNorm
    k_final<<<BT_, 256>>>(h_time, ln_w, ln_b, out);
}

// round 5
// speedup vs baseline: 4.3697x; 1.1982x over previous
#include <cuda_runtime.h>
#include <cuda_bf16.h>
#include <cuda_fp16.h>
#include <math.h>
#include <stdint.h>

#define N_ 1024
#define H_ 1024
#define B_ 64
#define T_ 256
#define BT_ (B_*T_)
#define HID_ 512

typedef __nv_bfloat16 bf16;

// ---------------- scratch (static device globals; no allocation) ----------------
__device__ __half g_hA16[BT_*H_];                  // h_time fp16
__device__ float g_hgate[B_*H_];
__device__ bf16  g_hgHi[128*H_], g_hgLo[128*H_];   // h_gate split, padded to 128 rows
__device__ float g_hmean[H_];
__device__ bf16  g_Ehi[N_*H_], g_Elo[N_*H_];
__device__ float g_S[N_*N_];
__device__ float g_rowsum[N_];
__device__ bf16  g_G1h[HID_*H_], g_G1l[HID_*H_];   // gate_W1^T [512,1024] split
__device__ bf16  g_G2h[N_*HID_], g_G2l[N_*HID_];   // gate_W2^T [1024,512] split
__device__ bf16  g_hidh[128*HID_], g_hidl[128*HID_];
__device__ float g_gamma[128*N_];
__device__ float g_gmean[N_];
__device__ bf16  g_Amh[N_*N_], g_Aml[N_*N_];       // A_mix [m][n] split
__device__ float g_Amf[N_*N_];                      // A_mix fp32 (bias fold)
__device__ bf16  g_W1h[H_*N_], g_W1l[H_*N_];       // h2n_W [H,N] split
__device__ bf16  g_W2th[H_*N_], g_W2tl[H_*N_];     // n2h_W^T [H,N] split
__device__ bf16  g_Ph[H_*N_], g_Pl[H_*N_];         // P = W1 @ AmixT
__device__ __half g_M16h[H_*H_];                   // McombT fp16 (single)
__device__ float g_u[N_];
__device__ float g_cvec[H_];
__device__ float g_msg[BT_*H_];

// ---------------- helpers ----------------
__device__ __forceinline__ unsigned short bfbits(bf16 x) {
    return *reinterpret_cast<unsigned short*>(&x);
}
__device__ __forceinline__ unsigned short hfbits(__half x) {
    return *reinterpret_cast<unsigned short*>(&x);
}
__device__ __forceinline__ uint32_t smem_u32(const void* p) {
    uint32_t a;
    asm("{ .reg .u64 t; cvta.to.shared.u64 t, %1; cvt.u32.u64 %0, t; }" : "=r"(a) : "l"(p));
    return a;
}
__device__ __forceinline__ uint32_t swz(uint32_t off) {
    return off ^ ((off >> 3) & 0x70);
}
#define CP_COMMIT() asm volatile("cp.async.commit_group;" ::: "memory")

__device__ __forceinline__ void ldsm4(uint32_t (&r)[4], uint32_t addr) {
    asm volatile("ldmatrix.sync.aligned.m8n8.x4.shared.b16 {%0,%1,%2,%3}, [%4];"
        : "=r"(r[0]), "=r"(r[1]), "=r"(r[2]), "=r"(r[3]) : "r"(addr));
}
__device__ __forceinline__ void mma_bf(float* c, const uint32_t* a, uint32_t b0, uint32_t b1) {
    asm volatile("mma.sync.aligned.m16n8k16.row.col.f32.bf16.bf16.f32 "
        "{%0,%1,%2,%3}, {%4,%5,%6,%7}, {%8,%9}, {%0,%1,%2,%3};"
        : "+f"(c[0]), "+f"(c[1]), "+f"(c[2]), "+f"(c[3])
        : "r"(a[0]), "r"(a[1]), "r"(a[2]), "r"(a[3]), "r"(b0), "r"(b1));
}
__device__ __forceinline__ void mma_fp(float* c, const uint32_t* a, uint32_t b0, uint32_t b1) {
    asm volatile("mma.sync.aligned.m16n8k16.row.col.f32.f16.f16.f32 "
        "{%0,%1,%2,%3}, {%4,%5,%6,%7}, {%8,%9}, {%0,%1,%2,%3};"
        : "+f"(c[0]), "+f"(c[1]), "+f"(c[2]), "+f"(c[3])
        : "r"(a[0]), "r"(a[1]), "r"(a[2]), "r"(a[3]), "r"(b0), "r"(b1));
}

// load one 128row x 64col 16-bit tile (SW128 swizzled, 128B/row); 256 threads
__device__ __forceinline__ void ld_tile(uint32_t sdst, const void* __restrict__ g,
                                        int row0, int K, int kc, int tid) {
    const int row = tid >> 1, half = tid & 1;
    const char* src = (const char*)g + (((size_t)(row0 + row) * K + (kc << 6)) << 1) + half * 64;
    uint32_t rb = (uint32_t)row * 128 + (uint32_t)half * 64;
    #pragma unroll
    for (int j = 0; j < 4; j++) {
        uint32_t sw = swz(rb + (j << 4));
        asm volatile("cp.async.cg.shared.global [%0], [%1], 16;"
            :: "r"(sdst + sw), "l"(src + (j << 4)));
    }
}

// ---------------- split-bf16 HMMA GEMM (TN), 3 passes
// OUT_MODE: 0 f32(+bias), 1 f32 relu, 2 split bf16, 3 gelu->split bf16, 4 sigmoid->f32, 6 fp16 single
#define TILE_B 16384
#define BUF_B  65536
#define GEMM_SMEM (1024 + 2 * BUF_B)

template<int OUT_MODE, int BIAS>
__global__ __launch_bounds__(256, 1) void hgemm(
    const bf16* __restrict__ Ahi, const bf16* __restrict__ Alo,
    const bf16* __restrict__ Bhi, const bf16* __restrict__ Blo,
    const float* __restrict__ bias,
    float* __restrict__ Cf, bf16* __restrict__ Chi, bf16* __restrict__ Clo,
    int M, int Nn, int K)
{
    extern __shared__ __align__(1024) char smem[];
    uint32_t sb = smem_u32(smem);
    const int tid = threadIdx.x;
    const int wid = tid >> 5, lane = tid & 31;
    const int wm = wid >> 1, wn = wid & 1;
    const int bx = blockIdx.x, by = blockIdx.y;

    float* sBias = (float*)(smem + 512);
    if (BIAS && tid < 128) sBias[tid] = bias[bx * 128 + tid];

    const uint32_t T0 = sb + 1024;
    const int NK = K >> 6;
    const int arow0 = by * 128, brow0 = bx * 128;

    float acc[2][8][4];
    #pragma unroll
    for (int i = 0; i < 2; i++)
        #pragma unroll
        for (int j = 0; j < 8; j++)
            #pragma unroll
            for (int l = 0; l < 4; l++) acc[i][j][l] = 0.f;

    const int mi = lane >> 3, li = lane & 7;
    const int rowoff = (mi & 1) * 8 + li;
    const int coloff = (mi >> 1) * 16;

    ld_tile(T0,              Ahi, arow0, K, 0, tid);
    ld_tile(T0 + TILE_B,     Alo, arow0, K, 0, tid);
    ld_tile(T0 + 2 * TILE_B, Bhi, brow0, K, 0, tid);
    ld_tile(T0 + 3 * TILE_B, Blo, brow0, K, 0, tid);
    CP_COMMIT();

    for (int kc = 0; kc < NK; kc++) {
        const int cur = kc & 1;
        if (kc + 1 < NK) {
            uint32_t nb = T0 + (cur ^ 1) * BUF_B;
            ld_tile(nb,              Ahi, arow0, K, kc + 1, tid);
            ld_tile(nb + TILE_B,     Alo, arow0, K, kc + 1, tid);
            ld_tile(nb + 2 * TILE_B, Bhi, brow0, K, kc + 1, tid);
            ld_tile(nb + 3 * TILE_B, Blo, brow0, K, kc + 1, tid);
            CP_COMMIT();
            asm volatile("cp.async.wait_group 1;" ::: "memory");
        } else {
            asm volatile("cp.async.wait_group 0;" ::: "memory");
        }
        __syncthreads();

        const uint32_t Ah = T0 + cur * BUF_B;
        const uint32_t Al = Ah + TILE_B;
        const uint32_t Bh = Ah + 2 * TILE_B;
        const uint32_t Bl = Ah + 3 * TILE_B;

        #pragma unroll
        for (int ks = 0; ks < 4; ks++) {
            const int kb = ks * 32;
            uint32_t ahi[2][4], alo[2][4];
            #pragma unroll
            for (int mt = 0; mt < 2; mt++) {
                uint32_t ra = swz((uint32_t)(wm * 32 + mt * 16 + rowoff) * 128 + kb + coloff);
                ldsm4(ahi[mt], Ah + ra);
                ldsm4(alo[mt], Al + ra);
            }
            #pragma unroll
            for (int g = 0; g < 4; g++) {
                uint32_t rb = swz((uint32_t)(wn * 64 + g * 16 + rowoff) * 128 + kb + coloff);
                uint32_t bh[4], bl[4];
                ldsm4(bh, Bh + rb);
                ldsm4(bl, Bl + rb);
                #pragma unroll
                for (int mt = 0; mt < 2; mt++) {
                    #pragma unroll
                    for (int sub = 0; sub < 2; sub++) {
                        float* c = acc[mt][g * 2 + sub];
                        mma_bf(c, ahi[mt], bh[sub], bh[2 + sub]);
                        mma_bf(c, ahi[mt], bl[sub], bl[2 + sub]);
                        mma_bf(c, alo[mt], bh[sub], bh[2 + sub]);
                    }
                }
            }
        }
        __syncthreads();
    }

    #pragma unroll
    for (int mt = 0; mt < 2; mt++) {
        #pragma unroll
        for (int nt = 0; nt < 8; nt++) {
            const int r0 = by * 128 + wm * 32 + mt * 16 + (lane >> 2);
            const int cb = wn * 64 + nt * 8 + (lane & 3) * 2;
            const int cg = bx * 128 + cb;
            float v0 = acc[mt][nt][0], v1 = acc[mt][nt][1];
            float v2 = acc[mt][nt][2], v3 = acc[mt][nt][3];
            if (BIAS) {
                float bb0 = sBias[cb], bb1 = sBias[cb + 1];
                v0 += bb0; v1 += bb1; v2 += bb0; v3 += bb1;
            }
            if (OUT_MODE == 1) {
                v0 = fmaxf(v0, 0.f); v1 = fmaxf(v1, 0.f);
                v2 = fmaxf(v2, 0.f); v3 = fmaxf(v3, 0.f);
            }
            if (OUT_MODE == 3) {
                const float is2 = 0.70710678118654752f;
                v0 = 0.5f * v0 * (1.0f + erff(v0 * is2));
                v1 = 0.5f * v1 * (1.0f + erff(v1 * is2));
                v2 = 0.5f * v2 * (1.0f + erff(v2 * is2));
                v3 = 0.5f * v3 * (1.0f + erff(v3 * is2));
            }
            if (OUT_MODE == 4) {
                v0 = 1.0f / (1.0f + expf(-v0)); v1 = 1.0f / (1.0f + expf(-v1));
                v2 = 1.0f / (1.0f + expf(-v2)); v3 = 1.0f / (1.0f + expf(-v3));
            }
            if (OUT_MODE == 2 || OUT_MODE == 3) {
                bf16 h0 = __float2bfloat16(v0), h1 = __float2bfloat16(v1);
                bf16 h2 = __float2bfloat16(v2), h3 = __float2bfloat16(v3);
                bf16 l0 = __float2bfloat16(v0 - __bfloat162float(h0));
                bf16 l1 = __float2bfloat16(v1 - __bfloat162float(h1));
                bf16 l2 = __float2bfloat16(v2 - __bfloat162float(h2));
                bf16 l3 = __float2bfloat16(v3 - __bfloat162float(h3));
                *(uint32_t*)(Chi + (size_t)r0 * Nn + cg)       = ((uint32_t)bfbits(h1) << 16) | bfbits(h0);
                *(uint32_t*)(Chi + (size_t)(r0 + 8) * Nn + cg) = ((uint32_t)bfbits(h3) << 16) | bfbits(h2);
                *(uint32_t*)(Clo + (size_t)r0 * Nn + cg)       = ((uint32_t)bfbits(l1) << 16) | bfbits(l0);
                *(uint32_t*)(Clo + (size_t)(r0 + 8) * Nn + cg) = ((uint32_t)bfbits(l3) << 16) | bfbits(l2);
            } else if (OUT_MODE == 6) {
                __half* Hh = (__half*)Chi;
                __half h0 = __float2half(v0), h1 = __float2half(v1);
                __half h2 = __float2half(v2), h3 = __float2half(v3);
                *(uint32_t*)(Hh + (size_t)r0 * Nn + cg)       = ((uint32_t)hfbits(h1) << 16) | hfbits(h0);
                *(uint32_t*)(Hh + (size_t)(r0 + 8) * Nn + cg) = ((uint32_t)hfbits(h3) << 16) | hfbits(h2);
            } else {
                *(float2*)(Cf + (size_t)r0 * Nn + cg)       = make_float2(v0, v1);
                *(float2*)(Cf + (size_t)(r0 + 8) * Nn + cg) = make_float2(v2, v3);
            }
        }
    }
}

// ---------------- fp16 single-pass GEMM: C = A @ Bh^T + bias, 4-stage pipeline ----------------
#define FTILE_B 16384
#define FSTAGE_B (2 * FTILE_B)
#define FGEMM_SMEM (1024 + 4 * FSTAGE_B)

__global__ __launch_bounds__(256, 1) void fgemm(
    const __half* __restrict__ A,
    const __half* __restrict__ Bh,
    const float* __restrict__ bias,
    float* __restrict__ Cf, int M, int Nn, int K)
{
    extern __shared__ __align__(1024) char smem[];
    uint32_t sb = smem_u32(smem);
    const int tid = threadIdx.x;
    const int wid = tid >> 5, lane = tid & 31;
    const int wm = wid >> 1, wn = wid & 1;
    const int bx = blockIdx.x, by = blockIdx.y;

    float* sBias = (float*)(smem + 512);
    if (tid < 128) sBias[tid] = bias[bx * 128 + tid];

    const uint32_t T0 = sb + 1024;
    const int NK = K >> 6;
    const int arow0 = by * 128, brow0 = bx * 128;

    float acc[2][8][4];
    #pragma unroll
    for (int i = 0; i < 2; i++)
        #pragma unroll
        for (int j = 0; j < 8; j++)
            #pragma unroll
            for (int l = 0; l < 4; l++) acc[i][j][l] = 0.f;

    const int mi = lane >> 3, li = lane & 7;
    const int rowoff = (mi & 1) * 8 + li;
    const int coloff = (mi >> 1) * 16;

    // prologue: stages 0..2
    #pragma unroll
    for (int s = 0; s < 3; s++) {
        uint32_t st = T0 + s * FSTAGE_B;
        ld_tile(st,           A,  arow0, K, s, tid);
        ld_tile(st + FTILE_B, Bh, brow0, K, s, tid);
        CP_COMMIT();
    }

    for (int kc = 0; kc < NK; kc++) {
        const int rem = NK - kc;
        if (rem >= 3)      asm volatile("cp.async.wait_group 2;" ::: "memory");
        else if (rem == 2) asm volatile("cp.async.wait_group 1;" ::: "memory");
        else               asm volatile("cp.async.wait_group 0;" ::: "memory");
        __syncthreads();

        if (kc + 3 < NK) {
            uint32_t st = T0 + ((kc + 3) & 3) * FSTAGE_B;
            ld_tile(st,           A,  arow0, K, kc + 3, tid);
            ld_tile(st + FTILE_B, Bh, brow0, K, kc + 3, tid);
            CP_COMMIT();
        }

        const uint32_t Sa = T0 + (kc & 3) * FSTAGE_B;
        const uint32_t Sh = Sa + FTILE_B;

        #pragma unroll
        for (int ks = 0; ks < 4; ks++) {
            const int kb = ks * 32;
            uint32_t a[2][4];
            #pragma unroll
            for (int mt = 0; mt < 2; mt++) {
                uint32_t ra = swz((uint32_t)(wm * 32 + mt * 16 + rowoff) * 128 + kb + coloff);
                ldsm4(a[mt], Sa + ra);
            }
            #pragma unroll
            for (int g = 0; g < 4; g++) {
                uint32_t rb = swz((uint32_t)(wn * 64 + g * 16 + rowoff) * 128 + kb + coloff);
                uint32_t bh[4];
                ldsm4(bh, Sh + rb);
                #pragma unroll
                for (int mt = 0; mt < 2; mt++) {
                    #pragma unroll
                    for (int sub = 0; sub < 2; sub++) {
                        mma_fp(acc[mt][g * 2 + sub], a[mt], bh[sub], bh[2 + sub]);
                    }
                }
            }
        }
    }

    #pragma unroll
    for (int mt = 0; mt < 2; mt++) {
        #pragma unroll
        for (int nt = 0; nt < 8; nt++) {
            const int r0 = by * 128 + wm * 32 + mt * 16 + (lane >> 2);
            const int cb = wn * 64 + nt * 8 + (lane & 3) * 2;
            const int cg = bx * 128 + cb;
            float bb0 = sBias[cb], bb1 = sBias[cb + 1];
            *(float2*)(Cf + (size_t)r0 * Nn + cg) =
                make_float2(acc[mt][nt][0] + bb0, acc[mt][nt][1] + bb1);
            *(float2*)(Cf + (size_t)(r0 + 8) * Nn + cg) =
                make_float2(acc[mt][nt][2] + bb0, acc[mt][nt][3] + bb1);
        }
    }
}

// ---------------- small kernels ----------------
__global__ __launch_bounds__(256) void k_pre(const float* __restrict__ h) {
    int b = blockIdx.y;
    int hh = blockIdx.x * 256 + threadIdx.x;
    const float* p = h + (size_t)b * T_ * H_ + hh;
    __half* q = g_hA16 + (size_t)b * T_ * H_ + hh;
    float s = 0.f;
    #pragma unroll 4
    for (int t = 0; t < T_; t++) {
        float v = p[(size_t)t * H_];
        q[(size_t)t * H_] = __float2half(v);
        s += v;
    }
    float mean = s * (1.0f / T_);
    g_hgate[b * H_ + hh] = mean;
    bf16 hi = __float2bfloat16(mean);
    g_hgHi[b * H_ + hh] = hi;
    g_hgLo[b * H_ + hh] = __float2bfloat16(mean - __bfloat162float(hi));
}

__global__ void k_padzero() {
    int i = blockIdx.x * blockDim.x + threadIdx.x;
    if (i >= 64 * H_) return;
    g_hgHi[64 * H_ + i] = __float2bfloat16(0.f);
    g_hgLo[64 * H_ + i] = __float2bfloat16(0.f);
}

__global__ void k_meanB() {
    int hh = blockIdx.x * blockDim.x + threadIdx.x;
    if (hh >= H_) return;
    float s = 0.f;
    #pragma unroll
    for (int b = 0; b < B_; b++) s += g_hgate[b * H_ + hh];
    g_hmean[hh] = s * (1.0f / B_);
}

__global__ __launch_bounds__(256) void k_enorm(const float* __restrict__ E_dyn) {
    int i = blockIdx.x;
    __shared__ float red[256];
    float vals[4];
    float ss = 0.f;
    #pragma unroll
    for (int j = 0; j < 4; j++) {
        int hh = threadIdx.x + j * 256;
        float v = E_dyn[i * H_ + hh] + g_hmean[hh];
        vals[j] = v; ss += v * v;
    }
    red[threadIdx.x] = ss; __syncthreads();
    for (int off = 128; off > 0; off >>= 1) {
        if (threadIdx.x < off) red[threadIdx.x] += red[threadIdx.x + off];
        __syncthreads();
    }
    float inv = 1.0f / fmaxf(sqrtf(red[0]), 1e-12f);
    #pragma unroll
    for (int j = 0; j < 4; j++) {
        int hh = threadIdx.x + j * 256;
        float v = vals[j] * inv;
        bf16 h = __float2bfloat16(v);
        g_Ehi[i * H_ + hh] = h;
        g_Elo[i * H_ + hh] = __float2bfloat16(v - __bfloat162float(h));
    }
}

__global__ __launch_bounds__(256) void k_rowsum() {
    int i = blockIdx.x;
    __shared__ float red[256];
    float s = 0.f;
    for (int j = threadIdx.x; j < N_; j += 256) s += g_S[i * N_ + j];
    red[threadIdx.x] = s; __syncthreads();
    for (int off = 128; off > 0; off >>= 1) {
        if (threadIdx.x < off) red[threadIdx.x] += red[threadIdx.x + off];
        __syncthreads();
    }
    if (threadIdx.x == 0) g_rowsum[i] = red[0];
}

__global__ void k_gmean() {
    int n = blockIdx.x * blockDim.x + threadIdx.x;
    if (n >= N_) return;
    float s = 0.f;
    #pragma unroll
    for (int b = 0; b < B_; b++) s += g_gamma[b * N_ + n];
    g_gmean[n] = s * (1.0f / B_);
}

__global__ void k_amix(const float* __restrict__ Ap, const float* __restrict__ alpha_raw) {
    int idx = blockIdx.x * blockDim.x + threadIdx.x;
    if (idx >= N_*N_) return;
    int m = idx >> 10, n = idx & 1023;
    float alpha = 1.0f / (1.0f + expf(-alpha_raw[0]));
    float ad = 0.5f * (g_S[idx] / (g_rowsum[m] + 1e-6f) + g_S[n * N_ + m] / (g_rowsum[n] + 1e-6f));
    float v = (alpha * Ap[idx] + (1.0f - alpha) * ad) * g_gmean[m];
    bf16 h = __float2bfloat16(v);
    g_Amh[idx] = h;
    g_Aml[idx] = __float2bfloat16(v - __bfloat162float(h));
    g_Amf[idx] = v;
}

__global__ void k_split(const float* __restrict__ x, bf16* __restrict__ hi, bf16* __restrict__ lo, int n4) {
    for (int i = blockIdx.x * blockDim.x + threadIdx.x; i < n4; i += gridDim.x * blockDim.x) {
        float4 v = ((const float4*)x)[i];
        bf16 h0 = __float2bfloat16(v.x), h1 = __float2bfloat16(v.y);
        bf16 h2 = __float2bfloat16(v.z), h3 = __float2bfloat16(v.w);
        bf16 l0 = __float2bfloat16(v.x - __bfloat162float(h0));
        bf16 l1 = __float2bfloat16(v.y - __bfloat162float(h1));
        bf16 l2 = __float2bfloat16(v.z - __bfloat162float(h2));
        bf16 l3 = __float2bfloat16(v.w - __bfloat162float(h3));
        uint2 hv, lv;
        hv.x = ((uint32_t)bfbits(h1) << 16) | bfbits(h0);
        hv.y = ((uint32_t)bfbits(h3) << 16) | bfbits(h2);
        lv.x = ((uint32_t)bfbits(l1) << 16) | bfbits(l0);
        lv.y = ((uint32_t)bfbits(l3) << 16) | bfbits(l2);
        ((uint2*)hi)[i] = hv;
        ((uint2*)lo)[i] = lv;
    }
}

__global__ void k_tsplit(const float* __restrict__ W, bf16* __restrict__ Oh, bf16* __restrict__ Ol,
                         int Rin, int Cin) {
    __shared__ float t[32][33];
    int c0 = blockIdx.x * 32, r0 = blockIdx.y * 32;
    #pragma unroll
    for (int i = 0; i < 4; i++)
        t[threadIdx.y + i * 8][threadIdx.x] = W[(size_t)(r0 + threadIdx.y + i * 8) * Cin + c0 + threadIdx.x];
    __syncthreads();
    #pragma unroll
    for (int i = 0; i < 4; i++) {
        int oc = threadIdx.y + i * 8;
        float v = t[threadIdx.x][oc];
        size_t o = (size_t)(c0 + oc) * Rin + r0 + threadIdx.x;
        bf16 h = __float2bfloat16(v);
        Oh[o] = h;
        Ol[o] = __float2bfloat16(v - __bfloat162float(h));
    }
}

// u[m] = sum_n A_mix[m][n] * b1[n]
__global__ __launch_bounds__(256) void k_bias_u(const float* __restrict__ b1) {
    int m = blockIdx.x;
    __shared__ float red[256];
    float s = 0.f;
    for (int n = threadIdx.x; n < N_; n += 256) s += g_Amf[m * N_ + n] * b1[n];
    red[threadIdx.x] = s; __syncthreads();
    for (int off = 128; off > 0; off >>= 1) {
        if (threadIdx.x < off) red[threadIdx.x] += red[threadIdx.x + off];
        __syncthreads();
    }
    if (threadIdx.x == 0) g_u[m] = red[0];
}

// cvec[h] = sum_m u[m] * W2t[h][m] + b2[h]
__global__ __launch_bounds__(256) void k_bias_c(const float* __restrict__ b2) {
    int h = blockIdx.x;
    __shared__ float red[256];
    float s = 0.f;
    for (int m = threadIdx.x; m < N_; m += 256)
        s += g_u[m] * (__bfloat162float(g_W2th[(size_t)h * N_ + m]) +
                       __bfloat162float(g_W2tl[(size_t)h * N_ + m]));
    red[threadIdx.x] = s; __syncthreads();
    for (int off = 128; off > 0; off >>= 1) {
        if (threadIdx.x < off) red[threadIdx.x] += red[threadIdx.x + off];
        __syncthreads();
    }
    if (threadIdx.x == 0) g_cvec[h] = red[0] + b2[h];
}

__global__ __launch_bounds__(256) void k_final(const float* __restrict__ h,
                                               const float* __restrict__ lw,
                                               const float* __restrict__ lb,
                                               float* __restrict__ out) {
    int row = blockIdx.x;
    size_t base = (size_t)row * H_ + threadIdx.x * 4;
    const float gw = 1.0f + tanhf(1.0f / 1024.0f);
    float4 a = *(const float4*)(h + base);
    float4 m = *(const float4*)(g_msg + base);
    float v0 = a.x * gw + m.x, v1 = a.y * gw + m.y;
    float v2 = a.z * gw + m.z, v3 = a.w * gw + m.w;

    __shared__ float red[256];
    red[threadIdx.x] = v0 + v1 + v2 + v3;
    __syncthreads();
    for (int off = 128; off > 0; off >>= 1) {
        if (threadIdx.x < off) red[threadIdx.x] += red[threadIdx.x + off];
        __syncthreads();
    }
    float mu = red[0] * (1.0f / H_);
    __syncthreads();
    float d0 = v0 - mu, d1 = v1 - mu, d2 = v2 - mu, d3 = v3 - mu;
    red[threadIdx.x] = d0 * d0 + d1 * d1 + d2 * d2 + d3 * d3;
    __syncthreads();
    for (int off = 128; off > 0; off >>= 1) {
        if (threadIdx.x < off) red[threadIdx.x] += red[threadIdx.x + off];
        __syncthreads();
    }
    float rstd = rsqrtf(red[0] * (1.0f / H_) + 1e-5f);
    float4 w = *(const float4*)(lw + threadIdx.x * 4);
    float4 bb = *(const float4*)(lb + threadIdx.x * 4);
    float4 o;
    o.x = d0 * rstd * w.x + bb.x;
    o.y = d1 * rstd * w.y + bb.y;
    o.z = d2 * rstd * w.z + bb.z;
    o.w = d3 * rstd * w.w + bb.w;
    *(float4*)(out + base) = o;
}

// ---------------- launcher ----------------
extern "C" void kernel_launch(void* const* d_in, const int* in_sizes, int n_in,
                              void* d_out, int out_size) {
    const float* h_time    = (const float*)d_in[0];
    const float* A_pearson = (const float*)d_in[1];
    const float* E_dyn     = (const float*)d_in[2];
    const float* alpha_raw = (const float*)d_in[3];
    // d_in[4] = tau_raw : analytically eliminated (mean over softmax axis == 1/N)
    const float* gate_W1   = (const float*)d_in[5];
    const float* gate_b1   = (const float*)d_in[6];
    const float* gate_W2   = (const float*)d_in[7];
    const float* gate_b2   = (const float*)d_in[8];
    const float* h2n_W     = (const float*)d_in[9];
    const float* h2n_b     = (const float*)d_in[10];
    const float* n2h_W     = (const float*)d_in[11];
    const float* n2h_b     = (const float*)d_in[12];
    const float* ln_w      = (const float*)d_in[13];
    const float* ln_b      = (const float*)d_in[14];
    float* out = (float*)d_out;

    bf16 *p_Ehi, *p_Elo, *p_Amh, *p_Aml, *p_W1h, *p_W1l, *p_W2th, *p_W2tl;
    bf16 *p_Ph, *p_Pl, *p_hgHi, *p_hgLo, *p_G1h, *p_G1l, *p_G2h, *p_G2l, *p_hidh, *p_hidl;
    __half *p_hA16, *p_M16h;
    float *p_S, *p_msg, *p_cvec, *p_gamma;
    cudaGetSymbolAddress((void**)&p_Ehi, g_Ehi);   cudaGetSymbolAddress((void**)&p_Elo, g_Elo);
    cudaGetSymbolAddress((void**)&p_Amh, g_Amh);   cudaGetSymbolAddress((void**)&p_Aml, g_Aml);
    cudaGetSymbolAddress((void**)&p_W1h, g_W1h);   cudaGetSymbolAddress((void**)&p_W1l, g_W1l);
    cudaGetSymbolAddress((void**)&p_W2th, g_W2th); cudaGetSymbolAddress((void**)&p_W2tl, g_W2tl);
    cudaGetSymbolAddress((void**)&p_Ph, g_Ph);     cudaGetSymbolAddress((void**)&p_Pl, g_Pl);
    cudaGetSymbolAddress((void**)&p_hgHi, g_hgHi); cudaGetSymbolAddress((void**)&p_hgLo, g_hgLo);
    cudaGetSymbolAddress((void**)&p_G1h, g_G1h);   cudaGetSymbolAddress((void**)&p_G1l, g_G1l);
    cudaGetSymbolAddress((void**)&p_G2h, g_G2h);   cudaGetSymbolAddress((void**)&p_G2l, g_G2l);
    cudaGetSymbolAddress((void**)&p_hidh, g_hidh); cudaGetSymbolAddress((void**)&p_hidl, g_hidl);
    cudaGetSymbolAddress((void**)&p_hA16, g_hA16);
    cudaGetSymbolAddress((void**)&p_M16h, g_M16h);
    cudaGetSymbolAddress((void**)&p_S, g_S);       cudaGetSymbolAddress((void**)&p_msg, g_msg);
    cudaGetSymbolAddress((void**)&p_cvec, g_cvec); cudaGetSymbolAddress((void**)&p_gamma, g_gamma);

    cudaFuncSetAttribute(hgemm<1, 0>, cudaFuncAttributeMaxDynamicSharedMemorySize, GEMM_SMEM);
    cudaFuncSetAttribute(hgemm<2, 0>, cudaFuncAttributeMaxDynamicSharedMemorySize, GEMM_SMEM);
    cudaFuncSetAttribute(hgemm<3, 1>, cudaFuncAttributeMaxDynamicSharedMemorySize, GEMM_SMEM);
    cudaFuncSetAttribute(hgemm<4, 1>, cudaFuncAttributeMaxDynamicSharedMemorySize, GEMM_SMEM);
    cudaFuncSetAttribute(hgemm<6, 0>, cudaFuncAttributeMaxDynamicSharedMemorySize, GEMM_SMEM);
    cudaFuncSetAttribute(fgemm, cudaFuncAttributeMaxDynamicSharedMemorySize, FGEMM_SMEM);

    // fused reductions + fp16 convert; weight prep
    k_pre<<<dim3(4, 64), 256>>>(h_time);
    k_padzero<<<(64 * H_ + 255) / 256, 256>>>();
    k_meanB<<<(H_ + 255) / 256, 256>>>();
    k_enorm<<<N_, 256>>>(E_dyn);
    k_split<<<512, 256>>>(h2n_W, p_W1h, p_W1l, H_*N_ / 4);
    {
        dim3 b(32, 8);
        k_tsplit<<<dim3(H_ / 32, N_ / 32), b>>>(n2h_W, p_W2th, p_W2tl, N_, H_);     // [N,H]->[H,N]
        k_tsplit<<<dim3(HID_ / 32, H_ / 32), b>>>(gate_W1, p_G1h, p_G1l, H_, HID_); // [H,HID]->[HID,H]
        k_tsplit<<<dim3(N_ / 32, HID_ / 32), b>>>(gate_W2, p_G2h, p_G2l, HID_, N_); // [HID,N]->[N,HID]
    }

    // S = relu(E_cur @ E_cur^T)
    hgemm<1, 0><<<dim3(N_ / 128, N_ / 128), 256, GEMM_SMEM>>>(
        p_Ehi, p_Elo, p_Ehi, p_Elo, nullptr, p_S, nullptr, nullptr, N_, N_, H_);
    k_rowsum<<<N_, 256>>>();

    // gate MLP on tensor cores (M padded 64->128)
    hgemm<3, 1><<<dim3(HID_ / 128, 1), 256, GEMM_SMEM>>>(
        p_hgHi, p_hgLo, p_G1h, p_G1l, gate_b1, nullptr, p_hidh, p_hidl, 128, HID_, H_);
    hgemm<4, 1><<<dim3(N_ / 128, 1), 256, GEMM_SMEM>>>(
        p_hidh, p_hidl, p_G2h, p_G2l, gate_b2, p_gamma, nullptr, nullptr, 128, N_, HID_);
    k_gmean<<<(N_ + 255) / 256, 256>>>();
    k_amix<<<(N_*N_ + 255) / 256, 256>>>(A_pearson, alpha_raw);

    // Mcomb^T = (W1 @ AmixT @ W2)^T via two 1024^3 GEMMs (3-pass bf16, accurate)
    hgemm<2, 0><<<dim3(N_ / 128, H_ / 128), 256, GEMM_SMEM>>>(
        p_W1h, p_W1l, p_Amh, p_Aml, nullptr, nullptr, p_Ph, p_Pl, H_, N_, N_);
    hgemm<6, 0><<<dim3(H_ / 128, H_ / 128), 256, GEMM_SMEM>>>(
        p_W2th, p_W2tl, p_Ph, p_Pl, nullptr, nullptr, (bf16*)p_M16h, nullptr, H_, H_, N_);

    // bias fold: cvec = b1 @ AmixT @ W2 + b2
    k_bias_u<<<N_, 256>>>(h2n_b);
    k_bias_c<<<H_, 256>>>(n2h_b);

    // THE big GEMM: msg = h_time @ Mcomb + cvec  (fp16 x fp16, single pass)
    fgemm<<<dim3(H_ / 128, BT_ / 128), 256, FGEMM_SMEM>>>(
        p_hA16, p_M16h, p_cvec, p_msg, BT_, H_, H_);

    // fused residual + LayerNorm
    k_final<<<BT_, 256>>>(h_time, ln_w, ln_b, out);
}

// round 6
// speedup vs baseline: 5.6501x; 1.2930x over previous
#include <cuda_runtime.h>
#include <cuda_bf16.h>
#include <cuda_fp16.h>
#include <math.h>
#include <stdint.h>

#define N_ 1024
#define H_ 1024
#define B_ 64
#define T_ 256
#define BT_ (B_*T_)
#define HID_ 512

typedef __nv_bfloat16 bf16;

// ---------------- scratch (static device globals; no allocation) ----------------
__device__ __half g_hA16[BT_*H_];                  // h_time fp16
__device__ float g_hgate[B_*H_];
__device__ bf16  g_hgHi[128*H_], g_hgLo[128*H_];   // h_gate, padded to 128 rows
__device__ float g_hmean[H_];
__device__ bf16  g_Ehi[N_*H_], g_Elo[N_*H_];
__device__ float g_S[N_*N_];
__device__ float g_rowsum[N_];
__device__ bf16  g_G1h[HID_*H_], g_G1l[HID_*H_];   // gate_W1^T split
__device__ bf16  g_G2h[N_*HID_], g_G2l[N_*HID_];   // gate_W2^T split
__device__ bf16  g_hidh[128*HID_], g_hidl[128*HID_];
__device__ float g_gmean[N_];
__device__ bf16  g_Amh[N_*N_], g_Aml[N_*N_];       // A_mix [m][n] split
__device__ float g_Amf[N_*N_];                      // A_mix fp32 (bias fold)
__device__ bf16  g_W1h[H_*N_], g_W1l[H_*N_];       // h2n_W [H,N] split
__device__ bf16  g_W2th[H_*N_], g_W2tl[H_*N_];     // n2h_W^T [H,N] split
__device__ bf16  g_Ph[H_*N_], g_Pl[H_*N_];         // P = W1 @ AmixT
__device__ __half g_M16h[H_*H_];                   // McombT fp16
__device__ float g_zb[2*(size_t)N_*H_];            // split-K partials
__device__ float g_u[N_];
__device__ float g_cvec[H_];
__device__ float g_msg[BT_*H_];

// ---------------- helpers ----------------
__device__ __forceinline__ unsigned short bfbits(bf16 x) {
    return *reinterpret_cast<unsigned short*>(&x);
}
__device__ __forceinline__ uint32_t smem_u32(const void* p) {
    uint32_t a;
    asm("{ .reg .u64 t; cvta.to.shared.u64 t, %1; cvt.u32.u64 %0, t; }" : "=r"(a) : "l"(p));
    return a;
}
__device__ __forceinline__ uint32_t swz(uint32_t off) {
    return off ^ ((off >> 3) & 0x70);
}
#define CP_COMMIT() asm volatile("cp.async.commit_group;" ::: "memory")

__device__ __forceinline__ void ldsm4(uint32_t (&r)[4], uint32_t addr) {
    asm volatile("ldmatrix.sync.aligned.m8n8.x4.shared.b16 {%0,%1,%2,%3}, [%4];"
        : "=r"(r[0]), "=r"(r[1]), "=r"(r[2]), "=r"(r[3]) : "r"(addr));
}
__device__ __forceinline__ void mma_bf(float* c, const uint32_t* a, uint32_t b0, uint32_t b1) {
    asm volatile("mma.sync.aligned.m16n8k16.row.col.f32.bf16.bf16.f32 "
        "{%0,%1,%2,%3}, {%4,%5,%6,%7}, {%8,%9}, {%0,%1,%2,%3};"
        : "+f"(c[0]), "+f"(c[1]), "+f"(c[2]), "+f"(c[3])
        : "r"(a[0]), "r"(a[1]), "r"(a[2]), "r"(a[3]), "r"(b0), "r"(b1));
}
__device__ __forceinline__ void mma_fp(float* c, const uint32_t* a, uint32_t b0, uint32_t b1) {
    asm volatile("mma.sync.aligned.m16n8k16.row.col.f32.f16.f16.f32 "
        "{%0,%1,%2,%3}, {%4,%5,%6,%7}, {%8,%9}, {%0,%1,%2,%3};"
        : "+f"(c[0]), "+f"(c[1]), "+f"(c[2]), "+f"(c[3])
        : "r"(a[0]), "r"(a[1]), "r"(a[2]), "r"(a[3]), "r"(b0), "r"(b1));
}

// load one 128row x 64col 16-bit tile (SW128 swizzled, 128B/row); 256 threads
__device__ __forceinline__ void ld_tile(uint32_t sdst, const void* __restrict__ g,
                                        int row0, int K, int kc, int tid) {
    const int row = tid >> 1, half = tid & 1;
    const char* src = (const char*)g + (((size_t)(row0 + row) * K + (kc << 6)) << 1) + half * 64;
    uint32_t rb = (uint32_t)row * 128 + (uint32_t)half * 64;
    #pragma unroll
    for (int j = 0; j < 4; j++) {
        uint32_t sw = swz(rb + (j << 4));
        asm volatile("cp.async.cg.shared.global [%0], [%1], 16;"
            :: "r"(sdst + sw), "l"(src + (j << 4)));
    }
}

// ---------------- split-bf16 HMMA GEMM (TN)
// PASSES: 3 = (Ah+Al)(Bh+Bl) minus lolo; 1 = Ah*Bh only.
// OUT_MODE: 0 f32(+bias) [z-split aware], 1 f32 relu, 3 gelu->split bf16,
//           7 sigmoid->column-mean over rows 0..63 -> Cf[N]
#define TILE_B 16384
#define BUF_B  65536
#define GEMM_SMEM (1024 + 2 * BUF_B)

template<int OUT_MODE, int BIAS, int PASSES>
__global__ __launch_bounds__(256, 1) void hgemm(
    const bf16* __restrict__ Ahi, const bf16* __restrict__ Alo,
    const bf16* __restrict__ Bhi, const bf16* __restrict__ Blo,
    const float* __restrict__ bias,
    float* __restrict__ Cf, bf16* __restrict__ Chi, bf16* __restrict__ Clo,
    int M, int Nn, int K)
{
    extern __shared__ __align__(1024) char smem[];
    uint32_t sb = smem_u32(smem);
    const int tid = threadIdx.x;
    const int wid = tid >> 5, lane = tid & 31;
    const int wm = wid >> 1, wn = wid & 1;
    const int bx = blockIdx.x, by = blockIdx.y, bz = blockIdx.z;

    float* sBias = (float*)(smem + 512);
    if (BIAS && tid < 128) sBias[tid] = bias[bx * 128 + tid];

    const uint32_t T0 = sb + 1024;
    const int NKtot = K >> 6;
    const int NKp = NKtot / (int)gridDim.z;
    const int kc0 = bz * NKp;
    if (OUT_MODE == 0 && gridDim.z > 1) Cf += (size_t)bz * M * Nn;

    const int arow0 = by * 128, brow0 = bx * 128;

    float acc[2][8][4];
    #pragma unroll
    for (int i = 0; i < 2; i++)
        #pragma unroll
        for (int j = 0; j < 8; j++)
            #pragma unroll
            for (int l = 0; l < 4; l++) acc[i][j][l] = 0.f;

    const int mi = lane >> 3, li = lane & 7;
    const int rowoff = (mi & 1) * 8 + li;
    const int coloff = (mi >> 1) * 16;

    ld_tile(T0,              Ahi, arow0, K, kc0, tid);
    if (PASSES == 3) ld_tile(T0 + TILE_B, Alo, arow0, K, kc0, tid);
    ld_tile(T0 + 2 * TILE_B, Bhi, brow0, K, kc0, tid);
    if (PASSES == 3) ld_tile(T0 + 3 * TILE_B, Blo, brow0, K, kc0, tid);
    CP_COMMIT();

    for (int i = 0; i < NKp; i++) {
        const int cur = i & 1;
        if (i + 1 < NKp) {
            uint32_t nb = T0 + (cur ^ 1) * BUF_B;
            ld_tile(nb,              Ahi, arow0, K, kc0 + i + 1, tid);
            if (PASSES == 3) ld_tile(nb + TILE_B, Alo, arow0, K, kc0 + i + 1, tid);
            ld_tile(nb + 2 * TILE_B, Bhi, brow0, K, kc0 + i + 1, tid);
            if (PASSES == 3) ld_tile(nb + 3 * TILE_B, Blo, brow0, K, kc0 + i + 1, tid);
            CP_COMMIT();
            asm volatile("cp.async.wait_group 1;" ::: "memory");
        } else {
            asm volatile("cp.async.wait_group 0;" ::: "memory");
        }
        __syncthreads();

        const uint32_t Ah = T0 + cur * BUF_B;
        const uint32_t Al = Ah + TILE_B;
        const uint32_t Bh = Ah + 2 * TILE_B;
        const uint32_t Bl = Ah + 3 * TILE_B;

        #pragma unroll
        for (int ks = 0; ks < 4; ks++) {
            const int kb = ks * 32;
            uint32_t ahi[2][4], alo[2][4];
            #pragma unroll
            for (int mt = 0; mt < 2; mt++) {
                uint32_t ra = swz((uint32_t)(wm * 32 + mt * 16 + rowoff) * 128 + kb + coloff);
                ldsm4(ahi[mt], Ah + ra);
                if (PASSES == 3) ldsm4(alo[mt], Al + ra);
            }
            #pragma unroll
            for (int g = 0; g < 4; g++) {
                uint32_t rb = swz((uint32_t)(wn * 64 + g * 16 + rowoff) * 128 + kb + coloff);
                uint32_t bh[4], bl[4];
                ldsm4(bh, Bh + rb);
                if (PASSES == 3) ldsm4(bl, Bl + rb);
                #pragma unroll
                for (int mt = 0; mt < 2; mt++) {
                    #pragma unroll
                    for (int sub = 0; sub < 2; sub++) {
                        float* c = acc[mt][g * 2 + sub];
                        mma_bf(c, ahi[mt], bh[sub], bh[2 + sub]);
                        if (PASSES == 3) {
                            mma_bf(c, ahi[mt], bl[sub], bl[2 + sub]);
                            mma_bf(c, alo[mt], bh[sub], bh[2 + sub]);
                        }
                    }
                }
            }
        }
        __syncthreads();
    }

    if (OUT_MODE == 7) {
        // sigmoid, stage into smem [128][128], column-mean over rows 0..63
        float* gb = (float*)(smem + 1024);
        #pragma unroll
        for (int mt = 0; mt < 2; mt++) {
            #pragma unroll
            for (int nt = 0; nt < 8; nt++) {
                const int rl = wm * 32 + mt * 16 + (lane >> 2);
                const int cl = wn * 64 + nt * 8 + (lane & 3) * 2;
                float bb0 = sBias[cl], bb1 = sBias[cl + 1];
                float v0 = 1.0f / (1.0f + expf(-(acc[mt][nt][0] + bb0)));
                float v1 = 1.0f / (1.0f + expf(-(acc[mt][nt][1] + bb1)));
                float v2 = 1.0f / (1.0f + expf(-(acc[mt][nt][2] + bb0)));
                float v3 = 1.0f / (1.0f + expf(-(acc[mt][nt][3] + bb1)));
                gb[rl * 128 + cl] = v0;       gb[rl * 128 + cl + 1] = v1;
                gb[(rl + 8) * 128 + cl] = v2; gb[(rl + 8) * 128 + cl + 1] = v3;
            }
        }
        __syncthreads();
        if (tid < 128) {
            float s = 0.f;
            #pragma unroll 8
            for (int r = 0; r < 64; r++) s += gb[r * 128 + tid];
            Cf[bx * 128 + tid] = s * (1.0f / 64.0f);
        }
        return;
    }

    #pragma unroll
    for (int mt = 0; mt < 2; mt++) {
        #pragma unroll
        for (int nt = 0; nt < 8; nt++) {
            const int r0 = by * 128 + wm * 32 + mt * 16 + (lane >> 2);
            const int cb = wn * 64 + nt * 8 + (lane & 3) * 2;
            const int cg = bx * 128 + cb;
            float v0 = acc[mt][nt][0], v1 = acc[mt][nt][1];
            float v2 = acc[mt][nt][2], v3 = acc[mt][nt][3];
            if (BIAS) {
                float bb0 = sBias[cb], bb1 = sBias[cb + 1];
                v0 += bb0; v1 += bb1; v2 += bb0; v3 += bb1;
            }
            if (OUT_MODE == 1) {
                v0 = fmaxf(v0, 0.f); v1 = fmaxf(v1, 0.f);
                v2 = fmaxf(v2, 0.f); v3 = fmaxf(v3, 0.f);
            }
            if (OUT_MODE == 3) {
                const float is2 = 0.70710678118654752f;
                v0 = 0.5f * v0 * (1.0f + erff(v0 * is2));
                v1 = 0.5f * v1 * (1.0f + erff(v1 * is2));
                v2 = 0.5f * v2 * (1.0f + erff(v2 * is2));
                v3 = 0.5f * v3 * (1.0f + erff(v3 * is2));
            }
            if (OUT_MODE == 3) {
                bf16 h0 = __float2bfloat16(v0), h1 = __float2bfloat16(v1);
                bf16 h2 = __float2bfloat16(v2), h3 = __float2bfloat16(v3);
                bf16 l0 = __float2bfloat16(v0 - __bfloat162float(h0));
                bf16 l1 = __float2bfloat16(v1 - __bfloat162float(h1));
                bf16 l2 = __float2bfloat16(v2 - __bfloat162float(h2));
                bf16 l3 = __float2bfloat16(v3 - __bfloat162float(h3));
                *(uint32_t*)(Chi + (size_t)r0 * Nn + cg)       = ((uint32_t)bfbits(h1) << 16) | bfbits(h0);
                *(uint32_t*)(Chi + (size_t)(r0 + 8) * Nn + cg) = ((uint32_t)bfbits(h3) << 16) | bfbits(h2);
                *(uint32_t*)(Clo + (size_t)r0 * Nn + cg)       = ((uint32_t)bfbits(l1) << 16) | bfbits(l0);
                *(uint32_t*)(Clo + (size_t)(r0 + 8) * Nn + cg) = ((uint32_t)bfbits(l3) << 16) | bfbits(l2);
            } else {
                *(float2*)(Cf + (size_t)r0 * Nn + cg)       = make_float2(v0, v1);
                *(float2*)(Cf + (size_t)(r0 + 8) * Nn + cg) = make_float2(v2, v3);
            }
        }
    }
}

// ---------------- fp16 single-pass GEMM: C = A @ Bh^T + bias, 4-stage pipeline ----------------
#define FTILE_B 16384
#define FSTAGE_B (2 * FTILE_B)
#define FGEMM_SMEM (1024 + 4 * FSTAGE_B)

__global__ __launch_bounds__(256, 1) void fgemm(
    const __half* __restrict__ A,
    const __half* __restrict__ Bh,
    const float* __restrict__ bias,
    float* __restrict__ Cf, int M, int Nn, int K)
{
    extern __shared__ __align__(1024) char smem[];
    uint32_t sb = smem_u32(smem);
    const int tid = threadIdx.x;
    const int wid = tid >> 5, lane = tid & 31;
    const int wm = wid >> 1, wn = wid & 1;
    const int bx = blockIdx.x, by = blockIdx.y;

    float* sBias = (float*)(smem + 512);
    if (tid < 128) sBias[tid] = bias[bx * 128 + tid];

    const uint32_t T0 = sb + 1024;
    const int NK = K >> 6;
    const int arow0 = by * 128, brow0 = bx * 128;

    float acc[2][8][4];
    #pragma unroll
    for (int i = 0; i < 2; i++)
        #pragma unroll
        for (int j = 0; j < 8; j++)
            #pragma unroll
            for (int l = 0; l < 4; l++) acc[i][j][l] = 0.f;

    const int mi = lane >> 3, li = lane & 7;
    const int rowoff = (mi & 1) * 8 + li;
    const int coloff = (mi >> 1) * 16;

    #pragma unroll
    for (int s = 0; s < 3; s++) {
        uint32_t st = T0 + s * FSTAGE_B;
        ld_tile(st,           A,  arow0, K, s, tid);
        ld_tile(st + FTILE_B, Bh, brow0, K, s, tid);
        CP_COMMIT();
    }

    for (int kc = 0; kc < NK; kc++) {
        const int rem = NK - kc;
        if (rem >= 3)      asm volatile("cp.async.wait_group 2;" ::: "memory");
        else if (rem == 2) asm volatile("cp.async.wait_group 1;" ::: "memory");
        else               asm volatile("cp.async.wait_group 0;" ::: "memory");
        __syncthreads();

        if (kc + 3 < NK) {
            uint32_t st = T0 + ((kc + 3) & 3) * FSTAGE_B;
            ld_tile(st,           A,  arow0, K, kc + 3, tid);
            ld_tile(st + FTILE_B, Bh, brow0, K, kc + 3, tid);
            CP_COMMIT();
        }

        const uint32_t Sa = T0 + (kc & 3) * FSTAGE_B;
        const uint32_t Sh = Sa + FTILE_B;

        #pragma unroll
        for (int ks = 0; ks < 4; ks++) {
            const int kb = ks * 32;
            uint32_t a[2][4];
            #pragma unroll
            for (int mt = 0; mt < 2; mt++) {
                uint32_t ra = swz((uint32_t)(wm * 32 + mt * 16 + rowoff) * 128 + kb + coloff);
                ldsm4(a[mt], Sa + ra);
            }
            #pragma unroll
            for (int g = 0; g < 4; g++) {
                uint32_t rb = swz((uint32_t)(wn * 64 + g * 16 + rowoff) * 128 + kb + coloff);
                uint32_t bh[4];
                ldsm4(bh, Sh + rb);
                #pragma unroll
                for (int mt = 0; mt < 2; mt++) {
                    #pragma unroll
                    for (int sub = 0; sub < 2; sub++) {
                        mma_fp(acc[mt][g * 2 + sub], a[mt], bh[sub], bh[2 + sub]);
                    }
                }
            }
        }
    }

    #pragma unroll
    for (int mt = 0; mt < 2; mt++) {
        #pragma unroll
        for (int nt = 0; nt < 8; nt++) {
            const int r0 = by * 128 + wm * 32 + mt * 16 + (lane >> 2);
            const int cb = wn * 64 + nt * 8 + (lane & 3) * 2;
            const int cg = bx * 128 + cb;
            float bb0 = sBias[cb], bb1 = sBias[cb + 1];
            *(float2*)(Cf + (size_t)r0 * Nn + cg) =
                make_float2(acc[mt][nt][0] + bb0, acc[mt][nt][1] + bb1);
            *(float2*)(Cf + (size_t)(r0 + 8) * Nn + cg) =
                make_float2(acc[mt][nt][2] + bb0, acc[mt][nt][3] + bb1);
        }
    }
}

// ---------------- small kernels ----------------
// fused: h_time -> fp16 + h_gate mean + bf16 split; rows >= 64 zero-padded
__global__ __launch_bounds__(256) void k_pre(const float* __restrict__ h) {
    int b = blockIdx.y;
    int hh = blockIdx.x * 256 + threadIdx.x;
    if (b >= 64) {
        g_hgHi[b * H_ + hh] = __float2bfloat16(0.f);
        g_hgLo[b * H_ + hh] = __float2bfloat16(0.f);
        return;
    }
    const float* p = h + (size_t)b * T_ * H_ + hh;
    __half* q = g_hA16 + (size_t)b * T_ * H_ + hh;
    float s = 0.f;
    #pragma unroll 4
    for (int t = 0; t < T_; t++) {
        float v = p[(size_t)t * H_];
        q[(size_t)t * H_] = __float2half(v);
        s += v;
    }
    float mean = s * (1.0f / T_);
    g_hgate[b * H_ + hh] = mean;
    bf16 hi = __float2bfloat16(mean);
    g_hgHi[b * H_ + hh] = hi;
    g_hgLo[b * H_ + hh] = __float2bfloat16(mean - __bfloat162float(hi));
}

__global__ void k_meanB() {
    int hh = blockIdx.x * blockDim.x + threadIdx.x;
    if (hh >= H_) return;
    float s = 0.f;
    #pragma unroll
    for (int b = 0; b < B_; b++) s += g_hgate[b * H_ + hh];
    g_hmean[hh] = s * (1.0f / B_);
}

__global__ __launch_bounds__(256) void k_enorm(const float* __restrict__ E_dyn) {
    int i = blockIdx.x;
    __shared__ float red[256];
    float vals[4];
    float ss = 0.f;
    #pragma unroll
    for (int j = 0; j < 4; j++) {
        int hh = threadIdx.x + j * 256;
        float v = E_dyn[i * H_ + hh] + g_hmean[hh];
        vals[j] = v; ss += v * v;
    }
    red[threadIdx.x] = ss; __syncthreads();
    for (int off = 128; off > 0; off >>= 1) {
        if (threadIdx.x < off) red[threadIdx.x] += red[threadIdx.x + off];
        __syncthreads();
    }
    float inv = 1.0f / fmaxf(sqrtf(red[0]), 1e-12f);
    #pragma unroll
    for (int j = 0; j < 4; j++) {
        int hh = threadIdx.x + j * 256;
        float v = vals[j] * inv;
        bf16 h = __float2bfloat16(v);
        g_Ehi[i * H_ + hh] = h;
        g_Elo[i * H_ + hh] = __float2bfloat16(v - __bfloat162float(h));
    }
}

__global__ __launch_bounds__(256) void k_rowsum() {
    int i = blockIdx.x;
    __shared__ float red[256];
    float s = 0.f;
    for (int j = threadIdx.x; j < N_; j += 256) s += g_S[i * N_ + j];
    red[threadIdx.x] = s; __syncthreads();
    for (int off = 128; off > 0; off >>= 1) {
        if (threadIdx.x < off) red[threadIdx.x] += red[threadIdx.x + off];
        __syncthreads();
    }
    if (threadIdx.x == 0) g_rowsum[i] = red[0];
}

__global__ void k_amix(const float* __restrict__ Ap, const float* __restrict__ alpha_raw) {
    int idx = blockIdx.x * blockDim.x + threadIdx.x;
    if (idx >= N_*N_) return;
    int m = idx >> 10, n = idx & 1023;
    float alpha = 1.0f / (1.0f + expf(-alpha_raw[0]));
    float ad = 0.5f * (g_S[idx] / (g_rowsum[m] + 1e-6f) + g_S[n * N_ + m] / (g_rowsum[n] + 1e-6f));
    float v = (alpha * Ap[idx] + (1.0f - alpha) * ad) * g_gmean[m];
    bf16 h = __float2bfloat16(v);
    g_Amh[idx] = h;
    g_Aml[idx] = __float2bfloat16(v - __bfloat162float(h));
    g_Amf[idx] = v;
}

__global__ void k_split(const float* __restrict__ x, bf16* __restrict__ hi, bf16* __restrict__ lo, int n4) {
    for (int i = blockIdx.x * blockDim.x + threadIdx.x; i < n4; i += gridDim.x * blockDim.x) {
        float4 v = ((const float4*)x)[i];
        bf16 h0 = __float2bfloat16(v.x), h1 = __float2bfloat16(v.y);
        bf16 h2 = __float2bfloat16(v.z), h3 = __float2bfloat16(v.w);
        bf16 l0 = __float2bfloat16(v.x - __bfloat162float(h0));
        bf16 l1 = __float2bfloat16(v.y - __bfloat162float(h1));
        bf16 l2 = __float2bfloat16(v.z - __bfloat162float(h2));
        bf16 l3 = __float2bfloat16(v.w - __bfloat162float(h3));
        uint2 hv, lv;
        hv.x = ((uint32_t)bfbits(h1) << 16) | bfbits(h0);
        hv.y = ((uint32_t)bfbits(h3) << 16) | bfbits(h2);
        lv.x = ((uint32_t)bfbits(l1) << 16) | bfbits(l0);
        lv.y = ((uint32_t)bfbits(l3) << 16) | bfbits(l2);
        ((uint2*)hi)[i] = hv;
        ((uint2*)lo)[i] = lv;
    }
}

__global__ void k_tsplit(const float* __restrict__ W, bf16* __restrict__ Oh, bf16* __restrict__ Ol,
                         int Rin, int Cin) {
    __shared__ float t[32][33];
    int c0 = blockIdx.x * 32, r0 = blockIdx.y * 32;
    #pragma unroll
    for (int i = 0; i < 4; i++)
        t[threadIdx.y + i * 8][threadIdx.x] = W[(size_t)(r0 + threadIdx.y + i * 8) * Cin + c0 + threadIdx.x];
    __syncthreads();
    #pragma unroll
    for (int i = 0; i < 4; i++) {
        int oc = threadIdx.y + i * 8;
        float v = t[threadIdx.x][oc];
        size_t o = (size_t)(c0 + oc) * Rin + r0 + threadIdx.x;
        bf16 h = __float2bfloat16(v);
        Oh[o] = h;
        Ol[o] = __float2bfloat16(v - __bfloat162float(h));
    }
}

// combine split-K partials -> bf16 hi/lo (P)
__global__ void k_combP() {
    int i = blockIdx.x * blockDim.x + threadIdx.x;
    if (i >= N_*H_) return;
    float v = g_zb[i] + g_zb[(size_t)N_*H_ + i];
    bf16 h = __float2bfloat16(v);
    g_Ph[i] = h;
    g_Pl[i] = __float2bfloat16(v - __bfloat162float(h));
}

// combine split-K partials -> fp16 (Mcomb)
__global__ void k_combM() {
    int i = blockIdx.x * blockDim.x + threadIdx.x;
    if (i >= H_*H_) return;
    g_M16h[i] = __float2half(g_zb[i] + g_zb[(size_t)N_*H_ + i]);
}

// u[m] = sum_n A_mix[m][n] * b1[n]
__global__ __launch_bounds__(256) void k_bias_u(const float* __restrict__ b1) {
    int m = blockIdx.x;
    __shared__ float red[256];
    float s = 0.f;
    for (int n = threadIdx.x; n < N_; n += 256) s += g_Amf[m * N_ + n] * b1[n];
    red[threadIdx.x] = s; __syncthreads();
    for (int off = 128; off > 0; off >>= 1) {
        if (threadIdx.x < off) red[threadIdx.x] += red[threadIdx.x + off];
        __syncthreads();
    }
    if (threadIdx.x == 0) g_u[m] = red[0];
}

// cvec[h] = sum_m u[m] * W2t[h][m] + b2[h]
__global__ __launch_bounds__(256) void k_bias_c(const float* __restrict__ b2) {
    int h = blockIdx.x;
    __shared__ float red[256];
    float s = 0.f;
    for (int m = threadIdx.x; m < N_; m += 256)
        s += g_u[m] * (__bfloat162float(g_W2th[(size_t)h * N_ + m]) +
                       __bfloat162float(g_W2tl[(size_t)h * N_ + m]));
    red[threadIdx.x] = s; __syncthreads();
    for (int off = 128; off > 0; off >>= 1) {
        if (threadIdx.x < off) red[threadIdx.x] += red[threadIdx.x + off];
        __syncthreads();
    }
    if (threadIdx.x == 0) g_cvec[h] = red[0] + b2[h];
}

__global__ __launch_bounds__(256) void k_final(const float* __restrict__ h,
                                               const float* __restrict__ lw,
                                               const float* __restrict__ lb,
                                               float* __restrict__ out) {
    int row = blockIdx.x;
    size_t base = (size_t)row * H_ + threadIdx.x * 4;
    const float gw = 1.0f + tanhf(1.0f / 1024.0f);
    float4 a = *(const float4*)(h + base);
    float4 m = *(const float4*)(g_msg + base);
    float v0 = a.x * gw + m.x, v1 = a.y * gw + m.y;
    float v2 = a.z * gw + m.z, v3 = a.w * gw + m.w;

    __shared__ float red[256];
    red[threadIdx.x] = v0 + v1 + v2 + v3;
    __syncthreads();
    for (int off = 128; off > 0; off >>= 1) {
        if (threadIdx.x < off) red[threadIdx.x] += red[threadIdx.x + off];
        __syncthreads();
    }
    float mu = red[0] * (1.0f / H_);
    __syncthreads();
    float d0 = v0 - mu, d1 = v1 - mu, d2 = v2 - mu, d3 = v3 - mu;
    red[threadIdx.x] = d0 * d0 + d1 * d1 + d2 * d2 + d3 * d3;
    __syncthreads();
    for (int off = 128; off > 0; off >>= 1) {
        if (threadIdx.x < off) red[threadIdx.x] += red[threadIdx.x + off];
        __syncthreads();
    }
    float rstd = rsqrtf(red[0] * (1.0f / H_) + 1e-5f);
    float4 w = *(const float4*)(lw + threadIdx.x * 4);
    float4 bb = *(const float4*)(lb + threadIdx.x * 4);
    float4 o;
    o.x = d0 * rstd * w.x + bb.x;
    o.y = d1 * rstd * w.y + bb.y;
    o.z = d2 * rstd * w.z + bb.z;
    o.w = d3 * rstd * w.w + bb.w;
    *(float4*)(out + base) = o;
}

// ---------------- launcher ----------------
extern "C" void kernel_launch(void* const* d_in, const int* in_sizes, int n_in,
                              void* d_out, int out_size) {
    const float* h_time    = (const float*)d_in[0];
    const float* A_pearson = (const float*)d_in[1];
    const float* E_dyn     = (const float*)d_in[2];
    const float* alpha_raw = (const float*)d_in[3];
    // d_in[4] = tau_raw : analytically eliminated (mean over softmax axis == 1/N)
    const float* gate_W1   = (const float*)d_in[5];
    const float* gate_b1   = (const float*)d_in[6];
    const float* gate_W2   = (const float*)d_in[7];
    const float* gate_b2   = (const float*)d_in[8];
    const float* h2n_W     = (const float*)d_in[9];
    const float* h2n_b     = (const float*)d_in[10];
    const float* n2h_W     = (const float*)d_in[11];
    const float* n2h_b     = (const float*)d_in[12];
    const float* ln_w      = (const float*)d_in[13];
    const float* ln_b      = (const float*)d_in[14];
    float* out = (float*)d_out;

    bf16 *p_Ehi, *p_Elo, *p_Amh, *p_Aml, *p_W1h, *p_W1l, *p_W2th, *p_W2tl;
    bf16 *p_Ph, *p_Pl, *p_hgHi, *p_hgLo, *p_G1h, *p_G1l, *p_G2h, *p_G2l, *p_hidh, *p_hidl;
    __half *p_hA16, *p_M16h;
    float *p_S, *p_msg, *p_cvec, *p_gmean, *p_zb;
    cudaGetSymbolAddress((void**)&p_Ehi, g_Ehi);   cudaGetSymbolAddress((void**)&p_Elo, g_Elo);
    cudaGetSymbolAddress((void**)&p_Amh, g_Amh);   cudaGetSymbolAddress((void**)&p_Aml, g_Aml);
    cudaGetSymbolAddress((void**)&p_W1h, g_W1h);   cudaGetSymbolAddress((void**)&p_W1l, g_W1l);
    cudaGetSymbolAddress((void**)&p_W2th, g_W2th); cudaGetSymbolAddress((void**)&p_W2tl, g_W2tl);
    cudaGetSymbolAddress((void**)&p_Ph, g_Ph);     cudaGetSymbolAddress((void**)&p_Pl, g_Pl);
    cudaGetSymbolAddress((void**)&p_hgHi, g_hgHi); cudaGetSymbolAddress((void**)&p_hgLo, g_hgLo);
    cudaGetSymbolAddress((void**)&p_G1h, g_G1h);   cudaGetSymbolAddress((void**)&p_G1l, g_G1l);
    cudaGetSymbolAddress((void**)&p_G2h, g_G2h);   cudaGetSymbolAddress((void**)&p_G2l, g_G2l);
    cudaGetSymbolAddress((void**)&p_hidh, g_hidh); cudaGetSymbolAddress((void**)&p_hidl, g_hidl);
    cudaGetSymbolAddress((void**)&p_hA16, g_hA16);
    cudaGetSymbolAddress((void**)&p_M16h, g_M16h);
    cudaGetSymbolAddress((void**)&p_S, g_S);       cudaGetSymbolAddress((void**)&p_msg, g_msg);
    cudaGetSymbolAddress((void**)&p_cvec, g_cvec); cudaGetSymbolAddress((void**)&p_gmean, g_gmean);
    cudaGetSymbolAddress((void**)&p_zb, g_zb);

    cudaFuncSetAttribute(hgemm<1, 0, 1>, cudaFuncAttributeMaxDynamicSharedMemorySize, GEMM_SMEM);
    cudaFuncSetAttribute(hgemm<3, 1, 1>, cudaFuncAttributeMaxDynamicSharedMemorySize, GEMM_SMEM);
    cudaFuncSetAttribute(hgemm<7, 1, 1>, cudaFuncAttributeMaxDynamicSharedMemorySize, GEMM_SMEM);
    cudaFuncSetAttribute(hgemm<0, 0, 3>, cudaFuncAttributeMaxDynamicSharedMemorySize, GEMM_SMEM);
    cudaFuncSetAttribute(fgemm, cudaFuncAttributeMaxDynamicSharedMemorySize, FGEMM_SMEM);

    // fused reductions + fp16 convert (+pad); weight prep
    k_pre<<<dim3(4, 128), 256>>>(h_time);
    k_meanB<<<(H_ + 255) / 256, 256>>>();
    k_enorm<<<N_, 256>>>(E_dyn);
    k_split<<<512, 256>>>(h2n_W, p_W1h, p_W1l, H_*N_ / 4);
    {
        dim3 b(32, 8);
        k_tsplit<<<dim3(H_ / 32, N_ / 32), b>>>(n2h_W, p_W2th, p_W2tl, N_, H_);     // [N,H]->[H,N]
        k_tsplit<<<dim3(HID_ / 32, H_ / 32), b>>>(gate_W1, p_G1h, p_G1l, H_, HID_); // [H,HID]->[HID,H]
        k_tsplit<<<dim3(N_ / 32, HID_ / 32), b>>>(gate_W2, p_G2h, p_G2l, HID_, N_); // [HID,N]->[N,HID]
    }

    // S = relu(E_cur @ E_cur^T) — single-pass bf16 (error diluted into tiny A_dyn)
    hgemm<1, 0, 1><<<dim3(N_ / 128, N_ / 128), 256, GEMM_SMEM>>>(
        p_Ehi, nullptr, p_Ehi, nullptr, nullptr, p_S, nullptr, nullptr, N_, N_, H_);
    k_rowsum<<<N_, 256>>>();

    // gate MLP — single-pass bf16; gate2 fuses sigmoid + column-mean -> gmean
    hgemm<3, 1, 1><<<dim3(HID_ / 128, 1), 256, GEMM_SMEM>>>(
        p_hgHi, nullptr, p_G1h, nullptr, gate_b1, nullptr, p_hidh, p_hidl, 128, HID_, H_);
    hgemm<7, 1, 1><<<dim3(N_ / 128, 1), 256, GEMM_SMEM>>>(
        p_hidh, nullptr, p_G2h, nullptr, gate_b2, p_gmean, nullptr, nullptr, 128, N_, HID_);
    k_amix<<<(N_*N_ + 255) / 256, 256>>>(A_pearson, alpha_raw);

    // P = W1 @ AmixT (3-pass bf16, split-K=2) -> combine -> split bf16
    hgemm<0, 0, 3><<<dim3(N_ / 128, H_ / 128, 2), 256, GEMM_SMEM>>>(
        p_W1h, p_W1l, p_Amh, p_Aml, nullptr, p_zb, nullptr, nullptr, H_, N_, N_);
    k_combP<<<(N_*H_ + 255) / 256, 256>>>();

    // McombT = W2t @ P^T (3-pass bf16, split-K=2) -> combine -> fp16
    hgemm<0, 0, 3><<<dim3(H_ / 128, H_ / 128, 2), 256, GEMM_SMEM>>>(
        p_W2th, p_W2tl, p_Ph, p_Pl, nullptr, p_zb, nullptr, nullptr, H_, H_, N_);
    k_combM<<<(H_*H_ + 255) / 256, 256>>>();

    // bias fold: cvec = b1 @ AmixT @ W2 + b2
    k_bias_u<<<N_, 256>>>(h2n_b);
    k_bias_c<<<H_, 256>>>(n2h_b);

    // THE big GEMM: msg = h_time @ Mcomb + cvec  (fp16 x fp16, single pass)
    fgemm<<<dim3(H_ / 128, BT_ / 128), 256, FGEMM_SMEM>>>(
        p_hA16, p_M16h, p_cvec, p_msg, BT_, H_, H_);

    // fused residual + LayerNorm
    k_final<<<BT_, 256>>>(h_time, ln_w, ln_b, out);
}

// round 7
// speedup vs baseline: 5.9607x; 1.0550x over previous
#include <cuda_runtime.h>
#include <cuda_bf16.h>
#include <cuda_fp16.h>
#include <math.h>
#include <stdint.h>

#define N_ 1024
#define H_ 1024
#define B_ 64
#define T_ 256
#define BT_ (B_*T_)
#define HID_ 512

typedef __nv_bfloat16 bf16;

// ---------------- scratch (static device globals; no allocation) ----------------
__device__ __half g_hA16[BT_*H_];                  // h_time fp16
__device__ float g_hgate[B_*H_];
__device__ bf16  g_hgHi[128*H_], g_hgLo[128*H_];   // h_gate, padded to 128 rows
__device__ float g_hmean[H_];
__device__ bf16  g_Ehi[N_*H_], g_Elo[N_*H_];
__device__ float g_S[N_*N_];
__device__ float g_rowsum[N_];
__device__ bf16  g_G1h[HID_*H_], g_G1l[HID_*H_];   // gate_W1^T split
__device__ bf16  g_G2h[N_*HID_], g_G2l[N_*HID_];   // gate_W2^T split
__device__ bf16  g_hidh[128*HID_];
__device__ float g_gmean[N_];
__device__ bf16  g_Amh[N_*N_], g_Aml[N_*N_];       // A_mix [m][n] split
__device__ bf16  g_W1h[H_*N_], g_W1l[H_*N_];       // h2n_W [H,N] split
__device__ bf16  g_W2th[H_*N_], g_W2tl[H_*N_];     // n2h_W^T [H,N] split
__device__ bf16  g_Ph[H_*N_], g_Pl[H_*N_];         // P = W1 @ AmixT
__device__ __half g_M16h[H_*H_];                   // McombT fp16
__device__ float g_zb[2*(size_t)N_*H_];            // split-K / gate partials
__device__ float g_u[N_];
__device__ float g_cvec[H_];
__device__ __half g_msg16[BT_*H_];

// ---------------- helpers ----------------
__device__ __forceinline__ unsigned short bfbits(bf16 x) {
    return *reinterpret_cast<unsigned short*>(&x);
}
__device__ __forceinline__ unsigned short hfbits(__half x) {
    return *reinterpret_cast<unsigned short*>(&x);
}
__device__ __forceinline__ uint32_t smem_u32(const void* p) {
    uint32_t a;
    asm("{ .reg .u64 t; cvta.to.shared.u64 t, %1; cvt.u32.u64 %0, t; }" : "=r"(a) : "l"(p));
    return a;
}
__device__ __forceinline__ uint32_t swz(uint32_t off) {
    return off ^ ((off >> 3) & 0x70);
}
#define CP_COMMIT() asm volatile("cp.async.commit_group;" ::: "memory")

__device__ __forceinline__ void ldsm4(uint32_t (&r)[4], uint32_t addr) {
    asm volatile("ldmatrix.sync.aligned.m8n8.x4.shared.b16 {%0,%1,%2,%3}, [%4];"
        : "=r"(r[0]), "=r"(r[1]), "=r"(r[2]), "=r"(r[3]) : "r"(addr));
}
__device__ __forceinline__ void mma_bf(float* c, const uint32_t* a, uint32_t b0, uint32_t b1) {
    asm volatile("mma.sync.aligned.m16n8k16.row.col.f32.bf16.bf16.f32 "
        "{%0,%1,%2,%3}, {%4,%5,%6,%7}, {%8,%9}, {%0,%1,%2,%3};"
        : "+f"(c[0]), "+f"(c[1]), "+f"(c[2]), "+f"(c[3])
        : "r"(a[0]), "r"(a[1]), "r"(a[2]), "r"(a[3]), "r"(b0), "r"(b1));
}
__device__ __forceinline__ void mma_fp(float* c, const uint32_t* a, uint32_t b0, uint32_t b1) {
    asm volatile("mma.sync.aligned.m16n8k16.row.col.f32.f16.f16.f32 "
        "{%0,%1,%2,%3}, {%4,%5,%6,%7}, {%8,%9}, {%0,%1,%2,%3};"
        : "+f"(c[0]), "+f"(c[1]), "+f"(c[2]), "+f"(c[3])
        : "r"(a[0]), "r"(a[1]), "r"(a[2]), "r"(a[3]), "r"(b0), "r"(b1));
}

// load one 128row x 64col 16-bit tile (SW128 swizzled, 128B/row); 256 threads
__device__ __forceinline__ void ld_tile(uint32_t sdst, const void* __restrict__ g,
                                        int row0, int K, int kc, int tid) {
    const int row = tid >> 1, half = tid & 1;
    const char* src = (const char*)g + (((size_t)(row0 + row) * K + (kc << 6)) << 1) + half * 64;
    uint32_t rb = (uint32_t)row * 128 + (uint32_t)half * 64;
    #pragma unroll
    for (int j = 0; j < 4; j++) {
        uint32_t sw = swz(rb + (j << 4));
        asm volatile("cp.async.cg.shared.global [%0], [%1], 16;"
            :: "r"(sdst + sw), "l"(src + (j << 4)));
    }
}

// ---------------- split-bf16 HMMA GEMM (TN)
// PASSES: 3 = (Ah+Al)(Bh+Bl) minus lolo; 1 = Ah*Bh only.
// OUT_MODE: 0 f32 [z-split aware], 1 f32 relu,
//           7 sigmoid->column-mean over rows 0..63 -> Cf[N]
#define TILE_B 16384
#define BUF_B  65536
#define GEMM_SMEM (1024 + 2 * BUF_B)

template<int OUT_MODE, int BIAS, int PASSES>
__global__ __launch_bounds__(256, 1) void hgemm(
    const bf16* __restrict__ Ahi, const bf16* __restrict__ Alo,
    const bf16* __restrict__ Bhi, const bf16* __restrict__ Blo,
    const float* __restrict__ bias,
    float* __restrict__ Cf, bf16* __restrict__ Chi, bf16* __restrict__ Clo,
    int M, int Nn, int K)
{
    extern __shared__ __align__(1024) char smem[];
    uint32_t sb = smem_u32(smem);
    const int tid = threadIdx.x;
    const int wid = tid >> 5, lane = tid & 31;
    const int wm = wid >> 1, wn = wid & 1;
    const int bx = blockIdx.x, by = blockIdx.y, bz = blockIdx.z;

    float* sBias = (float*)(smem + 512);
    if (BIAS && tid < 128) sBias[tid] = bias[bx * 128 + tid];

    const uint32_t T0 = sb + 1024;
    const int NKtot = K >> 6;
    const int NKp = NKtot / (int)gridDim.z;
    const int kc0 = bz * NKp;
    if (OUT_MODE == 0 && gridDim.z > 1) Cf += (size_t)bz * M * Nn;

    const int arow0 = by * 128, brow0 = bx * 128;

    float acc[2][8][4];
    #pragma unroll
    for (int i = 0; i < 2; i++)
        #pragma unroll
        for (int j = 0; j < 8; j++)
            #pragma unroll
            for (int l = 0; l < 4; l++) acc[i][j][l] = 0.f;

    const int mi = lane >> 3, li = lane & 7;
    const int rowoff = (mi & 1) * 8 + li;
    const int coloff = (mi >> 1) * 16;

    ld_tile(T0,              Ahi, arow0, K, kc0, tid);
    if (PASSES == 3) ld_tile(T0 + TILE_B, Alo, arow0, K, kc0, tid);
    ld_tile(T0 + 2 * TILE_B, Bhi, brow0, K, kc0, tid);
    if (PASSES == 3) ld_tile(T0 + 3 * TILE_B, Blo, brow0, K, kc0, tid);
    CP_COMMIT();

    for (int i = 0; i < NKp; i++) {
        const int cur = i & 1;
        if (i + 1 < NKp) {
            uint32_t nb = T0 + (cur ^ 1) * BUF_B;
            ld_tile(nb,              Ahi, arow0, K, kc0 + i + 1, tid);
            if (PASSES == 3) ld_tile(nb + TILE_B, Alo, arow0, K, kc0 + i + 1, tid);
            ld_tile(nb + 2 * TILE_B, Bhi, brow0, K, kc0 + i + 1, tid);
            if (PASSES == 3) ld_tile(nb + 3 * TILE_B, Blo, brow0, K, kc0 + i + 1, tid);
            CP_COMMIT();
            asm volatile("cp.async.wait_group 1;" ::: "memory");
        } else {
            asm volatile("cp.async.wait_group 0;" ::: "memory");
        }
        __syncthreads();

        const uint32_t Ah = T0 + cur * BUF_B;
        const uint32_t Al = Ah + TILE_B;
        const uint32_t Bh = Ah + 2 * TILE_B;
        const uint32_t Bl = Ah + 3 * TILE_B;

        #pragma unroll
        for (int ks = 0; ks < 4; ks++) {
            const int kb = ks * 32;
            uint32_t ahi[2][4], alo[2][4];
            #pragma unroll
            for (int mt = 0; mt < 2; mt++) {
                uint32_t ra = swz((uint32_t)(wm * 32 + mt * 16 + rowoff) * 128 + kb + coloff);
                ldsm4(ahi[mt], Ah + ra);
                if (PASSES == 3) ldsm4(alo[mt], Al + ra);
            }
            #pragma unroll
            for (int g = 0; g < 4; g++) {
                uint32_t rb = swz((uint32_t)(wn * 64 + g * 16 + rowoff) * 128 + kb + coloff);
                uint32_t bh[4], bl[4];
                ldsm4(bh, Bh + rb);
                if (PASSES == 3) ldsm4(bl, Bl + rb);
                #pragma unroll
                for (int mt = 0; mt < 2; mt++) {
                    #pragma unroll
                    for (int sub = 0; sub < 2; sub++) {
                        float* c = acc[mt][g * 2 + sub];
                        mma_bf(c, ahi[mt], bh[sub], bh[2 + sub]);
                        if (PASSES == 3) {
                            mma_bf(c, ahi[mt], bl[sub], bl[2 + sub]);
                            mma_bf(c, alo[mt], bh[sub], bh[2 + sub]);
                        }
                    }
                }
            }
        }
        __syncthreads();
    }

    if (OUT_MODE == 7) {
        // sigmoid, stage into smem [128][128], column-mean over rows 0..63
        float* gb = (float*)(smem + 1024);
        #pragma unroll
        for (int mt = 0; mt < 2; mt++) {
            #pragma unroll
            for (int nt = 0; nt < 8; nt++) {
                const int rl = wm * 32 + mt * 16 + (lane >> 2);
                const int cl = wn * 64 + nt * 8 + (lane & 3) * 2;
                float bb0 = sBias[cl], bb1 = sBias[cl + 1];
                float v0 = 1.0f / (1.0f + expf(-(acc[mt][nt][0] + bb0)));
                float v1 = 1.0f / (1.0f + expf(-(acc[mt][nt][1] + bb1)));
                float v2 = 1.0f / (1.0f + expf(-(acc[mt][nt][2] + bb0)));
                float v3 = 1.0f / (1.0f + expf(-(acc[mt][nt][3] + bb1)));
                gb[rl * 128 + cl] = v0;       gb[rl * 128 + cl + 1] = v1;
                gb[(rl + 8) * 128 + cl] = v2; gb[(rl + 8) * 128 + cl + 1] = v3;
            }
        }
        __syncthreads();
        if (tid < 128) {
            float s = 0.f;
            #pragma unroll 8
            for (int r = 0; r < 64; r++) s += gb[r * 128 + tid];
            Cf[bx * 128 + tid] = s * (1.0f / 64.0f);
        }
        return;
    }

    #pragma unroll
    for (int mt = 0; mt < 2; mt++) {
        #pragma unroll
        for (int nt = 0; nt < 8; nt++) {
            const int r0 = by * 128 + wm * 32 + mt * 16 + (lane >> 2);
            const int cb = wn * 64 + nt * 8 + (lane & 3) * 2;
            const int cg = bx * 128 + cb;
            float v0 = acc[mt][nt][0], v1 = acc[mt][nt][1];
            float v2 = acc[mt][nt][2], v3 = acc[mt][nt][3];
            if (BIAS) {
                float bb0 = sBias[cb], bb1 = sBias[cb + 1];
                v0 += bb0; v1 += bb1; v2 += bb0; v3 += bb1;
            }
            if (OUT_MODE == 1) {
                v0 = fmaxf(v0, 0.f); v1 = fmaxf(v1, 0.f);
                v2 = fmaxf(v2, 0.f); v3 = fmaxf(v3, 0.f);
            }
            *(float2*)(Cf + (size_t)r0 * Nn + cg)       = make_float2(v0, v1);
            *(float2*)(Cf + (size_t)(r0 + 8) * Nn + cg) = make_float2(v2, v3);
        }
    }
}

// ---------------- fp16 single-pass GEMM: C = A @ Bh^T + bias -> fp16, 3-stage, 2 CTAs/SM ----------------
#define FTILE_B 16384
#define FSTAGE_B (2 * FTILE_B)
#define FGEMM_SMEM (1024 + 3 * FSTAGE_B)

__global__ __launch_bounds__(256, 2) void fgemm(
    const __half* __restrict__ A,
    const __half* __restrict__ Bh,
    const float* __restrict__ bias,
    __half* __restrict__ Ch, int M, int Nn, int K)
{
    extern __shared__ __align__(1024) char smem[];
    uint32_t sb = smem_u32(smem);
    const int tid = threadIdx.x;
    const int wid = tid >> 5, lane = tid & 31;
    const int wm = wid >> 1, wn = wid & 1;
    const int bx = blockIdx.x, by = blockIdx.y;

    float* sBias = (float*)(smem + 512);
    if (tid < 128) sBias[tid] = bias[bx * 128 + tid];

    const uint32_t T0 = sb + 1024;
    const int NK = K >> 6;
    const int arow0 = by * 128, brow0 = bx * 128;

    float acc[2][8][4];
    #pragma unroll
    for (int i = 0; i < 2; i++)
        #pragma unroll
        for (int j = 0; j < 8; j++)
            #pragma unroll
            for (int l = 0; l < 4; l++) acc[i][j][l] = 0.f;

    const int mi = lane >> 3, li = lane & 7;
    const int rowoff = (mi & 1) * 8 + li;
    const int coloff = (mi >> 1) * 16;

    // prologue: stages 0,1
    #pragma unroll
    for (int s = 0; s < 2; s++) {
        uint32_t st = T0 + s * FSTAGE_B;
        ld_tile(st,           A,  arow0, K, s, tid);
        ld_tile(st + FTILE_B, Bh, brow0, K, s, tid);
        CP_COMMIT();
    }

    for (int kc = 0; kc < NK; kc++) {
        if (kc == NK - 1) asm volatile("cp.async.wait_group 0;" ::: "memory");
        else              asm volatile("cp.async.wait_group 1;" ::: "memory");
        __syncthreads();

        if (kc + 2 < NK) {
            uint32_t st = T0 + ((kc + 2) % 3) * FSTAGE_B;
            ld_tile(st,           A,  arow0, K, kc + 2, tid);
            ld_tile(st + FTILE_B, Bh, brow0, K, kc + 2, tid);
            CP_COMMIT();
        }

        const uint32_t Sa = T0 + (kc % 3) * FSTAGE_B;
        const uint32_t Sh = Sa + FTILE_B;

        #pragma unroll
        for (int ks = 0; ks < 4; ks++) {
            const int kb = ks * 32;
            uint32_t a[2][4];
            #pragma unroll
            for (int mt = 0; mt < 2; mt++) {
                uint32_t ra = swz((uint32_t)(wm * 32 + mt * 16 + rowoff) * 128 + kb + coloff);
                ldsm4(a[mt], Sa + ra);
            }
            #pragma unroll
            for (int g = 0; g < 4; g++) {
                uint32_t rb = swz((uint32_t)(wn * 64 + g * 16 + rowoff) * 128 + kb + coloff);
                uint32_t bh[4];
                ldsm4(bh, Sh + rb);
                #pragma unroll
                for (int mt = 0; mt < 2; mt++) {
                    #pragma unroll
                    for (int sub = 0; sub < 2; sub++) {
                        mma_fp(acc[mt][g * 2 + sub], a[mt], bh[sub], bh[2 + sub]);
                    }
                }
            }
        }
    }

    #pragma unroll
    for (int mt = 0; mt < 2; mt++) {
        #pragma unroll
        for (int nt = 0; nt < 8; nt++) {
            const int r0 = by * 128 + wm * 32 + mt * 16 + (lane >> 2);
            const int cb = wn * 64 + nt * 8 + (lane & 3) * 2;
            const int cg = bx * 128 + cb;
            float bb0 = sBias[cb], bb1 = sBias[cb + 1];
            __half h0 = __float2half(acc[mt][nt][0] + bb0);
            __half h1 = __float2half(acc[mt][nt][1] + bb1);
            __half h2 = __float2half(acc[mt][nt][2] + bb0);
            __half h3 = __float2half(acc[mt][nt][3] + bb1);
            *(uint32_t*)(Ch + (size_t)r0 * Nn + cg)       = ((uint32_t)hfbits(h1) << 16) | hfbits(h0);
            *(uint32_t*)(Ch + (size_t)(r0 + 8) * Nn + cg) = ((uint32_t)hfbits(h3) << 16) | hfbits(h2);
        }
    }
}

// ---------------- small kernels ----------------
// fused: h_time -> fp16 + h_gate mean + bf16 split; rows >= 64 zero-padded
__global__ __launch_bounds__(256) void k_pre(const float* __restrict__ h) {
    int b = blockIdx.y;
    int hh = blockIdx.x * 256 + threadIdx.x;
    if (b >= 64) {
        g_hgHi[b * H_ + hh] = __float2bfloat16(0.f);
        g_hgLo[b * H_ + hh] = __float2bfloat16(0.f);
        return;
    }
    const float* p = h + (size_t)b * T_ * H_ + hh;
    __half* q = g_hA16 + (size_t)b * T_ * H_ + hh;
    float s = 0.f;
    #pragma unroll 4
    for (int t = 0; t < T_; t++) {
        float v = p[(size_t)t * H_];
        q[(size_t)t * H_] = __float2half(v);
        s += v;
    }
    float mean = s * (1.0f / T_);
    g_hgate[b * H_ + hh] = mean;
    bf16 hi = __float2bfloat16(mean);
    g_hgHi[b * H_ + hh] = hi;
    g_hgLo[b * H_ + hh] = __float2bfloat16(mean - __bfloat162float(hi));
}

__global__ void k_meanB() {
    int hh = blockIdx.x * blockDim.x + threadIdx.x;
    if (hh >= H_) return;
    float s = 0.f;
    #pragma unroll
    for (int b = 0; b < B_; b++) s += g_hgate[b * H_ + hh];
    g_hmean[hh] = s * (1.0f / B_);
}

__global__ __launch_bounds__(256) void k_enorm(const float* __restrict__ E_dyn) {
    int i = blockIdx.x;
    __shared__ float red[256];
    float vals[4];
    float ss = 0.f;
    #pragma unroll
    for (int j = 0; j < 4; j++) {
        int hh = threadIdx.x + j * 256;
        float v = E_dyn[i * H_ + hh] + g_hmean[hh];
        vals[j] = v; ss += v * v;
    }
    red[threadIdx.x] = ss; __syncthreads();
    for (int off = 128; off > 0; off >>= 1) {
        if (threadIdx.x < off) red[threadIdx.x] += red[threadIdx.x + off];
        __syncthreads();
    }
    float inv = 1.0f / fmaxf(sqrtf(red[0]), 1e-12f);
    #pragma unroll
    for (int j = 0; j < 4; j++) {
        int hh = threadIdx.x + j * 256;
        float v = vals[j] * inv;
        bf16 h = __float2bfloat16(v);
        g_Ehi[i * H_ + hh] = h;
        g_Elo[i * H_ + hh] = __float2bfloat16(v - __bfloat162float(h));
    }
}

__global__ __launch_bounds__(256) void k_rowsum() {
    int i = blockIdx.x;
    __shared__ float red[256];
    float s = 0.f;
    for (int j = threadIdx.x; j < N_; j += 256) s += g_S[i * N_ + j];
    red[threadIdx.x] = s; __syncthreads();
    for (int off = 128; off > 0; off >>= 1) {
        if (threadIdx.x < off) red[threadIdx.x] += red[threadIdx.x + off];
        __syncthreads();
    }
    if (threadIdx.x == 0) g_rowsum[i] = red[0];
}

// gate1 split-K combine: v = sum of 4 partials + b1 -> gelu -> bf16 hi
__global__ void k_combG(const float* __restrict__ b1) {
    int i = blockIdx.x * blockDim.x + threadIdx.x;
    if (i >= 128 * HID_) return;
    int n = i & (HID_ - 1);
    float v = g_zb[i] + g_zb[128*HID_ + i] + g_zb[2*128*HID_ + i] + g_zb[3*128*HID_ + i] + b1[n];
    v = 0.5f * v * (1.0f + erff(v * 0.70710678118654752f));
    g_hidh[i] = __float2bfloat16(v);
}

// A_mix tiled (coalesced transpose via smem): Amix[m][n] = (a*Ap + (1-a)*0.5*(R[m][n]+R[n][m]))*gmean[m]
__global__ __launch_bounds__(256) void k_amix(const float* __restrict__ Ap,
                                              const float* __restrict__ alpha_raw) {
    __shared__ float sT[32][33];
    int n0 = blockIdx.x * 32, m0 = blockIdx.y * 32;
    int tx = threadIdx.x, ty = threadIdx.y;
    float alpha = 1.0f / (1.0f + expf(-alpha_raw[0]));
    #pragma unroll
    for (int i = 0; i < 4; i++) {
        int n = n0 + ty + i * 8;
        sT[ty + i * 8][tx] = g_S[(size_t)n * N_ + m0 + tx] / (g_rowsum[n] + 1e-6f);
    }
    __syncthreads();
    #pragma unroll
    for (int i = 0; i < 4; i++) {
        int m = m0 + ty + i * 8;
        int n = n0 + tx;
        size_t idx = (size_t)m * N_ + n;
        float r  = g_S[idx] / (g_rowsum[m] + 1e-6f);
        float rt = sT[tx][ty + i * 8];
        float v = (alpha * Ap[idx] + (1.0f - alpha) * 0.5f * (r + rt)) * g_gmean[m];
        bf16 h = __float2bfloat16(v);
        g_Amh[idx] = h;
        g_Aml[idx] = __float2bfloat16(v - __bfloat162float(h));
    }
}

__global__ void k_split(const float* __restrict__ x, bf16* __restrict__ hi, bf16* __restrict__ lo, int n4) {
    for (int i = blockIdx.x * blockDim.x + threadIdx.x; i < n4; i += gridDim.x * blockDim.x) {
        float4 v = ((const float4*)x)[i];
        bf16 h0 = __float2bfloat16(v.x), h1 = __float2bfloat16(v.y);
        bf16 h2 = __float2bfloat16(v.z), h3 = __float2bfloat16(v.w);
        bf16 l0 = __float2bfloat16(v.x - __bfloat162float(h0));
        bf16 l1 = __float2bfloat16(v.y - __bfloat162float(h1));
        bf16 l2 = __float2bfloat16(v.z - __bfloat162float(h2));
        bf16 l3 = __float2bfloat16(v.w - __bfloat162float(h3));
        uint2 hv, lv;
        hv.x = ((uint32_t)bfbits(h1) << 16) | bfbits(h0);
        hv.y = ((uint32_t)bfbits(h3) << 16) | bfbits(h2);
        lv.x = ((uint32_t)bfbits(l1) << 16) | bfbits(l0);
        lv.y = ((uint32_t)bfbits(l3) << 16) | bfbits(l2);
        ((uint2*)hi)[i] = hv;
        ((uint2*)lo)[i] = lv;
    }
}

__global__ void k_tsplit(const float* __restrict__ W, bf16* __restrict__ Oh, bf16* __restrict__ Ol,
                         int Rin, int Cin) {
    __shared__ float t[32][33];
    int c0 = blockIdx.x * 32, r0 = blockIdx.y * 32;
    #pragma unroll
    for (int i = 0; i < 4; i++)
        t[threadIdx.y + i * 8][threadIdx.x] = W[(size_t)(r0 + threadIdx.y + i * 8) * Cin + c0 + threadIdx.x];
    __syncthreads();
    #pragma unroll
    for (int i = 0; i < 4; i++) {
        int oc = threadIdx.y + i * 8;
        float v = t[threadIdx.x][oc];
        size_t o = (size_t)(c0 + oc) * Rin + r0 + threadIdx.x;
        bf16 h = __float2bfloat16(v);
        Oh[o] = h;
        Ol[o] = __float2bfloat16(v - __bfloat162float(h));
    }
}

// combine split-K partials -> bf16 hi/lo (P)
__global__ void k_combP() {
    int i = blockIdx.x * blockDim.x + threadIdx.x;
    if (i >= N_*H_) return;
    float v = g_zb[i] + g_zb[(size_t)N_*H_ + i];
    bf16 h = __float2bfloat16(v);
    g_Ph[i] = h;
    g_Pl[i] = __float2bfloat16(v - __bfloat162float(h));
}

// combine split-K partials -> fp16 (Mcomb)
__global__ void k_combM() {
    int i = blockIdx.x * blockDim.x + threadIdx.x;
    if (i >= H_*H_) return;
    g_M16h[i] = __float2half(g_zb[i] + g_zb[(size_t)N_*H_ + i]);
}

// u[m] = sum_n A_mix[m][n] * b1[n]  (hi+lo reconstruct)
__global__ __launch_bounds__(256) void k_bias_u(const float* __restrict__ b1) {
    int m = blockIdx.x;
    __shared__ float red[256];
    float s = 0.f;
    for (int n = threadIdx.x; n < N_; n += 256) {
        size_t idx = (size_t)m * N_ + n;
        s += (__bfloat162float(g_Amh[idx]) + __bfloat162float(g_Aml[idx])) * b1[n];
    }
    red[threadIdx.x] = s; __syncthreads();
    for (int off = 128; off > 0; off >>= 1) {
        if (threadIdx.x < off) red[threadIdx.x] += red[threadIdx.x + off];
        __syncthreads();
    }
    if (threadIdx.x == 0) g_u[m] = red[0];
}

// cvec[h] = sum_m u[m] * W2t[h][m] + b2[h]
__global__ __launch_bounds__(256) void k_bias_c(const float* __restrict__ b2) {
    int h = blockIdx.x;
    __shared__ float red[256];
    float s = 0.f;
    for (int m = threadIdx.x; m < N_; m += 256)
        s += g_u[m] * (__bfloat162float(g_W2th[(size_t)h * N_ + m]) +
                       __bfloat162float(g_W2tl[(size_t)h * N_ + m]));
    red[threadIdx.x] = s; __syncthreads();
    for (int off = 128; off > 0; off >>= 1) {
        if (threadIdx.x < off) red[threadIdx.x] += red[threadIdx.x + off];
        __syncthreads();
    }
    if (threadIdx.x == 0) g_cvec[h] = red[0] + b2[h];
}

// y = hA16*(1+tanh(1/N)) + msg16 -> LayerNorm  (fp16 inputs, fp32 math/out)
__global__ __launch_bounds__(256) void k_final(const float* __restrict__ lw,
                                               const float* __restrict__ lb,
                                               float* __restrict__ out) {
    int row = blockIdx.x;
    size_t base = (size_t)row * H_ + threadIdx.x * 4;
    const float gw = 1.0f + tanhf(1.0f / 1024.0f);
    uint2 ha = *(const uint2*)(g_hA16 + base);
    uint2 ma = *(const uint2*)(g_msg16 + base);
    __half2 h01 = *reinterpret_cast<__half2*>(&ha.x);
    __half2 h23 = *reinterpret_cast<__half2*>(&ha.y);
    __half2 m01 = *reinterpret_cast<__half2*>(&ma.x);
    __half2 m23 = *reinterpret_cast<__half2*>(&ma.y);
    float v0 = __low2float(h01) * gw + __low2float(m01);
    float v1 = __high2float(h01) * gw + __high2float(m01);
    float v2 = __low2float(h23) * gw + __low2float(m23);
    float v3 = __high2float(h23) * gw + __high2float(m23);

    __shared__ float red[256];
    red[threadIdx.x] = v0 + v1 + v2 + v3;
    __syncthreads();
    for (int off = 128; off > 0; off >>= 1) {
        if (threadIdx.x < off) red[threadIdx.x] += red[threadIdx.x + off];
        __syncthreads();
    }
    float mu = red[0] * (1.0f / H_);
    __syncthreads();
    float d0 = v0 - mu, d1 = v1 - mu, d2 = v2 - mu, d3 = v3 - mu;
    red[threadIdx.x] = d0 * d0 + d1 * d1 + d2 * d2 + d3 * d3;
    __syncthreads();
    for (int off = 128; off > 0; off >>= 1) {
        if (threadIdx.x < off) red[threadIdx.x] += red[threadIdx.x + off];
        __syncthreads();
    }
    float rstd = rsqrtf(red[0] * (1.0f / H_) + 1e-5f);
    float4 w = *(const float4*)(lw + threadIdx.x * 4);
    float4 bb = *(const float4*)(lb + threadIdx.x * 4);
    float4 o;
    o.x = d0 * rstd * w.x + bb.x;
    o.y = d1 * rstd * w.y + bb.y;
    o.z = d2 * rstd * w.z + bb.z;
    o.w = d3 * rstd * w.w + bb.w;
    *(float4*)(out + base) = o;
}

// ---------------- launcher ----------------
extern "C" void kernel_launch(void* const* d_in, const int* in_sizes, int n_in,
                              void* d_out, int out_size) {
    const float* h_time    = (const float*)d_in[0];
    const float* A_pearson = (const float*)d_in[1];
    const float* E_dyn     = (const float*)d_in[2];
    const float* alpha_raw = (const float*)d_in[3];
    // d_in[4] = tau_raw : analytically eliminated (mean over softmax axis == 1/N)
    const float* gate_W1   = (const float*)d_in[5];
    const float* gate_b1   = (const float*)d_in[6];
    const float* gate_W2   = (const float*)d_in[7];
    const float* gate_b2   = (const float*)d_in[8];
    const float* h2n_W     = (const float*)d_in[9];
    const float* h2n_b     = (const float*)d_in[10];
    const float* n2h_W     = (const float*)d_in[11];
    const float* n2h_b     = (const float*)d_in[12];
    const float* ln_w      = (const float*)d_in[13];
    const float* ln_b      = (const float*)d_in[14];
    float* out = (float*)d_out;

    bf16 *p_Ehi, *p_Elo, *p_Amh, *p_Aml, *p_W1h, *p_W1l, *p_W2th, *p_W2tl;
    bf16 *p_Ph, *p_Pl, *p_hgHi, *p_hgLo, *p_G1h, *p_G1l, *p_G2h, *p_G2l, *p_hidh;
    __half *p_hA16, *p_M16h, *p_msg16;
    float *p_S, *p_cvec, *p_gmean, *p_zb;
    cudaGetSymbolAddress((void**)&p_Ehi, g_Ehi);   cudaGetSymbolAddress((void**)&p_Elo, g_Elo);
    cudaGetSymbolAddress((void**)&p_Amh, g_Amh);   cudaGetSymbolAddress((void**)&p_Aml, g_Aml);
    cudaGetSymbolAddress((void**)&p_W1h, g_W1h);   cudaGetSymbolAddress((void**)&p_W1l, g_W1l);
    cudaGetSymbolAddress((void**)&p_W2th, g_W2th); cudaGetSymbolAddress((void**)&p_W2tl, g_W2tl);
    cudaGetSymbolAddress((void**)&p_Ph, g_Ph);     cudaGetSymbolAddress((void**)&p_Pl, g_Pl);
    cudaGetSymbolAddress((void**)&p_hgHi, g_hgHi); cudaGetSymbolAddress((void**)&p_hgLo, g_hgLo);
    cudaGetSymbolAddress((void**)&p_G1h, g_G1h);   cudaGetSymbolAddress((void**)&p_G1l, g_G1l);
    cudaGetSymbolAddress((void**)&p_G2h, g_G2h);   cudaGetSymbolAddress((void**)&p_G2l, g_G2l);
    cudaGetSymbolAddress((void**)&p_hidh, g_hidh);
    cudaGetSymbolAddress((void**)&p_hA16, g_hA16);
    cudaGetSymbolAddress((void**)&p_M16h, g_M16h); cudaGetSymbolAddress((void**)&p_msg16, g_msg16);
    cudaGetSymbolAddress((void**)&p_S, g_S);
    cudaGetSymbolAddress((void**)&p_cvec, g_cvec); cudaGetSymbolAddress((void**)&p_gmean, g_gmean);
    cudaGetSymbolAddress((void**)&p_zb, g_zb);

    cudaFuncSetAttribute(hgemm<1, 0, 1>, cudaFuncAttributeMaxDynamicSharedMemorySize, GEMM_SMEM);
    cudaFuncSetAttribute(hgemm<0, 0, 1>, cudaFuncAttributeMaxDynamicSharedMemorySize, GEMM_SMEM);
    cudaFuncSetAttribute(hgemm<7, 1, 1>, cudaFuncAttributeMaxDynamicSharedMemorySize, GEMM_SMEM);
    cudaFuncSetAttribute(hgemm<0, 0, 3>, cudaFuncAttributeMaxDynamicSharedMemorySize, GEMM_SMEM);
    cudaFuncSetAttribute(fgemm, cudaFuncAttributeMaxDynamicSharedMemorySize, FGEMM_SMEM);

    // fused reductions + fp16 convert (+pad); weight prep
    k_pre<<<dim3(4, 128), 256>>>(h_time);
    k_meanB<<<(H_ + 255) / 256, 256>>>();
    k_enorm<<<N_, 256>>>(E_dyn);
    k_split<<<512, 256>>>(h2n_W, p_W1h, p_W1l, H_*N_ / 4);
    {
        dim3 b(32, 8);
        k_tsplit<<<dim3(H_ / 32, N_ / 32), b>>>(n2h_W, p_W2th, p_W2tl, N_, H_);     // [N,H]->[H,N]
        k_tsplit<<<dim3(HID_ / 32, H_ / 32), b>>>(gate_W1, p_G1h, p_G1l, H_, HID_); // [H,HID]->[HID,H]
        k_tsplit<<<dim3(N_ / 32, HID_ / 32), b>>>(gate_W2, p_G2h, p_G2l, HID_, N_); // [HID,N]->[N,HID]
    }

    // S = relu(E_cur @ E_cur^T) — single-pass bf16 (error diluted into tiny A_dyn)
    hgemm<1, 0, 1><<<dim3(N_ / 128, N_ / 128), 256, GEMM_SMEM>>>(
        p_Ehi, nullptr, p_Ehi, nullptr, nullptr, p_S, nullptr, nullptr, N_, N_, H_);
    k_rowsum<<<N_, 256>>>();

    // gate MLP — gate1 split-K=4 (16 CTAs), combine+gelu; gate2 fuses sigmoid+column-mean
    hgemm<0, 0, 1><<<dim3(HID_ / 128, 1, 4), 256, GEMM_SMEM>>>(
        p_hgHi, nullptr, p_G1h, nullptr, nullptr, p_zb, nullptr, nullptr, 128, HID_, H_);
    k_combG<<<(128 * HID_ + 255) / 256, 256>>>(gate_b1);
    hgemm<7, 1, 1><<<dim3(N_ / 128, 1), 256, GEMM_SMEM>>>(
        p_hidh, nullptr, p_G2h, nullptr, gate_b2, p_gmean, nullptr, nullptr, 128, N_, HID_);

    // Amix (tiled, coalesced)
    {
        dim3 b(32, 8);
        k_amix<<<dim3(N_ / 32, N_ / 32), b>>>(A_pearson, alpha_raw);
    }

    // P = W1 @ AmixT (3-pass bf16, split-K=2) -> combine -> split bf16
    hgemm<0, 0, 3><<<dim3(N_ / 128, H_ / 128, 2), 256, GEMM_SMEM>>>(
        p_W1h, p_W1l, p_Amh, p_Aml, nullptr, p_zb, nullptr, nullptr, H_, N_, N_);
    k_combP<<<(N_*H_ + 255) / 256, 256>>>();

    // McombT = W2t @ P^T (3-pass bf16, split-K=2) -> combine -> fp16
    hgemm<0, 0, 3><<<dim3(H_ / 128, H_ / 128, 2), 256, GEMM_SMEM>>>(
        p_W2th, p_W2tl, p_Ph, p_Pl, nullptr, p_zb, nullptr, nullptr, H_, H_, N_);
    k_combM<<<(H_*H_ + 255) / 256, 256>>>();

    // bias fold: cvec = b1 @ AmixT @ W2 + b2
    k_bias_u<<<N_, 256>>>(h2n_b);
    k_bias_c<<<H_, 256>>>(n2h_b);

    // THE big GEMM: msg = h_time @ Mcomb + cvec  (fp16 x fp16, single pass, fp16 out)
    fgemm<<<dim3(H_ / 128, BT_ / 128), 256, FGEMM_SMEM>>>(
        p_hA16, p_M16h, p_cvec, p_msg16, BT_, H_, H_);

    // fused residual + LayerNorm (fp16 inputs)
    k_final<<<BT_, 256>>>(ln_w, ln_b, out);
}

// round 8
// speedup vs baseline: 6.3013x; 1.0571x over previous
#include <cuda_runtime.h>
#include <cuda_bf16.h>
#include <cuda_fp16.h>
#include <math.h>
#include <stdint.h>

#define N_ 1024
#define H_ 1024
#define B_ 64
#define T_ 256
#define BT_ (B_*T_)
#define HID_ 512

typedef __nv_bfloat16 bf16;

// ---------------- scratch (static device globals; no allocation) ----------------
__device__ __half g_hA16[BT_*H_];                  // h_time fp16
__device__ float g_hgate[B_*H_];
__device__ bf16  g_hgHi[128*H_];                   // h_gate bf16, padded to 128 rows
__device__ float g_hmean[H_];
__device__ bf16  g_Ehi[N_*H_];
__device__ float g_S[N_*N_];
__device__ float g_rowsum[N_];                     // stores 1/(rowsum+1e-6)
__device__ bf16  g_G1h[HID_*H_];                   // gate_W1^T bf16
__device__ bf16  g_G2h[N_*HID_];                   // gate_W2^T bf16
__device__ bf16  g_hidh[128*HID_];
__device__ float g_gmean[N_];
__device__ __half g_Am16h[N_*N_], g_Am16l[N_*N_];  // A_mix fp16 hi/lo
__device__ __half g_W116[H_*N_];                   // h2n_W fp16
__device__ __half g_W2t16[H_*N_];                  // n2h_W^T fp16
__device__ __half g_P16h[H_*N_], g_P16l[H_*N_];    // P fp16 hi/lo
__device__ __half g_M16h[H_*H_];                   // McombT fp16
__device__ float g_zb[2*(size_t)N_*H_];            // split-K partials
__device__ float g_u[N_];
__device__ float g_cvec[H_];
__device__ __half g_msg16[BT_*H_];

// ---------------- helpers ----------------
__device__ __forceinline__ unsigned short bfbits(bf16 x) {
    return *reinterpret_cast<unsigned short*>(&x);
}
__device__ __forceinline__ unsigned short hfbits(__half x) {
    return *reinterpret_cast<unsigned short*>(&x);
}
__device__ __forceinline__ uint32_t smem_u32(const void* p) {
    uint32_t a;
    asm("{ .reg .u64 t; cvta.to.shared.u64 t, %1; cvt.u32.u64 %0, t; }" : "=r"(a) : "l"(p));
    return a;
}
__device__ __forceinline__ uint32_t swz(uint32_t off) {
    return off ^ ((off >> 3) & 0x70);
}
#define CP_COMMIT() asm volatile("cp.async.commit_group;" ::: "memory")

__device__ __forceinline__ void ldsm4(uint32_t (&r)[4], uint32_t addr) {
    asm volatile("ldmatrix.sync.aligned.m8n8.x4.shared.b16 {%0,%1,%2,%3}, [%4];"
        : "=r"(r[0]), "=r"(r[1]), "=r"(r[2]), "=r"(r[3]) : "r"(addr));
}
__device__ __forceinline__ void mma_bf(float* c, const uint32_t* a, uint32_t b0, uint32_t b1) {
    asm volatile("mma.sync.aligned.m16n8k16.row.col.f32.bf16.bf16.f32 "
        "{%0,%1,%2,%3}, {%4,%5,%6,%7}, {%8,%9}, {%0,%1,%2,%3};"
        : "+f"(c[0]), "+f"(c[1]), "+f"(c[2]), "+f"(c[3])
        : "r"(a[0]), "r"(a[1]), "r"(a[2]), "r"(a[3]), "r"(b0), "r"(b1));
}
__device__ __forceinline__ void mma_fp(float* c, const uint32_t* a, uint32_t b0, uint32_t b1) {
    asm volatile("mma.sync.aligned.m16n8k16.row.col.f32.f16.f16.f32 "
        "{%0,%1,%2,%3}, {%4,%5,%6,%7}, {%8,%9}, {%0,%1,%2,%3};"
        : "+f"(c[0]), "+f"(c[1]), "+f"(c[2]), "+f"(c[3])
        : "r"(a[0]), "r"(a[1]), "r"(a[2]), "r"(a[3]), "r"(b0), "r"(b1));
}

// load one 128row x 64col 16-bit tile (SW128 swizzled, 128B/row); 256 threads
__device__ __forceinline__ void ld_tile(uint32_t sdst, const void* __restrict__ g,
                                        int row0, int K, int kc, int tid) {
    const int row = tid >> 1, half = tid & 1;
    const char* src = (const char*)g + (((size_t)(row0 + row) * K + (kc << 6)) << 1) + half * 64;
    uint32_t rb = (uint32_t)row * 128 + (uint32_t)half * 64;
    #pragma unroll
    for (int j = 0; j < 4; j++) {
        uint32_t sw = swz(rb + (j << 4));
        asm volatile("cp.async.cg.shared.global [%0], [%1], 16;"
            :: "r"(sdst + sw), "l"(src + (j << 4)));
    }
}

// ---------------- HMMA GEMM (TN): C[M,Nn] = op(A) @ op(B)^T
// DT: 0 bf16, 1 fp16.  PASSES: 1 = Ah*Bh; 2 = Ah*(Bh+Bl); 3 = (Ah+Al)(Bh+Bl) minus lolo.
// OUT_MODE: 0 f32 (z-split aware); 1 f32 relu (+SYM transpose mirror); 7 sigmoid->colmean rows0..63.
#define TILE_B 16384
#define BUF_B  65536
#define GEMM_SMEM (1024 + 2 * BUF_B)

template<int DT, int PASSES, int OUT_MODE, int BIAS, int SYM>
__global__ __launch_bounds__(256, 1) void hgemm(
    const void* __restrict__ Ahi, const void* __restrict__ Alo,
    const void* __restrict__ Bhi, const void* __restrict__ Blo,
    const float* __restrict__ bias,
    float* __restrict__ Cf, int M, int Nn, int K)
{
    extern __shared__ __align__(1024) char smem[];
    uint32_t sb = smem_u32(smem);
    const int tid = threadIdx.x;
    const int wid = tid >> 5, lane = tid & 31;
    const int wm = wid >> 1, wn = wid & 1;
    int bx, by;
    if (SYM) {
        int t = blockIdx.x, i = 0;
        while (t >= 8 - i) { t -= 8 - i; i++; }
        by = i; bx = i + t;
    } else { bx = blockIdx.x; by = blockIdx.y; }
    const int bz = blockIdx.z;

    float* sBias = (float*)(smem + 512);
    if (BIAS && tid < 128) sBias[tid] = bias[bx * 128 + tid];

    const uint32_t T0 = sb + 1024;
    const int NKtot = K >> 6;
    const int NKp = NKtot / (int)gridDim.z;
    const int kc0 = bz * NKp;
    if (OUT_MODE == 0 && gridDim.z > 1) Cf += (size_t)bz * M * Nn;

    const int arow0 = by * 128, brow0 = bx * 128;

    float acc[2][8][4];
    #pragma unroll
    for (int i = 0; i < 2; i++)
        #pragma unroll
        for (int j = 0; j < 8; j++)
            #pragma unroll
            for (int l = 0; l < 4; l++) acc[i][j][l] = 0.f;

    const int mi = lane >> 3, li = lane & 7;
    const int rowoff = (mi & 1) * 8 + li;
    const int coloff = (mi >> 1) * 16;

    ld_tile(T0, Ahi, arow0, K, kc0, tid);
    if (PASSES == 3) ld_tile(T0 + TILE_B, Alo, arow0, K, kc0, tid);
    ld_tile(T0 + 2 * TILE_B, Bhi, brow0, K, kc0, tid);
    if (PASSES >= 2) ld_tile(T0 + 3 * TILE_B, Blo, brow0, K, kc0, tid);
    CP_COMMIT();

    for (int i = 0; i < NKp; i++) {
        const int cur = i & 1;
        if (i + 1 < NKp) {
            uint32_t nb = T0 + (cur ^ 1) * BUF_B;
            ld_tile(nb, Ahi, arow0, K, kc0 + i + 1, tid);
            if (PASSES == 3) ld_tile(nb + TILE_B, Alo, arow0, K, kc0 + i + 1, tid);
            ld_tile(nb + 2 * TILE_B, Bhi, brow0, K, kc0 + i + 1, tid);
            if (PASSES >= 2) ld_tile(nb + 3 * TILE_B, Blo, brow0, K, kc0 + i + 1, tid);
            CP_COMMIT();
            asm volatile("cp.async.wait_group 1;" ::: "memory");
        } else {
            asm volatile("cp.async.wait_group 0;" ::: "memory");
        }
        __syncthreads();

        const uint32_t Ah = T0 + cur * BUF_B;
        const uint32_t Al = Ah + TILE_B;
        const uint32_t Bh = Ah + 2 * TILE_B;
        const uint32_t Bl = Ah + 3 * TILE_B;

        #pragma unroll
        for (int ks = 0; ks < 4; ks++) {
            const int kb = ks * 32;
            uint32_t ahi[2][4], alo[2][4];
            #pragma unroll
            for (int mt = 0; mt < 2; mt++) {
                uint32_t ra = swz((uint32_t)(wm * 32 + mt * 16 + rowoff) * 128 + kb + coloff);
                ldsm4(ahi[mt], Ah + ra);
                if (PASSES == 3) ldsm4(alo[mt], Al + ra);
            }
            #pragma unroll
            for (int g = 0; g < 4; g++) {
                uint32_t rb = swz((uint32_t)(wn * 64 + g * 16 + rowoff) * 128 + kb + coloff);
                uint32_t bh[4], bl[4];
                ldsm4(bh, Bh + rb);
                if (PASSES >= 2) ldsm4(bl, Bl + rb);
                #pragma unroll
                for (int mt = 0; mt < 2; mt++) {
                    #pragma unroll
                    for (int sub = 0; sub < 2; sub++) {
                        float* c = acc[mt][g * 2 + sub];
                        if (DT == 0) mma_bf(c, ahi[mt], bh[sub], bh[2 + sub]);
                        else         mma_fp(c, ahi[mt], bh[sub], bh[2 + sub]);
                        if (PASSES >= 2) {
                            if (DT == 0) mma_bf(c, ahi[mt], bl[sub], bl[2 + sub]);
                            else         mma_fp(c, ahi[mt], bl[sub], bl[2 + sub]);
                        }
                        if (PASSES == 3) {
                            if (DT == 0) mma_bf(c, alo[mt], bh[sub], bh[2 + sub]);
                            else         mma_fp(c, alo[mt], bh[sub], bh[2 + sub]);
                        }
                    }
                }
            }
        }
        __syncthreads();
    }

    if (OUT_MODE == 7) {
        float* gb = (float*)(smem + 1024);
        #pragma unroll
        for (int mt = 0; mt < 2; mt++) {
            #pragma unroll
            for (int nt = 0; nt < 8; nt++) {
                const int rl = wm * 32 + mt * 16 + (lane >> 2);
                const int cl = wn * 64 + nt * 8 + (lane & 3) * 2;
                float bb0 = sBias[cl], bb1 = sBias[cl + 1];
                gb[rl * 128 + cl]           = 1.0f / (1.0f + expf(-(acc[mt][nt][0] + bb0)));
                gb[rl * 128 + cl + 1]       = 1.0f / (1.0f + expf(-(acc[mt][nt][1] + bb1)));
                gb[(rl + 8) * 128 + cl]     = 1.0f / (1.0f + expf(-(acc[mt][nt][2] + bb0)));
                gb[(rl + 8) * 128 + cl + 1] = 1.0f / (1.0f + expf(-(acc[mt][nt][3] + bb1)));
            }
        }
        __syncthreads();
        if (tid < 128) {
            float s = 0.f;
            #pragma unroll 8
            for (int r = 0; r < 64; r++) s += gb[r * 128 + tid];
            Cf[bx * 128 + tid] = s * (1.0f / 64.0f);
        }
        return;
    }

    float* sT = (float*)(smem + 1024);   // [128][132] transpose staging (SYM only)
    #pragma unroll
    for (int mt = 0; mt < 2; mt++) {
        #pragma unroll
        for (int nt = 0; nt < 8; nt++) {
            const int rl = wm * 32 + mt * 16 + (lane >> 2);
            const int cl = wn * 64 + nt * 8 + (lane & 3) * 2;
            const int r0 = by * 128 + rl;
            const int cg = bx * 128 + cl;
            float v0 = acc[mt][nt][0], v1 = acc[mt][nt][1];
            float v2 = acc[mt][nt][2], v3 = acc[mt][nt][3];
            if (BIAS) {
                float bb0 = sBias[cl], bb1 = sBias[cl + 1];
                v0 += bb0; v1 += bb1; v2 += bb0; v3 += bb1;
            }
            if (OUT_MODE == 1) {
                v0 = fmaxf(v0, 0.f); v1 = fmaxf(v1, 0.f);
                v2 = fmaxf(v2, 0.f); v3 = fmaxf(v3, 0.f);
            }
            *(float2*)(Cf + (size_t)r0 * Nn + cg)       = make_float2(v0, v1);
            *(float2*)(Cf + (size_t)(r0 + 8) * Nn + cg) = make_float2(v2, v3);
            if (SYM && bx != by) {
                sT[cl * 132 + rl] = v0;       sT[(cl + 1) * 132 + rl] = v1;
                sT[cl * 132 + rl + 8] = v2;   sT[(cl + 1) * 132 + rl + 8] = v3;
            }
        }
    }
    if (SYM && bx != by) {
        __syncthreads();
        const int rr = tid >> 1;
        const int c0 = (tid & 1) * 64;
        const float* src = sT + rr * 132 + c0;
        float4* dst = (float4*)(Cf + (size_t)(bx * 128 + rr) * Nn + by * 128 + c0);
        #pragma unroll
        for (int q = 0; q < 16; q++) dst[q] = *(const float4*)(src + q * 4);
    }
}

// ---------------- fp16 single-pass GEMM (unchanged — at HMMA ceiling) ----------------
#define FTILE_B 16384
#define FSTAGE_B (2 * FTILE_B)
#define FGEMM_SMEM (1024 + 3 * FSTAGE_B)

__global__ __launch_bounds__(256, 2) void fgemm(
    const __half* __restrict__ A,
    const __half* __restrict__ Bh,
    const float* __restrict__ bias,
    __half* __restrict__ Ch, int M, int Nn, int K)
{
    extern __shared__ __align__(1024) char smem[];
    uint32_t sb = smem_u32(smem);
    const int tid = threadIdx.x;
    const int wid = tid >> 5, lane = tid & 31;
    const int wm = wid >> 1, wn = wid & 1;
    const int bx = blockIdx.x, by = blockIdx.y;

    float* sBias = (float*)(smem + 512);
    if (tid < 128) sBias[tid] = bias[bx * 128 + tid];

    const uint32_t T0 = sb + 1024;
    const int NK = K >> 6;
    const int arow0 = by * 128, brow0 = bx * 128;

    float acc[2][8][4];
    #pragma unroll
    for (int i = 0; i < 2; i++)
        #pragma unroll
        for (int j = 0; j < 8; j++)
            #pragma unroll
            for (int l = 0; l < 4; l++) acc[i][j][l] = 0.f;

    const int mi = lane >> 3, li = lane & 7;
    const int rowoff = (mi & 1) * 8 + li;
    const int coloff = (mi >> 1) * 16;

    #pragma unroll
    for (int s = 0; s < 2; s++) {
        uint32_t st = T0 + s * FSTAGE_B;
        ld_tile(st,           A,  arow0, K, s, tid);
        ld_tile(st + FTILE_B, Bh, brow0, K, s, tid);
        CP_COMMIT();
    }

    for (int kc = 0; kc < NK; kc++) {
        if (kc == NK - 1) asm volatile("cp.async.wait_group 0;" ::: "memory");
        else              asm volatile("cp.async.wait_group 1;" ::: "memory");
        __syncthreads();

        if (kc + 2 < NK) {
            uint32_t st = T0 + ((kc + 2) % 3) * FSTAGE_B;
            ld_tile(st,           A,  arow0, K, kc + 2, tid);
            ld_tile(st + FTILE_B, Bh, brow0, K, kc + 2, tid);
            CP_COMMIT();
        }

        const uint32_t Sa = T0 + (kc % 3) * FSTAGE_B;
        const uint32_t Sh = Sa + FTILE_B;

        #pragma unroll
        for (int ks = 0; ks < 4; ks++) {
            const int kb = ks * 32;
            uint32_t a[2][4];
            #pragma unroll
            for (int mt = 0; mt < 2; mt++) {
                uint32_t ra = swz((uint32_t)(wm * 32 + mt * 16 + rowoff) * 128 + kb + coloff);
                ldsm4(a[mt], Sa + ra);
            }
            #pragma unroll
            for (int g = 0; g < 4; g++) {
                uint32_t rb = swz((uint32_t)(wn * 64 + g * 16 + rowoff) * 128 + kb + coloff);
                uint32_t bh[4];
                ldsm4(bh, Sh + rb);
                #pragma unroll
                for (int mt = 0; mt < 2; mt++) {
                    #pragma unroll
                    for (int sub = 0; sub < 2; sub++) {
                        mma_fp(acc[mt][g * 2 + sub], a[mt], bh[sub], bh[2 + sub]);
                    }
                }
            }
        }
    }

    #pragma unroll
    for (int mt = 0; mt < 2; mt++) {
        #pragma unroll
        for (int nt = 0; nt < 8; nt++) {
            const int r0 = by * 128 + wm * 32 + mt * 16 + (lane >> 2);
            const int cb = wn * 64 + nt * 8 + (lane & 3) * 2;
            const int cg = bx * 128 + cb;
            float bb0 = sBias[cb], bb1 = sBias[cb + 1];
            __half h0 = __float2half(acc[mt][nt][0] + bb0);
            __half h1 = __float2half(acc[mt][nt][1] + bb1);
            __half h2 = __float2half(acc[mt][nt][2] + bb0);
            __half h3 = __float2half(acc[mt][nt][3] + bb1);
            *(uint32_t*)(Ch + (size_t)r0 * Nn + cg)       = ((uint32_t)hfbits(h1) << 16) | hfbits(h0);
            *(uint32_t*)(Ch + (size_t)(r0 + 8) * Nn + cg) = ((uint32_t)hfbits(h3) << 16) | hfbits(h2);
        }
    }
}

// ---------------- small kernels ----------------
__global__ __launch_bounds__(256) void k_pre(const float* __restrict__ h) {
    int b = blockIdx.y;
    int hh = blockIdx.x * 256 + threadIdx.x;
    if (b >= 64) { g_hgHi[b * H_ + hh] = __float2bfloat16(0.f); return; }
    const float* p = h + (size_t)b * T_ * H_ + hh;
    __half* q = g_hA16 + (size_t)b * T_ * H_ + hh;
    float s = 0.f;
    #pragma unroll 4
    for (int t = 0; t < T_; t++) {
        float v = p[(size_t)t * H_];
        q[(size_t)t * H_] = __float2half(v);
        s += v;
    }
    float mean = s * (1.0f / T_);
    g_hgate[b * H_ + hh] = mean;
    g_hgHi[b * H_ + hh] = __float2bfloat16(mean);
}

__global__ void k_meanB() {
    int hh = blockIdx.x * blockDim.x + threadIdx.x;
    if (hh >= H_) return;
    float s = 0.f;
    #pragma unroll
    for (int b = 0; b < B_; b++) s += g_hgate[b * H_ + hh];
    g_hmean[hh] = s * (1.0f / B_);
}

__global__ __launch_bounds__(256) void k_enorm(const float* __restrict__ E_dyn) {
    int i = blockIdx.x;
    __shared__ float red[256];
    float vals[4];
    float ss = 0.f;
    #pragma unroll
    for (int j = 0; j < 4; j++) {
        int hh = threadIdx.x + j * 256;
        float v = E_dyn[i * H_ + hh] + g_hmean[hh];
        vals[j] = v; ss += v * v;
    }
    red[threadIdx.x] = ss; __syncthreads();
    for (int off = 128; off > 0; off >>= 1) {
        if (threadIdx.x < off) red[threadIdx.x] += red[threadIdx.x + off];
        __syncthreads();
    }
    float inv = 1.0f / fmaxf(sqrtf(red[0]), 1e-12f);
    #pragma unroll
    for (int j = 0; j < 4; j++) {
        int hh = threadIdx.x + j * 256;
        g_Ehi[i * H_ + hh] = __float2bfloat16(vals[j] * inv);
    }
}

// rowsum -> store reciprocal 1/(sum+1e-6)
__global__ __launch_bounds__(256) void k_rowsum() {
    int i = blockIdx.x;
    __shared__ float red[256];
    float s = 0.f;
    for (int j = threadIdx.x; j < N_; j += 256) s += g_S[i * N_ + j];
    red[threadIdx.x] = s; __syncthreads();
    for (int off = 128; off > 0; off >>= 1) {
        if (threadIdx.x < off) red[threadIdx.x] += red[threadIdx.x + off];
        __syncthreads();
    }
    if (threadIdx.x == 0) g_rowsum[i] = 1.0f / (red[0] + 1e-6f);
}

// gate1 split-K combine: sum 4 partials + b1 -> gelu -> bf16
__global__ void k_combG(const float* __restrict__ b1) {
    int i = blockIdx.x * blockDim.x + threadIdx.x;
    if (i >= 128 * HID_) return;
    int n = i & (HID_ - 1);
    float v = g_zb[i] + g_zb[128*HID_ + i] + g_zb[2*128*HID_ + i] + g_zb[3*128*HID_ + i] + b1[n];
    v = 0.5f * v * (1.0f + erff(v * 0.70710678118654752f));
    g_hidh[i] = __float2bfloat16(v);
}

// Amix elementwise (S bitwise-symmetric): v = (a*Ap + (1-a)*0.5*S*(ir[m]+ir[n]))*gmean[m] -> fp16 split
__global__ void k_amix(const float* __restrict__ Ap, const float* __restrict__ alpha_raw) {
    int idx = blockIdx.x * blockDim.x + threadIdx.x;
    if (idx >= N_*N_) return;
    int m = idx >> 10, n = idx & 1023;
    float alpha = 1.0f / (1.0f + expf(-alpha_raw[0]));
    float v = (alpha * Ap[idx] + (1.0f - alpha) * 0.5f * g_S[idx] * (g_rowsum[m] + g_rowsum[n])) * g_gmean[m];
    __half h = __float2half(v);
    g_Am16h[idx] = h;
    g_Am16l[idx] = __float2half(v - __half2float(h));
}

// fp32 -> fp16 elementwise
__global__ void k_cvt16(const float* __restrict__ x, __half* __restrict__ o, int n4) {
    int i = blockIdx.x * blockDim.x + threadIdx.x;
    if (i >= n4) return;
    float4 v = ((const float4*)x)[i];
    __half h0 = __float2half(v.x), h1 = __float2half(v.y);
    __half h2 = __float2half(v.z), h3 = __float2half(v.w);
    uint2 hv;
    hv.x = ((uint32_t)hfbits(h1) << 16) | hfbits(h0);
    hv.y = ((uint32_t)hfbits(h3) << 16) | hfbits(h2);
    ((uint2*)o)[i] = hv;
}

// transpose [Rin,Cin] -> [Cin,Rin] fp16
__global__ void k_t16(const float* __restrict__ W, __half* __restrict__ O, int Rin, int Cin) {
    __shared__ float t[32][33];
    int c0 = blockIdx.x * 32, r0 = blockIdx.y * 32;
    #pragma unroll
    for (int i = 0; i < 4; i++)
        t[threadIdx.y + i * 8][threadIdx.x] = W[(size_t)(r0 + threadIdx.y + i * 8) * Cin + c0 + threadIdx.x];
    __syncthreads();
    #pragma unroll
    for (int i = 0; i < 4; i++) {
        int oc = threadIdx.y + i * 8;
        O[(size_t)(c0 + oc) * Rin + r0 + threadIdx.x] = __float2half(t[threadIdx.x][oc]);
    }
}

// transpose [Rin,Cin] -> [Cin,Rin] bf16
__global__ void k_tbf(const float* __restrict__ W, bf16* __restrict__ O, int Rin, int Cin) {
    __shared__ float t[32][33];
    int c0 = blockIdx.x * 32, r0 = blockIdx.y * 32;
    #pragma unroll
    for (int i = 0; i < 4; i++)
        t[threadIdx.y + i * 8][threadIdx.x] = W[(size_t)(r0 + threadIdx.y + i * 8) * Cin + c0 + threadIdx.x];
    __syncthreads();
    #pragma unroll
    for (int i = 0; i < 4; i++) {
        int oc = threadIdx.y + i * 8;
        O[(size_t)(c0 + oc) * Rin + r0 + threadIdx.x] = __float2bfloat16(t[threadIdx.x][oc]);
    }
}

// combine split-K partials -> fp16 hi/lo (P)
__global__ void k_combP() {
    int i = blockIdx.x * blockDim.x + threadIdx.x;
    if (i >= N_*H_) return;
    float v = g_zb[i] + g_zb[(size_t)N_*H_ + i];
    __half h = __float2half(v);
    g_P16h[i] = h;
    g_P16l[i] = __float2half(v - __half2float(h));
}

// combine split-K partials -> fp16 (Mcomb)
__global__ void k_combM() {
    int i = blockIdx.x * blockDim.x + threadIdx.x;
    if (i >= H_*H_) return;
    g_M16h[i] = __float2half(g_zb[i] + g_zb[(size_t)N_*H_ + i]);
}

// u[m] = sum_n A_mix[m][n] * b1[n]
__global__ __launch_bounds__(256) void k_bias_u(const float* __restrict__ b1) {
    int m = blockIdx.x;
    __shared__ float red[256];
    float s = 0.f;
    for (int n = threadIdx.x; n < N_; n += 256) {
        size_t idx = (size_t)m * N_ + n;
        s += (__half2float(g_Am16h[idx]) + __half2float(g_Am16l[idx])) * b1[n];
    }
    red[threadIdx.x] = s; __syncthreads();
    for (int off = 128; off > 0; off >>= 1) {
        if (threadIdx.x < off) red[threadIdx.x] += red[threadIdx.x + off];
        __syncthreads();
    }
    if (threadIdx.x == 0) g_u[m] = red[0];
}

// cvec[h] = sum_m u[m] * W2t[h][m] + b2[h]
__global__ __launch_bounds__(256) void k_bias_c(const float* __restrict__ b2) {
    int h = blockIdx.x;
    __shared__ float red[256];
    float s = 0.f;
    for (int m = threadIdx.x; m < N_; m += 256)
        s += g_u[m] * __half2float(g_W2t16[(size_t)h * N_ + m]);
    red[threadIdx.x] = s; __syncthreads();
    for (int off = 128; off > 0; off >>= 1) {
        if (threadIdx.x < off) red[threadIdx.x] += red[threadIdx.x + off];
        __syncthreads();
    }
    if (threadIdx.x == 0) g_cvec[h] = red[0] + b2[h];
}

// y = hA16*(1+tanh(1/N)) + msg16 -> LayerNorm (fp32 math/out)
__global__ __launch_bounds__(256) void k_final(const float* __restrict__ lw,
                                               const float* __restrict__ lb,
                                               float* __restrict__ out) {
    int row = blockIdx.x;
    size_t base = (size_t)row * H_ + threadIdx.x * 4;
    const float gw = 1.0f + tanhf(1.0f / 1024.0f);
    uint2 ha = *(const uint2*)(g_hA16 + base);
    uint2 ma = *(const uint2*)(g_msg16 + base);
    __half2 h01 = *reinterpret_cast<__half2*>(&ha.x);
    __half2 h23 = *reinterpret_cast<__half2*>(&ha.y);
    __half2 m01 = *reinterpret_cast<__half2*>(&ma.x);
    __half2 m23 = *reinterpret_cast<__half2*>(&ma.y);
    float v0 = __low2float(h01) * gw + __low2float(m01);
    float v1 = __high2float(h01) * gw + __high2float(m01);
    float v2 = __low2float(h23) * gw + __low2float(m23);
    float v3 = __high2float(h23) * gw + __high2float(m23);

    __shared__ float red[256];
    red[threadIdx.x] = v0 + v1 + v2 + v3;
    __syncthreads();
    for (int off = 128; off > 0; off >>= 1) {
        if (threadIdx.x < off) red[threadIdx.x] += red[threadIdx.x + off];
        __syncthreads();
    }
    float mu = red[0] * (1.0f / H_);
    __syncthreads();
    float d0 = v0 - mu, d1 = v1 - mu, d2 = v2 - mu, d3 = v3 - mu;
    red[threadIdx.x] = d0 * d0 + d1 * d1 + d2 * d2 + d3 * d3;
    __syncthreads();
    for (int off = 128; off > 0; off >>= 1) {
        if (threadIdx.x < off) red[threadIdx.x] += red[threadIdx.x + off];
        __syncthreads();
    }
    float rstd = rsqrtf(red[0] * (1.0f / H_) + 1e-5f);
    float4 w = *(const float4*)(lw + threadIdx.x * 4);
    float4 bb = *(const float4*)(lb + threadIdx.x * 4);
    float4 o;
    o.x = d0 * rstd * w.x + bb.x;
    o.y = d1 * rstd * w.y + bb.y;
    o.z = d2 * rstd * w.z + bb.z;
    o.w = d3 * rstd * w.w + bb.w;
    *(float4*)(out + base) = o;
}

// ---------------- launcher ----------------
extern "C" void kernel_launch(void* const* d_in, const int* in_sizes, int n_in,
                              void* d_out, int out_size) {
    const float* h_time    = (const float*)d_in[0];
    const float* A_pearson = (const float*)d_in[1];
    const float* E_dyn     = (const float*)d_in[2];
    const float* alpha_raw = (const float*)d_in[3];
    // d_in[4] = tau_raw : analytically eliminated (mean over softmax axis == 1/N)
    const float* gate_W1   = (const float*)d_in[5];
    const float* gate_b1   = (const float*)d_in[6];
    const float* gate_W2   = (const float*)d_in[7];
    const float* gate_b2   = (const float*)d_in[8];
    const float* h2n_W     = (const float*)d_in[9];
    const float* h2n_b     = (const float*)d_in[10];
    const float* n2h_W     = (const float*)d_in[11];
    const float* n2h_b     = (const float*)d_in[12];
    const float* ln_w      = (const float*)d_in[13];
    const float* ln_b      = (const float*)d_in[14];
    float* out = (float*)d_out;

    bf16 *p_Ehi, *p_hgHi, *p_G1h, *p_G2h, *p_hidh;
    __half *p_hA16, *p_M16h, *p_msg16, *p_Am16h, *p_Am16l, *p_W116, *p_W2t16, *p_P16h, *p_P16l;
    float *p_S, *p_cvec, *p_gmean, *p_zb;
    cudaGetSymbolAddress((void**)&p_Ehi, g_Ehi);
    cudaGetSymbolAddress((void**)&p_hgHi, g_hgHi);
    cudaGetSymbolAddress((void**)&p_G1h, g_G1h);   cudaGetSymbolAddress((void**)&p_G2h, g_G2h);
    cudaGetSymbolAddress((void**)&p_hidh, g_hidh);
    cudaGetSymbolAddress((void**)&p_hA16, g_hA16);
    cudaGetSymbolAddress((void**)&p_M16h, g_M16h); cudaGetSymbolAddress((void**)&p_msg16, g_msg16);
    cudaGetSymbolAddress((void**)&p_Am16h, g_Am16h); cudaGetSymbolAddress((void**)&p_Am16l, g_Am16l);
    cudaGetSymbolAddress((void**)&p_W116, g_W116); cudaGetSymbolAddress((void**)&p_W2t16, g_W2t16);
    cudaGetSymbolAddress((void**)&p_P16h, g_P16h); cudaGetSymbolAddress((void**)&p_P16l, g_P16l);
    cudaGetSymbolAddress((void**)&p_S, g_S);
    cudaGetSymbolAddress((void**)&p_cvec, g_cvec); cudaGetSymbolAddress((void**)&p_gmean, g_gmean);
    cudaGetSymbolAddress((void**)&p_zb, g_zb);

    cudaFuncSetAttribute(hgemm<0,1,1,0,1>, cudaFuncAttributeMaxDynamicSharedMemorySize, GEMM_SMEM);
    cudaFuncSetAttribute(hgemm<0,1,0,0,0>, cudaFuncAttributeMaxDynamicSharedMemorySize, GEMM_SMEM);
    cudaFuncSetAttribute(hgemm<0,1,7,1,0>, cudaFuncAttributeMaxDynamicSharedMemorySize, GEMM_SMEM);
    cudaFuncSetAttribute(hgemm<1,2,0,0,0>, cudaFuncAttributeMaxDynamicSharedMemorySize, GEMM_SMEM);
    cudaFuncSetAttribute(fgemm, cudaFuncAttributeMaxDynamicSharedMemorySize, FGEMM_SMEM);

    // fused reductions + fp16 convert; weight prep
    k_pre<<<dim3(4, 128), 256>>>(h_time);
    k_meanB<<<(H_ + 255) / 256, 256>>>();
    k_enorm<<<N_, 256>>>(E_dyn);
    k_cvt16<<<(H_*N_/4 + 255) / 256, 256>>>(h2n_W, p_W116, H_*N_ / 4);
    {
        dim3 b(32, 8);
        k_t16<<<dim3(H_ / 32, N_ / 32), b>>>(n2h_W, p_W2t16, N_, H_);          // [N,H]->[H,N]
        k_tbf<<<dim3(HID_ / 32, H_ / 32), b>>>(gate_W1, p_G1h, H_, HID_);      // [H,HID]->[HID,H]
        k_tbf<<<dim3(N_ / 32, HID_ / 32), b>>>(gate_W2, p_G2h, HID_, N_);      // [HID,N]->[N,HID]
    }

    // S = relu(E_cur @ E_cur^T) — symmetric: 36 upper-triangle tiles + mirrored write
    hgemm<0,1,1,0,1><<<36, 256, GEMM_SMEM>>>(
        p_Ehi, nullptr, p_Ehi, nullptr, nullptr, p_S, N_, N_, H_);
    k_rowsum<<<N_, 256>>>();

    // gate MLP — gate1 split-K=4, combine+gelu; gate2 sigmoid+column-mean
    hgemm<0,1,0,0,0><<<dim3(HID_ / 128, 1, 4), 256, GEMM_SMEM>>>(
        p_hgHi, nullptr, p_G1h, nullptr, nullptr, p_zb, 128, HID_, H_);
    k_combG<<<(128 * HID_ + 255) / 256, 256>>>(gate_b1);
    hgemm<0,1,7,1,0><<<dim3(N_ / 128, 1), 256, GEMM_SMEM>>>(
        p_hidh, nullptr, p_G2h, nullptr, gate_b2, p_gmean, 128, N_, HID_);

    // Amix (elementwise; S symmetric) -> fp16 split
    k_amix<<<(N_*N_ + 255) / 256, 256>>>(A_pearson, alpha_raw);

    // P = W1 @ AmixT (fp16 2-pass, split-K=2) -> combine -> fp16 split
    hgemm<1,2,0,0,0><<<dim3(N_ / 128, H_ / 128, 2), 256, GEMM_SMEM>>>(
        p_W116, nullptr, p_Am16h, p_Am16l, nullptr, p_zb, H_, N_, N_);
    k_combP<<<(N_*H_ + 255) / 256, 256>>>();

    // McombT = W2t @ P^T (fp16 2-pass, split-K=2) -> combine -> fp16
    hgemm<1,2,0,0,0><<<dim3(H_ / 128, H_ / 128, 2), 256, GEMM_SMEM>>>(
        p_W2t16, nullptr, p_P16h, p_P16l, nullptr, p_zb, H_, H_, N_);
    k_combM<<<(H_*H_ + 255) / 256, 256>>>();

    // bias fold: cvec = b1 @ AmixT @ W2 + b2
    k_bias_u<<<N_, 256>>>(h2n_b);
    k_bias_c<<<H_, 256>>>(n2h_b);

    // THE big GEMM: msg = h_time @ Mcomb + cvec (fp16 x fp16, single pass, fp16 out)
    fgemm<<<dim3(H_ / 128, BT_ / 128), 256, FGEMM_SMEM>>>(
        p_hA16, p_M16h, p_cvec, p_msg16, BT_, H_, H_);

    // fused residual + LayerNorm
    k_final<<<BT_, 256>>>(ln_w, ln_b, out);
}